// round 1
// baseline (speedup 1.0000x reference)
#include <cuda_runtime.h>
#include <math.h>

#define NN 2048
#define NFEAT 64
#define DD 256
#define HH 8
#define HDD 32
#define LL 6
#define FFND 1024
#define EE 32768
#define EFD 16
#define NFT 2049
#define MAXDEGC 64

__device__ float g_h[NFT * DD];
__device__ float g_hn[NFT * DD];
__device__ float g_q[NFT * DD];
__device__ float g_k[NFT * DD];
__device__ float g_v[NFT * DD];
__device__ float g_o[NFT * DD];
__device__ float g_ffn[NFT * FFND];
__device__ float g_scores[(size_t)HH * NFT * NFT];
__device__ float g_bias[(size_t)HH * NFT * NFT];
__device__ int g_indeg[NN];
__device__ int g_outdeg[NN];

static const size_t NF2H = (size_t)NFT * NFT;

// ---------------------------------------------------------------------------
// degree counting
// ---------------------------------------------------------------------------
__global__ void zero_deg_kernel() {
    int i = blockIdx.x * blockDim.x + threadIdx.x;
    if (i < NN) { g_indeg[i] = 0; g_outdeg[i] = 0; }
}

__global__ void count_deg_kernel(const int* __restrict__ edge_index) {
    int e = blockIdx.x * blockDim.x + threadIdx.x;
    if (e < EE) {
        atomicAdd(&g_outdeg[edge_index[e]], 1);
        atomicAdd(&g_indeg[edge_index[EE + e]], 1);
    }
}

// ---------------------------------------------------------------------------
// node embedding: h[1+n] = x[n] @ W^T + b + in_emb + out_emb ;  h[0] = cls
// ---------------------------------------------------------------------------
__global__ void node_embed_kernel(const float* __restrict__ x,
                                  const float* __restrict__ W,
                                  const float* __restrict__ b,
                                  const float* __restrict__ inemb,
                                  const float* __restrict__ outemb) {
    int row = blockIdx.x;
    int col = threadIdx.x;
    __shared__ float xs[NFEAT];
    if (col < NFEAT) xs[col] = x[row * NFEAT + col];
    __syncthreads();
    float acc = 0.f;
#pragma unroll
    for (int k = 0; k < NFEAT; k++) acc += xs[k] * W[col * NFEAT + k];
    int ind = min(g_indeg[row], MAXDEGC);
    int outd = min(g_outdeg[row], MAXDEGC);
    g_h[(size_t)(row + 1) * DD + col] =
        acc + b[col] + inemb[ind * DD + col] + outemb[outd * DD + col];
}

__global__ void cls_kernel(const float* __restrict__ cls) {
    g_h[threadIdx.x] = cls[threadIdx.x];
}

// ---------------------------------------------------------------------------
// spatial bias fill + edge-feature scatter add
// ---------------------------------------------------------------------------
__global__ void bias_fill_kernel(const int* __restrict__ dist,
                                 const float* __restrict__ dist_bias) {
    size_t idx = (size_t)blockIdx.x * blockDim.x + threadIdx.x;
    if (idx >= NF2H) return;
    int i = (int)(idx / NFT);
    int j = (int)(idx % NFT);
    int d = 0;
    if (i > 0 && j > 0) {
        d = dist[(size_t)(i - 1) * NN + (j - 1)];
        d = max(0, min(d, 9));
    }
#pragma unroll
    for (int h = 0; h < HH; h++) {
        g_bias[(size_t)h * NF2H + idx] = dist_bias[d * HH + h];
    }
}

__global__ void edge_bias_kernel(const float* __restrict__ edge_attr,
                                 const float* __restrict__ epw,
                                 const float* __restrict__ epb,
                                 const int* __restrict__ edge_index) {
    int e = blockIdx.x * blockDim.x + threadIdx.x;
    if (e >= EE) return;
    const float* ea = edge_attr + (size_t)e * EFD;
    int src = edge_index[e];
    int dst = edge_index[EE + e];
    size_t base = (size_t)(src + 1) * NFT + (dst + 1);
#pragma unroll
    for (int h = 0; h < HH; h++) {
        float p = epb[h];
#pragma unroll
        for (int k = 0; k < EFD; k++) p += ea[k] * epw[h * EFD + k];
        atomicAdd(&g_bias[(size_t)h * NF2H + base], p);
    }
}

// ---------------------------------------------------------------------------
// layernorm over D=256, one block per row (256 threads)
// ---------------------------------------------------------------------------
__global__ void ln_kernel(const float* __restrict__ in, float* __restrict__ out,
                          const float* __restrict__ s, const float* __restrict__ b) {
    int row = blockIdx.x;
    int c = threadIdx.x;
    float v = in[(size_t)row * DD + c];
    __shared__ float red[256];
    red[c] = v;
    __syncthreads();
    for (int off = 128; off > 0; off >>= 1) {
        if (c < off) red[c] += red[c + off];
        __syncthreads();
    }
    float mean = red[0] / DD;
    __syncthreads();
    float d = v - mean;
    red[c] = d * d;
    __syncthreads();
    for (int off = 128; off > 0; off >>= 1) {
        if (c < off) red[c] += red[c + off];
        __syncthreads();
    }
    float var = red[0] / DD;
    out[(size_t)row * DD + c] = d * rsqrtf(var + 1e-5f) * s[c] + b[c];
}

// ---------------------------------------------------------------------------
// generic GEMM: out[M,Ncol] = A[M,K] @ W[Ncol,K]^T + bias (+res / gelu)
// MODE 0: plain, 1: + residual, 2: gelu
// ---------------------------------------------------------------------------
template <int MODE>
__global__ void gemm_kernel(const float* __restrict__ A, const float* __restrict__ W,
                            const float* __restrict__ bias,
                            const float* __restrict__ res,
                            float* __restrict__ out, int M, int Ncol, int K) {
    __shared__ __align__(16) float As[16][68];
    __shared__ __align__(16) float Bs[16][68];
    int tid = threadIdx.x;
    int n0 = blockIdx.x * 64, m0 = blockIdx.y * 64;
    int tx = tid & 15, ty = tid >> 4;
    float acc[4][4] = {};
    int lm = tid >> 2;          // 0..63
    int lk = (tid & 3) * 4;     // 0,4,8,12

    for (int k0 = 0; k0 < K; k0 += 16) {
        float4 av = make_float4(0.f, 0.f, 0.f, 0.f);
        if (m0 + lm < M)
            av = *(const float4*)&A[(size_t)(m0 + lm) * K + k0 + lk];
        As[lk + 0][lm] = av.x; As[lk + 1][lm] = av.y;
        As[lk + 2][lm] = av.z; As[lk + 3][lm] = av.w;
        float4 bv = *(const float4*)&W[(size_t)(n0 + lm) * K + k0 + lk];
        Bs[lk + 0][lm] = bv.x; Bs[lk + 1][lm] = bv.y;
        Bs[lk + 2][lm] = bv.z; Bs[lk + 3][lm] = bv.w;
        __syncthreads();
#pragma unroll
        for (int k = 0; k < 16; k++) {
            float a[4], b[4];
            *(float4*)a = *(const float4*)&As[k][ty * 4];
            *(float4*)b = *(const float4*)&Bs[k][tx * 4];
#pragma unroll
            for (int i = 0; i < 4; i++)
#pragma unroll
                for (int j = 0; j < 4; j++) acc[i][j] += a[i] * b[j];
        }
        __syncthreads();
    }
#pragma unroll
    for (int i = 0; i < 4; i++) {
        int r = m0 + ty * 4 + i;
        if (r >= M) continue;
#pragma unroll
        for (int j = 0; j < 4; j++) {
            int c = n0 + tx * 4 + j;
            float v = acc[i][j] + bias[c];
            if (MODE == 2) v = 0.5f * v * (1.0f + erff(v * 0.7071067811865475f));
            if (MODE == 1) v += res[(size_t)r * Ncol + c];
            out[(size_t)r * Ncol + c] = v;
        }
    }
}

// ---------------------------------------------------------------------------
// logits: scores[z,i,j] = (Q[i,z*32:]·K[j,z*32:])/sqrt(32) + bias[z,i,j]
// ---------------------------------------------------------------------------
__global__ void logits_kernel(const float* __restrict__ Q, const float* __restrict__ Kt,
                              const float* __restrict__ bias, float* __restrict__ S) {
    __shared__ __align__(16) float Qs[32][68];
    __shared__ __align__(16) float Ks[32][68];
    int z = blockIdx.z;
    int i0 = blockIdx.y * 64, j0 = blockIdx.x * 64;
    int tid = threadIdx.x;
    int tx = tid & 15, ty = tid >> 4;

#pragma unroll
    for (int it = 0; it < 2; it++) {
        int idx = tid + it * 256;
        int m = idx >> 3;
        int k4 = (idx & 7) * 4;
        float4 qv = make_float4(0.f, 0.f, 0.f, 0.f);
        float4 kv = qv;
        if (i0 + m < NFT)
            qv = *(const float4*)&Q[(size_t)(i0 + m) * DD + z * HDD + k4];
        if (j0 + m < NFT)
            kv = *(const float4*)&Kt[(size_t)(j0 + m) * DD + z * HDD + k4];
        Qs[k4 + 0][m] = qv.x; Qs[k4 + 1][m] = qv.y;
        Qs[k4 + 2][m] = qv.z; Qs[k4 + 3][m] = qv.w;
        Ks[k4 + 0][m] = kv.x; Ks[k4 + 1][m] = kv.y;
        Ks[k4 + 2][m] = kv.z; Ks[k4 + 3][m] = kv.w;
    }
    __syncthreads();

    float acc[4][4] = {};
#pragma unroll
    for (int k = 0; k < 32; k++) {
        float a[4], b[4];
        *(float4*)a = *(const float4*)&Qs[k][ty * 4];
        *(float4*)b = *(const float4*)&Ks[k][tx * 4];
#pragma unroll
        for (int i = 0; i < 4; i++)
#pragma unroll
            for (int j = 0; j < 4; j++) acc[i][j] += a[i] * b[j];
    }
    const float inv = 0.17677669529663687f;  // 1/sqrt(32)
#pragma unroll
    for (int i = 0; i < 4; i++) {
        int r = i0 + ty * 4 + i;
        if (r >= NFT) continue;
#pragma unroll
        for (int j = 0; j < 4; j++) {
            int c = j0 + tx * 4 + j;
            if (c >= NFT) continue;
            size_t o = (size_t)z * NF2H + (size_t)r * NFT + c;
            S[o] = acc[i][j] * inv + bias[o];
        }
    }
}

// ---------------------------------------------------------------------------
// row softmax over 2049 entries, one block per (head,row)
// ---------------------------------------------------------------------------
__global__ void softmax_kernel(float* __restrict__ S) {
    size_t row = blockIdx.x;
    float* p = S + row * NFT;
    int tid = threadIdx.x;
    __shared__ float red[256];
    float m = -1e30f;
    for (int j = tid; j < NFT; j += 256) m = fmaxf(m, p[j]);
    red[tid] = m;
    __syncthreads();
    for (int off = 128; off > 0; off >>= 1) {
        if (tid < off) red[tid] = fmaxf(red[tid], red[tid + off]);
        __syncthreads();
    }
    m = red[0];
    __syncthreads();
    float s = 0.f;
    for (int j = tid; j < NFT; j += 256) {
        float e = expf(p[j] - m);
        p[j] = e;
        s += e;
    }
    red[tid] = s;
    __syncthreads();
    for (int off = 128; off > 0; off >>= 1) {
        if (tid < off) red[tid] += red[tid + off];
        __syncthreads();
    }
    float invs = 1.0f / red[0];
    for (int j = tid; j < NFT; j += 256) p[j] *= invs;
}

// ---------------------------------------------------------------------------
// attn @ V per head: O[i, z*32+c] = sum_m attn[z,i,m] * V[m, z*32+c]
// tile: 64 rows x 32 cols, 256 threads each 4x2
// ---------------------------------------------------------------------------
__global__ void av_kernel(const float* __restrict__ S, const float* __restrict__ V,
                          float* __restrict__ O) {
    __shared__ float As[32][65];
    __shared__ float Vs[32][34];
    int z = blockIdx.y;
    int i0 = blockIdx.x * 64;
    int tid = threadIdx.x;
    int tx = tid & 15, ty = tid >> 4;
    float acc[4][2] = {};
    const float* Sh = S + (size_t)z * NF2H;

    for (int kc = 0; kc < NFT; kc += 32) {
#pragma unroll
        for (int it = 0; it < 8; it++) {
            int idx = tid + it * 256;  // 0..2047
            int m = idx >> 5, k = idx & 31;
            float v = 0.f;
            if (i0 + m < NFT && kc + k < NFT)
                v = Sh[(size_t)(i0 + m) * NFT + kc + k];
            As[k][m] = v;
        }
        {
            int k = tid >> 3;
            int c4 = (tid & 7) * 4;
            float4 vv = make_float4(0.f, 0.f, 0.f, 0.f);
            if (kc + k < NFT)
                vv = *(const float4*)&V[(size_t)(kc + k) * DD + z * HDD + c4];
            Vs[k][c4 + 0] = vv.x; Vs[k][c4 + 1] = vv.y;
            Vs[k][c4 + 2] = vv.z; Vs[k][c4 + 3] = vv.w;
        }
        __syncthreads();
#pragma unroll
        for (int k = 0; k < 32; k++) {
            float b0 = Vs[k][tx * 2];
            float b1 = Vs[k][tx * 2 + 1];
#pragma unroll
            for (int i = 0; i < 4; i++) {
                float a = As[k][ty * 4 + i];
                acc[i][0] += a * b0;
                acc[i][1] += a * b1;
            }
        }
        __syncthreads();
    }
#pragma unroll
    for (int i = 0; i < 4; i++) {
        int r = i0 + ty * 4 + i;
        if (r >= NFT) continue;
        O[(size_t)r * DD + z * HDD + tx * 2 + 0] = acc[i][0];
        O[(size_t)r * DD + z * HDD + tx * 2 + 1] = acc[i][1];
    }
}

// ---------------------------------------------------------------------------
// launch
// ---------------------------------------------------------------------------
extern "C" void kernel_launch(void* const* d_in, const int* in_sizes, int n_in,
                              void* d_out, int out_size) {
    const float* x            = (const float*)d_in[0];
    const float* edge_attr    = (const float*)d_in[1];
    const float* node_proj_w  = (const float*)d_in[2];
    const float* node_proj_b  = (const float*)d_in[3];
    const float* in_deg_emb   = (const float*)d_in[4];
    const float* out_deg_emb  = (const float*)d_in[5];
    const float* dist_bias    = (const float*)d_in[6];
    const float* edge_proj_w  = (const float*)d_in[7];
    const float* edge_proj_b  = (const float*)d_in[8];
    const float* cls_token    = (const float*)d_in[9];
    const float* q_w = (const float*)d_in[10];
    const float* q_b = (const float*)d_in[11];
    const float* k_w = (const float*)d_in[12];
    const float* k_b = (const float*)d_in[13];
    const float* v_w = (const float*)d_in[14];
    const float* v_b = (const float*)d_in[15];
    const float* o_w = (const float*)d_in[16];
    const float* o_b = (const float*)d_in[17];
    const float* ffn1_w = (const float*)d_in[18];
    const float* ffn1_b = (const float*)d_in[19];
    const float* ffn2_w = (const float*)d_in[20];
    const float* ffn2_b = (const float*)d_in[21];
    const float* ln1_s = (const float*)d_in[22];
    const float* ln1_b = (const float*)d_in[23];
    const float* ln2_s = (const float*)d_in[24];
    const float* ln2_b = (const float*)d_in[25];
    const float* fn_s = (const float*)d_in[26];
    const float* fn_b = (const float*)d_in[27];
    const int* edge_index  = (const int*)d_in[28];
    const int* dist_matrix = (const int*)d_in[29];
    float* out = (float*)d_out;

    float *h, *hn, *q, *k, *v, *o, *ffn, *scores, *bias;
    cudaGetSymbolAddress((void**)&h, g_h);
    cudaGetSymbolAddress((void**)&hn, g_hn);
    cudaGetSymbolAddress((void**)&q, g_q);
    cudaGetSymbolAddress((void**)&k, g_k);
    cudaGetSymbolAddress((void**)&v, g_v);
    cudaGetSymbolAddress((void**)&o, g_o);
    cudaGetSymbolAddress((void**)&ffn, g_ffn);
    cudaGetSymbolAddress((void**)&scores, g_scores);
    cudaGetSymbolAddress((void**)&bias, g_bias);

    zero_deg_kernel<<<(NN + 255) / 256, 256>>>();
    count_deg_kernel<<<(EE + 255) / 256, 256>>>(edge_index);
    node_embed_kernel<<<NN, 256>>>(x, node_proj_w, node_proj_b, in_deg_emb, out_deg_emb);
    cls_kernel<<<1, 256>>>(cls_token);

    size_t nf2 = (size_t)NFT * NFT;
    bias_fill_kernel<<<(unsigned)((nf2 + 255) / 256), 256>>>(dist_matrix, dist_bias);
    edge_bias_kernel<<<(EE + 255) / 256, 256>>>(edge_attr, edge_proj_w, edge_proj_b,
                                                edge_index);

    dim3 gemmD(4, 33);    // Ncol=256, M=2049
    dim3 gemmF1(16, 33);  // Ncol=1024
    dim3 logitsG(33, 33, 8);
    dim3 avG(33, 8);

    for (int l = 0; l < LL; l++) {
        ln_kernel<<<NFT, 256>>>(h, hn, ln1_s + l * DD, ln1_b + l * DD);
        gemm_kernel<0><<<gemmD, 256>>>(hn, q_w + (size_t)l * DD * DD, q_b + l * DD,
                                       nullptr, q, NFT, DD, DD);
        gemm_kernel<0><<<gemmD, 256>>>(hn, k_w + (size_t)l * DD * DD, k_b + l * DD,
                                       nullptr, k, NFT, DD, DD);
        gemm_kernel<0><<<gemmD, 256>>>(hn, v_w + (size_t)l * DD * DD, v_b + l * DD,
                                       nullptr, v, NFT, DD, DD);
        logits_kernel<<<logitsG, 256>>>(q, k, bias, scores);
        softmax_kernel<<<HH * NFT, 256>>>(scores);
        av_kernel<<<avG, 256>>>(scores, v, o);
        gemm_kernel<1><<<gemmD, 256>>>(o, o_w + (size_t)l * DD * DD, o_b + l * DD,
                                       h, h, NFT, DD, DD);
        ln_kernel<<<NFT, 256>>>(h, hn, ln2_s + l * DD, ln2_b + l * DD);
        gemm_kernel<2><<<gemmF1, 256>>>(hn, ffn1_w + (size_t)l * FFND * DD,
                                        ffn1_b + l * FFND, nullptr, ffn, NFT, FFND, DD);
        gemm_kernel<1><<<gemmD, 256>>>(ffn, ffn2_w + (size_t)l * DD * FFND,
                                       ffn2_b + l * DD, h, h, NFT, DD, FFND);
    }

    // final LN into scratch, then copy to output (h then h[0])
    ln_kernel<<<NFT, 256>>>(h, q, fn_s, fn_b);
    size_t total = (size_t)NFT * DD;
    if ((size_t)out_size >= total + DD) {
        cudaMemcpyAsync(out, q, total * sizeof(float), cudaMemcpyDeviceToDevice);
        cudaMemcpyAsync(out + total, q, DD * sizeof(float), cudaMemcpyDeviceToDevice);
    } else if ((size_t)out_size >= total) {
        cudaMemcpyAsync(out, q, total * sizeof(float), cudaMemcpyDeviceToDevice);
    } else {
        cudaMemcpyAsync(out, q, (size_t)out_size * sizeof(float),
                        cudaMemcpyDeviceToDevice);
    }
}

// round 2
// speedup vs baseline: 1.3735x; 1.3735x over previous
#include <cuda_runtime.h>
#include <math.h>

#define NN 2048
#define NFEAT 64
#define DD 256
#define HH 8
#define HDD 32
#define LL 6
#define FFND 1024
#define EE 32768
#define EFD 16
#define NFT 2049
#define MAXDEGC 64

__device__ float g_h[NFT * DD];
__device__ float g_hn[NFT * DD];
__device__ float g_q[NFT * DD];
__device__ float g_k[NFT * DD];
__device__ float g_v[NFT * DD];
__device__ float g_o[NFT * DD];
__device__ float g_ffn[NFT * FFND];
__device__ float g_bias[(size_t)HH * NFT * NFT];
__device__ int g_indeg[NN];
__device__ int g_outdeg[NN];

static const size_t NF2H = (size_t)NFT * NFT;

// ---------------------------------------------------------------------------
// degree counting
// ---------------------------------------------------------------------------
__global__ void zero_deg_kernel() {
    int i = blockIdx.x * blockDim.x + threadIdx.x;
    if (i < NN) { g_indeg[i] = 0; g_outdeg[i] = 0; }
}

__global__ void count_deg_kernel(const int* __restrict__ edge_index) {
    int e = blockIdx.x * blockDim.x + threadIdx.x;
    if (e < EE) {
        atomicAdd(&g_outdeg[edge_index[e]], 1);
        atomicAdd(&g_indeg[edge_index[EE + e]], 1);
    }
}

// ---------------------------------------------------------------------------
// node embedding: h[1+n] = x[n] @ W^T + b + in_emb + out_emb ;  h[0] = cls
// ---------------------------------------------------------------------------
__global__ void node_embed_kernel(const float* __restrict__ x,
                                  const float* __restrict__ W,
                                  const float* __restrict__ b,
                                  const float* __restrict__ inemb,
                                  const float* __restrict__ outemb) {
    int row = blockIdx.x;
    int col = threadIdx.x;
    __shared__ float xs[NFEAT];
    if (col < NFEAT) xs[col] = x[row * NFEAT + col];
    __syncthreads();
    float acc = 0.f;
#pragma unroll
    for (int k = 0; k < NFEAT; k++) acc += xs[k] * W[col * NFEAT + k];
    int ind = min(g_indeg[row], MAXDEGC);
    int outd = min(g_outdeg[row], MAXDEGC);
    g_h[(size_t)(row + 1) * DD + col] =
        acc + b[col] + inemb[ind * DD + col] + outemb[outd * DD + col];
}

__global__ void cls_kernel(const float* __restrict__ cls) {
    g_h[threadIdx.x] = cls[threadIdx.x];
}

// ---------------------------------------------------------------------------
// spatial bias fill + edge-feature scatter add
// ---------------------------------------------------------------------------
__global__ void bias_fill_kernel(const int* __restrict__ dist,
                                 const float* __restrict__ dist_bias) {
    size_t idx = (size_t)blockIdx.x * blockDim.x + threadIdx.x;
    if (idx >= NF2H) return;
    int i = (int)(idx / NFT);
    int j = (int)(idx % NFT);
    int d = 0;
    if (i > 0 && j > 0) {
        d = dist[(size_t)(i - 1) * NN + (j - 1)];
        d = max(0, min(d, 9));
    }
#pragma unroll
    for (int h = 0; h < HH; h++) {
        g_bias[(size_t)h * NF2H + idx] = dist_bias[d * HH + h];
    }
}

__global__ void edge_bias_kernel(const float* __restrict__ edge_attr,
                                 const float* __restrict__ epw,
                                 const float* __restrict__ epb,
                                 const int* __restrict__ edge_index) {
    int e = blockIdx.x * blockDim.x + threadIdx.x;
    if (e >= EE) return;
    const float* ea = edge_attr + (size_t)e * EFD;
    int src = edge_index[e];
    int dst = edge_index[EE + e];
    size_t base = (size_t)(src + 1) * NFT + (dst + 1);
#pragma unroll
    for (int h = 0; h < HH; h++) {
        float p = epb[h];
#pragma unroll
        for (int k = 0; k < EFD; k++) p += ea[k] * epw[h * EFD + k];
        atomicAdd(&g_bias[(size_t)h * NF2H + base], p);
    }
}

// ---------------------------------------------------------------------------
// layernorm over D=256, one block per row (256 threads)
// ---------------------------------------------------------------------------
__global__ void ln_kernel(const float* __restrict__ in, float* __restrict__ out,
                          const float* __restrict__ s, const float* __restrict__ b) {
    int row = blockIdx.x;
    int c = threadIdx.x;
    float v = in[(size_t)row * DD + c];
    __shared__ float red[256];
    red[c] = v;
    __syncthreads();
    for (int off = 128; off > 0; off >>= 1) {
        if (c < off) red[c] += red[c + off];
        __syncthreads();
    }
    float mean = red[0] / DD;
    __syncthreads();
    float d = v - mean;
    red[c] = d * d;
    __syncthreads();
    for (int off = 128; off > 0; off >>= 1) {
        if (c < off) red[c] += red[c + off];
        __syncthreads();
    }
    float var = red[0] / DD;
    out[(size_t)row * DD + c] = d * rsqrtf(var + 1e-5f) * s[c] + b[c];
}

// ---------------------------------------------------------------------------
// generic GEMM: out[M,Ncol] = A[M,K] @ W[Ncol,K]^T + bias (+res / gelu)
// MODE 0: plain, 1: + residual, 2: gelu
// ---------------------------------------------------------------------------
template <int MODE>
__global__ void gemm_kernel(const float* __restrict__ A, const float* __restrict__ W,
                            const float* __restrict__ bias,
                            const float* __restrict__ res,
                            float* __restrict__ out, int M, int Ncol, int K) {
    __shared__ __align__(16) float As[16][68];
    __shared__ __align__(16) float Bs[16][68];
    int tid = threadIdx.x;
    int n0 = blockIdx.x * 64, m0 = blockIdx.y * 64;
    int tx = tid & 15, ty = tid >> 4;
    float acc[4][4] = {};
    int lm = tid >> 2;          // 0..63
    int lk = (tid & 3) * 4;     // 0,4,8,12

    for (int k0 = 0; k0 < K; k0 += 16) {
        float4 av = make_float4(0.f, 0.f, 0.f, 0.f);
        if (m0 + lm < M)
            av = *(const float4*)&A[(size_t)(m0 + lm) * K + k0 + lk];
        As[lk + 0][lm] = av.x; As[lk + 1][lm] = av.y;
        As[lk + 2][lm] = av.z; As[lk + 3][lm] = av.w;
        float4 bv = *(const float4*)&W[(size_t)(n0 + lm) * K + k0 + lk];
        Bs[lk + 0][lm] = bv.x; Bs[lk + 1][lm] = bv.y;
        Bs[lk + 2][lm] = bv.z; Bs[lk + 3][lm] = bv.w;
        __syncthreads();
#pragma unroll
        for (int k = 0; k < 16; k++) {
            float a[4], b[4];
            *(float4*)a = *(const float4*)&As[k][ty * 4];
            *(float4*)b = *(const float4*)&Bs[k][tx * 4];
#pragma unroll
            for (int i = 0; i < 4; i++)
#pragma unroll
                for (int j = 0; j < 4; j++) acc[i][j] += a[i] * b[j];
        }
        __syncthreads();
    }
#pragma unroll
    for (int i = 0; i < 4; i++) {
        int r = m0 + ty * 4 + i;
        if (r >= M) continue;
#pragma unroll
        for (int j = 0; j < 4; j++) {
            int c = n0 + tx * 4 + j;
            float v = acc[i][j] + bias[c];
            if (MODE == 2) v = 0.5f * v * (1.0f + erff(v * 0.7071067811865475f));
            if (MODE == 1) v += res[(size_t)r * Ncol + c];
            out[(size_t)r * Ncol + c] = v;
        }
    }
}

// ---------------------------------------------------------------------------
// fused attention (flash style): per (i-tile of 64 rows, head z) block.
// Online softmax over j-tiles of 64 keys. Scores never touch gmem.
// Thread layout: tx = tid&15, ty = tid>>4.
//   S rows: ty*4+i (i<4).  S cols: tx + 16*j (j<4).
//   O cols: tx*2+c (c<2).
// ---------------------------------------------------------------------------
__global__ void attn_kernel(const float* __restrict__ Q, const float* __restrict__ K,
                            const float* __restrict__ V, const float* __restrict__ bias,
                            float* __restrict__ O) {
    __shared__ float Qs[32][65];
    __shared__ float Ks[32][65];
    __shared__ __align__(16) float Vs[64][36];
    __shared__ float Ps[64][68];

    int z = blockIdx.y;
    int i0 = blockIdx.x * 64;
    int tid = threadIdx.x;
    int tx = tid & 15, ty = tid >> 4;

    // load Q tile (transposed into Qs[k][m])
#pragma unroll
    for (int it = 0; it < 2; it++) {
        int idx = tid + it * 256;
        int m = idx >> 3, k4 = (idx & 7) * 4;
        float4 qv = make_float4(0.f, 0.f, 0.f, 0.f);
        if (i0 + m < NFT)
            qv = *(const float4*)&Q[(size_t)(i0 + m) * DD + z * HDD + k4];
        Qs[k4 + 0][m] = qv.x; Qs[k4 + 1][m] = qv.y;
        Qs[k4 + 2][m] = qv.z; Qs[k4 + 3][m] = qv.w;
    }

    float m_r[4], l_r[4], acc[4][2];
#pragma unroll
    for (int i = 0; i < 4; i++) {
        m_r[i] = -1e30f; l_r[i] = 0.f; acc[i][0] = 0.f; acc[i][1] = 0.f;
    }

    const float inv = 0.17677669529663687f;  // 1/sqrt(32)
    const float* biasH = bias + (size_t)z * NF2H;

    for (int j0 = 0; j0 < NFT; j0 += 64) {
        __syncthreads();
        // load K,V tiles
#pragma unroll
        for (int it = 0; it < 2; it++) {
            int idx = tid + it * 256;
            int n = idx >> 3, k4 = (idx & 7) * 4;
            float4 kv = make_float4(0.f, 0.f, 0.f, 0.f);
            float4 vv = kv;
            if (j0 + n < NFT) {
                kv = *(const float4*)&K[(size_t)(j0 + n) * DD + z * HDD + k4];
                vv = *(const float4*)&V[(size_t)(j0 + n) * DD + z * HDD + k4];
            }
            Ks[k4 + 0][n] = kv.x; Ks[k4 + 1][n] = kv.y;
            Ks[k4 + 2][n] = kv.z; Ks[k4 + 3][n] = kv.w;
            *(float4*)&Vs[n][k4] = vv;
        }
        __syncthreads();

        // S = Q @ K^T
        float s[4][4] = {};
#pragma unroll
        for (int k = 0; k < 32; k++) {
            float a[4], b[4];
#pragma unroll
            for (int i = 0; i < 4; i++) a[i] = Qs[k][ty * 4 + i];
#pragma unroll
            for (int j = 0; j < 4; j++) b[j] = Ks[k][tx + 16 * j];
#pragma unroll
            for (int i = 0; i < 4; i++)
#pragma unroll
                for (int j = 0; j < 4; j++) s[i][j] += a[i] * b[j];
        }

        // scale + bias + validity
#pragma unroll
        for (int i = 0; i < 4; i++) {
            int r = i0 + ty * 4 + i;
            bool rv = (r < NFT);
            const float* brow = biasH + (size_t)r * NFT;
#pragma unroll
            for (int j = 0; j < 4; j++) {
                int c = j0 + tx + 16 * j;
                if (rv && c < NFT)
                    s[i][j] = s[i][j] * inv + brow[c];
                else
                    s[i][j] = -1e30f;
            }
        }

        // online softmax update
#pragma unroll
        for (int i = 0; i < 4; i++) {
            float mx = fmaxf(fmaxf(s[i][0], s[i][1]), fmaxf(s[i][2], s[i][3]));
#pragma unroll
            for (int o = 1; o < 16; o <<= 1)
                mx = fmaxf(mx, __shfl_xor_sync(0xffffffffu, mx, o));
            float mn = fmaxf(m_r[i], mx);
            float corr = __expf(m_r[i] - mn);
            m_r[i] = mn;
            l_r[i] *= corr;
            acc[i][0] *= corr; acc[i][1] *= corr;
            float ls = 0.f;
#pragma unroll
            for (int j = 0; j < 4; j++) {
                float p = __expf(s[i][j] - mn);
                s[i][j] = p;
                ls += p;
            }
#pragma unroll
            for (int o = 1; o < 16; o <<= 1)
                ls += __shfl_xor_sync(0xffffffffu, ls, o);
            l_r[i] += ls;
#pragma unroll
            for (int j = 0; j < 4; j++) Ps[ty * 4 + i][tx + 16 * j] = s[i][j];
        }
        __syncthreads();

        // O += P @ V
#pragma unroll
        for (int k = 0; k < 64; k++) {
            float v0 = Vs[k][tx * 2];
            float v1 = Vs[k][tx * 2 + 1];
#pragma unroll
            for (int i = 0; i < 4; i++) {
                float p = Ps[ty * 4 + i][k];
                acc[i][0] += p * v0;
                acc[i][1] += p * v1;
            }
        }
    }

#pragma unroll
    for (int i = 0; i < 4; i++) {
        int r = i0 + ty * 4 + i;
        if (r < NFT) {
            float invl = 1.0f / l_r[i];
            O[(size_t)r * DD + z * HDD + tx * 2 + 0] = acc[i][0] * invl;
            O[(size_t)r * DD + z * HDD + tx * 2 + 1] = acc[i][1] * invl;
        }
    }
}

// ---------------------------------------------------------------------------
// launch
// ---------------------------------------------------------------------------
extern "C" void kernel_launch(void* const* d_in, const int* in_sizes, int n_in,
                              void* d_out, int out_size) {
    const float* x            = (const float*)d_in[0];
    const float* edge_attr    = (const float*)d_in[1];
    const float* node_proj_w  = (const float*)d_in[2];
    const float* node_proj_b  = (const float*)d_in[3];
    const float* in_deg_emb   = (const float*)d_in[4];
    const float* out_deg_emb  = (const float*)d_in[5];
    const float* dist_bias    = (const float*)d_in[6];
    const float* edge_proj_w  = (const float*)d_in[7];
    const float* edge_proj_b  = (const float*)d_in[8];
    const float* cls_token    = (const float*)d_in[9];
    const float* q_w = (const float*)d_in[10];
    const float* q_b = (const float*)d_in[11];
    const float* k_w = (const float*)d_in[12];
    const float* k_b = (const float*)d_in[13];
    const float* v_w = (const float*)d_in[14];
    const float* v_b = (const float*)d_in[15];
    const float* o_w = (const float*)d_in[16];
    const float* o_b = (const float*)d_in[17];
    const float* ffn1_w = (const float*)d_in[18];
    const float* ffn1_b = (const float*)d_in[19];
    const float* ffn2_w = (const float*)d_in[20];
    const float* ffn2_b = (const float*)d_in[21];
    const float* ln1_s = (const float*)d_in[22];
    const float* ln1_b = (const float*)d_in[23];
    const float* ln2_s = (const float*)d_in[24];
    const float* ln2_b = (const float*)d_in[25];
    const float* fn_s = (const float*)d_in[26];
    const float* fn_b = (const float*)d_in[27];
    const int* edge_index  = (const int*)d_in[28];
    const int* dist_matrix = (const int*)d_in[29];
    float* out = (float*)d_out;

    float *h, *hn, *q, *k, *v, *o, *ffn, *bias;
    cudaGetSymbolAddress((void**)&h, g_h);
    cudaGetSymbolAddress((void**)&hn, g_hn);
    cudaGetSymbolAddress((void**)&q, g_q);
    cudaGetSymbolAddress((void**)&k, g_k);
    cudaGetSymbolAddress((void**)&v, g_v);
    cudaGetSymbolAddress((void**)&o, g_o);
    cudaGetSymbolAddress((void**)&ffn, g_ffn);
    cudaGetSymbolAddress((void**)&bias, g_bias);

    zero_deg_kernel<<<(NN + 255) / 256, 256>>>();
    count_deg_kernel<<<(EE + 255) / 256, 256>>>(edge_index);
    node_embed_kernel<<<NN, 256>>>(x, node_proj_w, node_proj_b, in_deg_emb, out_deg_emb);
    cls_kernel<<<1, 256>>>(cls_token);

    size_t nf2 = (size_t)NFT * NFT;
    bias_fill_kernel<<<(unsigned)((nf2 + 255) / 256), 256>>>(dist_matrix, dist_bias);
    edge_bias_kernel<<<(EE + 255) / 256, 256>>>(edge_attr, edge_proj_w, edge_proj_b,
                                                edge_index);

    dim3 gemmD(4, 33);    // Ncol=256, M=2049
    dim3 gemmF1(16, 33);  // Ncol=1024
    dim3 attnG(33, 8);

    for (int l = 0; l < LL; l++) {
        ln_kernel<<<NFT, 256>>>(h, hn, ln1_s + l * DD, ln1_b + l * DD);
        gemm_kernel<0><<<gemmD, 256>>>(hn, q_w + (size_t)l * DD * DD, q_b + l * DD,
                                       nullptr, q, NFT, DD, DD);
        gemm_kernel<0><<<gemmD, 256>>>(hn, k_w + (size_t)l * DD * DD, k_b + l * DD,
                                       nullptr, k, NFT, DD, DD);
        gemm_kernel<0><<<gemmD, 256>>>(hn, v_w + (size_t)l * DD * DD, v_b + l * DD,
                                       nullptr, v, NFT, DD, DD);
        attn_kernel<<<attnG, 256>>>(q, k, v, bias, o);
        gemm_kernel<1><<<gemmD, 256>>>(o, o_w + (size_t)l * DD * DD, o_b + l * DD,
                                       h, h, NFT, DD, DD);
        ln_kernel<<<NFT, 256>>>(h, hn, ln2_s + l * DD, ln2_b + l * DD);
        gemm_kernel<2><<<gemmF1, 256>>>(hn, ffn1_w + (size_t)l * FFND * DD,
                                        ffn1_b + l * FFND, nullptr, ffn, NFT, FFND, DD);
        gemm_kernel<1><<<gemmD, 256>>>(ffn, ffn2_w + (size_t)l * DD * FFND,
                                       ffn2_b + l * DD, h, h, NFT, DD, FFND);
    }

    // final LN into scratch, then copy to output (h then h[0])
    ln_kernel<<<NFT, 256>>>(h, q, fn_s, fn_b);
    size_t total = (size_t)NFT * DD;
    if ((size_t)out_size >= total + DD) {
        cudaMemcpyAsync(out, q, total * sizeof(float), cudaMemcpyDeviceToDevice);
        cudaMemcpyAsync(out + total, q, DD * sizeof(float), cudaMemcpyDeviceToDevice);
    } else if ((size_t)out_size >= total) {
        cudaMemcpyAsync(out, q, total * sizeof(float), cudaMemcpyDeviceToDevice);
    } else {
        cudaMemcpyAsync(out, q, (size_t)out_size * sizeof(float),
                        cudaMemcpyDeviceToDevice);
    }
}

// round 3
// speedup vs baseline: 1.5443x; 1.1244x over previous
#include <cuda_runtime.h>
#include <math.h>
#include <stdint.h>

#define NN 2048
#define NFEAT 64
#define DD 256
#define HH 8
#define HDD 32
#define LL 6
#define FFND 1024
#define EE 32768
#define EFD 16
#define NFT 2049
#define MAXDEGC 64

__device__ float g_h[NFT * DD];
__device__ float g_hn[NFT * DD];
__device__ float g_q[NFT * DD];
__device__ float g_k[NFT * DD];
__device__ float g_v[NFT * DD];
__device__ float g_o[NFT * DD];
__device__ float g_ffn[NFT * FFND];
__device__ float g_bias[(size_t)HH * NFT * NFT];
__device__ int g_indeg[NN];
__device__ int g_outdeg[NN];

static const size_t NF2H = (size_t)NFT * NFT;

// ---------------------------------------------------------------------------
// degree counting
// ---------------------------------------------------------------------------
__global__ void zero_deg_kernel() {
    int i = blockIdx.x * blockDim.x + threadIdx.x;
    if (i < NN) { g_indeg[i] = 0; g_outdeg[i] = 0; }
}

__global__ void count_deg_kernel(const int* __restrict__ edge_index) {
    int e = blockIdx.x * blockDim.x + threadIdx.x;
    if (e < EE) {
        atomicAdd(&g_outdeg[edge_index[e]], 1);
        atomicAdd(&g_indeg[edge_index[EE + e]], 1);
    }
}

// ---------------------------------------------------------------------------
// node embedding
// ---------------------------------------------------------------------------
__global__ void node_embed_kernel(const float* __restrict__ x,
                                  const float* __restrict__ W,
                                  const float* __restrict__ b,
                                  const float* __restrict__ inemb,
                                  const float* __restrict__ outemb) {
    int row = blockIdx.x;
    int col = threadIdx.x;
    __shared__ float xs[NFEAT];
    if (col < NFEAT) xs[col] = x[row * NFEAT + col];
    __syncthreads();
    float acc = 0.f;
#pragma unroll
    for (int k = 0; k < NFEAT; k++) acc += xs[k] * W[col * NFEAT + k];
    int ind = min(g_indeg[row], MAXDEGC);
    int outd = min(g_outdeg[row], MAXDEGC);
    g_h[(size_t)(row + 1) * DD + col] =
        acc + b[col] + inemb[ind * DD + col] + outemb[outd * DD + col];
}

__global__ void cls_kernel(const float* __restrict__ cls) {
    g_h[threadIdx.x] = cls[threadIdx.x];
}

// ---------------------------------------------------------------------------
// spatial bias fill + edge-feature scatter add
// ---------------------------------------------------------------------------
__global__ void bias_fill_kernel(const int* __restrict__ dist,
                                 const float* __restrict__ dist_bias) {
    size_t idx = (size_t)blockIdx.x * blockDim.x + threadIdx.x;
    if (idx >= NF2H) return;
    int i = (int)(idx / NFT);
    int j = (int)(idx % NFT);
    int d = 0;
    if (i > 0 && j > 0) {
        d = dist[(size_t)(i - 1) * NN + (j - 1)];
        d = max(0, min(d, 9));
    }
#pragma unroll
    for (int h = 0; h < HH; h++) {
        g_bias[(size_t)h * NF2H + idx] = dist_bias[d * HH + h];
    }
}

__global__ void edge_bias_kernel(const float* __restrict__ edge_attr,
                                 const float* __restrict__ epw,
                                 const float* __restrict__ epb,
                                 const int* __restrict__ edge_index) {
    int e = blockIdx.x * blockDim.x + threadIdx.x;
    if (e >= EE) return;
    const float* ea = edge_attr + (size_t)e * EFD;
    int src = edge_index[e];
    int dst = edge_index[EE + e];
    size_t base = (size_t)(src + 1) * NFT + (dst + 1);
#pragma unroll
    for (int h = 0; h < HH; h++) {
        float p = epb[h];
#pragma unroll
        for (int k = 0; k < EFD; k++) p += ea[k] * epw[h * EFD + k];
        atomicAdd(&g_bias[(size_t)h * NF2H + base], p);
    }
}

// ---------------------------------------------------------------------------
// layernorm
// ---------------------------------------------------------------------------
__global__ void ln_kernel(const float* __restrict__ in, float* __restrict__ out,
                          const float* __restrict__ s, const float* __restrict__ b) {
    int row = blockIdx.x;
    int c = threadIdx.x;
    float v = in[(size_t)row * DD + c];
    __shared__ float red[256];
    red[c] = v;
    __syncthreads();
    for (int off = 128; off > 0; off >>= 1) {
        if (c < off) red[c] += red[c + off];
        __syncthreads();
    }
    float mean = red[0] / DD;
    __syncthreads();
    float d = v - mean;
    red[c] = d * d;
    __syncthreads();
    for (int off = 128; off > 0; off >>= 1) {
        if (c < off) red[c] += red[c + off];
        __syncthreads();
    }
    float var = red[0] / DD;
    out[(size_t)row * DD + c] = d * rsqrtf(var + 1e-5f) * s[c] + b[c];
}

// ---------------------------------------------------------------------------
// tf32 helpers
// ---------------------------------------------------------------------------
__device__ __forceinline__ uint32_t f2tf32(float v) {
    uint32_t r;
    asm("cvt.rna.tf32.f32 %0, %1;" : "=r"(r) : "f"(v));
    return r;
}

__device__ __forceinline__ void mma_tf32(float c[4], uint32_t a0, uint32_t a1,
                                         uint32_t a2, uint32_t a3,
                                         uint32_t b0, uint32_t b1) {
    asm volatile(
        "mma.sync.aligned.m16n8k8.row.col.f32.tf32.tf32.f32 "
        "{%0,%1,%2,%3}, {%4,%5,%6,%7}, {%8,%9}, {%0,%1,%2,%3};"
        : "+f"(c[0]), "+f"(c[1]), "+f"(c[2]), "+f"(c[3])
        : "r"(a0), "r"(a1), "r"(a2), "r"(a3), "r"(b0), "r"(b1));
}

// ---------------------------------------------------------------------------
// tf32 tensor-core GEMM: out[M,Ncol] = A[M,K] @ W[Ncol,K]^T + bias (+res/gelu)
// Block tile 64x64, 8 warps (warpM 0..3 -> 16 rows, warpN 0..1 -> 32 cols).
// MODE 0: plain, 1: + residual, 2: gelu
// ---------------------------------------------------------------------------
template <int MODE>
__global__ void gemm_tf32_kernel(const float* __restrict__ A, const float* __restrict__ W,
                                 const float* __restrict__ bias,
                                 const float* __restrict__ res,
                                 float* __restrict__ out, int M, int Ncol, int K) {
    __shared__ uint32_t As[64][17];
    __shared__ uint32_t Bs[64][17];
    int tid = threadIdx.x;
    int lane = tid & 31, wid = tid >> 5;
    int warpM = wid & 3, warpN = wid >> 2;
    int m0 = blockIdx.y * 64, n0 = blockIdx.x * 64;
    int g = lane >> 2, t = lane & 3;

    float c[4][4] = {};

    int lr = tid >> 2;         // 0..63
    int lk = (tid & 3) * 4;    // 0,4,8,12

    for (int k0 = 0; k0 < K; k0 += 16) {
        float4 av = make_float4(0.f, 0.f, 0.f, 0.f);
        if (m0 + lr < M) av = *(const float4*)&A[(size_t)(m0 + lr) * K + k0 + lk];
        As[lr][lk + 0] = f2tf32(av.x); As[lr][lk + 1] = f2tf32(av.y);
        As[lr][lk + 2] = f2tf32(av.z); As[lr][lk + 3] = f2tf32(av.w);
        float4 bv = *(const float4*)&W[(size_t)(n0 + lr) * K + k0 + lk];
        Bs[lr][lk + 0] = f2tf32(bv.x); Bs[lr][lk + 1] = f2tf32(bv.y);
        Bs[lr][lk + 2] = f2tf32(bv.z); Bs[lr][lk + 3] = f2tf32(bv.w);
        __syncthreads();
#pragma unroll
        for (int ks = 0; ks < 2; ks++) {
            int kb = ks * 8;
            uint32_t a0 = As[warpM * 16 + g][kb + t];
            uint32_t a1 = As[warpM * 16 + g + 8][kb + t];
            uint32_t a2 = As[warpM * 16 + g][kb + t + 4];
            uint32_t a3 = As[warpM * 16 + g + 8][kb + t + 4];
#pragma unroll
            for (int ni = 0; ni < 4; ni++) {
                uint32_t b0 = Bs[warpN * 32 + ni * 8 + g][kb + t];
                uint32_t b1 = Bs[warpN * 32 + ni * 8 + g][kb + t + 4];
                mma_tf32(c[ni], a0, a1, a2, a3, b0, b1);
            }
        }
        __syncthreads();
    }

#pragma unroll
    for (int ni = 0; ni < 4; ni++) {
        int col = n0 + warpN * 32 + ni * 8 + t * 2;
#pragma unroll
        for (int half = 0; half < 2; half++) {
            int r = m0 + warpM * 16 + g + half * 8;
            if (r >= M) continue;
#pragma unroll
            for (int jj = 0; jj < 2; jj++) {
                float v = c[ni][half * 2 + jj] + bias[col + jj];
                if (MODE == 2) v = 0.5f * v * (1.0f + erff(v * 0.7071067811865475f));
                if (MODE == 1) v += res[(size_t)r * Ncol + col + jj];
                out[(size_t)r * Ncol + col + jj] = v;
            }
        }
    }
}

// ---------------------------------------------------------------------------
// fused flash attention (fp32 FFMA), unchanged from R2
// ---------------------------------------------------------------------------
__global__ void attn_kernel(const float* __restrict__ Q, const float* __restrict__ K,
                            const float* __restrict__ V, const float* __restrict__ bias,
                            float* __restrict__ O) {
    __shared__ float Qs[32][65];
    __shared__ float Ks[32][65];
    __shared__ __align__(16) float Vs[64][36];
    __shared__ float Ps[64][68];

    int z = blockIdx.y;
    int i0 = blockIdx.x * 64;
    int tid = threadIdx.x;
    int tx = tid & 15, ty = tid >> 4;

#pragma unroll
    for (int it = 0; it < 2; it++) {
        int idx = tid + it * 256;
        int m = idx >> 3, k4 = (idx & 7) * 4;
        float4 qv = make_float4(0.f, 0.f, 0.f, 0.f);
        if (i0 + m < NFT)
            qv = *(const float4*)&Q[(size_t)(i0 + m) * DD + z * HDD + k4];
        Qs[k4 + 0][m] = qv.x; Qs[k4 + 1][m] = qv.y;
        Qs[k4 + 2][m] = qv.z; Qs[k4 + 3][m] = qv.w;
    }

    float m_r[4], l_r[4], acc[4][2];
#pragma unroll
    for (int i = 0; i < 4; i++) {
        m_r[i] = -1e30f; l_r[i] = 0.f; acc[i][0] = 0.f; acc[i][1] = 0.f;
    }

    const float inv = 0.17677669529663687f;
    const float* biasH = bias + (size_t)z * NF2H;

    for (int j0 = 0; j0 < NFT; j0 += 64) {
        __syncthreads();
#pragma unroll
        for (int it = 0; it < 2; it++) {
            int idx = tid + it * 256;
            int n = idx >> 3, k4 = (idx & 7) * 4;
            float4 kv = make_float4(0.f, 0.f, 0.f, 0.f);
            float4 vv = kv;
            if (j0 + n < NFT) {
                kv = *(const float4*)&K[(size_t)(j0 + n) * DD + z * HDD + k4];
                vv = *(const float4*)&V[(size_t)(j0 + n) * DD + z * HDD + k4];
            }
            Ks[k4 + 0][n] = kv.x; Ks[k4 + 1][n] = kv.y;
            Ks[k4 + 2][n] = kv.z; Ks[k4 + 3][n] = kv.w;
            *(float4*)&Vs[n][k4] = vv;
        }
        __syncthreads();

        float s[4][4] = {};
#pragma unroll
        for (int k = 0; k < 32; k++) {
            float a[4], b[4];
#pragma unroll
            for (int i = 0; i < 4; i++) a[i] = Qs[k][ty * 4 + i];
#pragma unroll
            for (int j = 0; j < 4; j++) b[j] = Ks[k][tx + 16 * j];
#pragma unroll
            for (int i = 0; i < 4; i++)
#pragma unroll
                for (int j = 0; j < 4; j++) s[i][j] += a[i] * b[j];
        }

#pragma unroll
        for (int i = 0; i < 4; i++) {
            int r = i0 + ty * 4 + i;
            bool rv = (r < NFT);
            const float* brow = biasH + (size_t)r * NFT;
#pragma unroll
            for (int j = 0; j < 4; j++) {
                int c = j0 + tx + 16 * j;
                if (rv && c < NFT)
                    s[i][j] = s[i][j] * inv + brow[c];
                else
                    s[i][j] = -1e30f;
            }
        }

#pragma unroll
        for (int i = 0; i < 4; i++) {
            float mx = fmaxf(fmaxf(s[i][0], s[i][1]), fmaxf(s[i][2], s[i][3]));
#pragma unroll
            for (int o = 1; o < 16; o <<= 1)
                mx = fmaxf(mx, __shfl_xor_sync(0xffffffffu, mx, o));
            float mn = fmaxf(m_r[i], mx);
            float corr = __expf(m_r[i] - mn);
            m_r[i] = mn;
            l_r[i] *= corr;
            acc[i][0] *= corr; acc[i][1] *= corr;
            float ls = 0.f;
#pragma unroll
            for (int j = 0; j < 4; j++) {
                float p = __expf(s[i][j] - mn);
                s[i][j] = p;
                ls += p;
            }
#pragma unroll
            for (int o = 1; o < 16; o <<= 1)
                ls += __shfl_xor_sync(0xffffffffu, ls, o);
            l_r[i] += ls;
#pragma unroll
            for (int j = 0; j < 4; j++) Ps[ty * 4 + i][tx + 16 * j] = s[i][j];
        }
        __syncthreads();

#pragma unroll
        for (int k = 0; k < 64; k++) {
            float v0 = Vs[k][tx * 2];
            float v1 = Vs[k][tx * 2 + 1];
#pragma unroll
            for (int i = 0; i < 4; i++) {
                float p = Ps[ty * 4 + i][k];
                acc[i][0] += p * v0;
                acc[i][1] += p * v1;
            }
        }
    }

#pragma unroll
    for (int i = 0; i < 4; i++) {
        int r = i0 + ty * 4 + i;
        if (r < NFT) {
            float invl = 1.0f / l_r[i];
            O[(size_t)r * DD + z * HDD + tx * 2 + 0] = acc[i][0] * invl;
            O[(size_t)r * DD + z * HDD + tx * 2 + 1] = acc[i][1] * invl;
        }
    }
}

// ---------------------------------------------------------------------------
// launch
// ---------------------------------------------------------------------------
extern "C" void kernel_launch(void* const* d_in, const int* in_sizes, int n_in,
                              void* d_out, int out_size) {
    const float* x            = (const float*)d_in[0];
    const float* edge_attr    = (const float*)d_in[1];
    const float* node_proj_w  = (const float*)d_in[2];
    const float* node_proj_b  = (const float*)d_in[3];
    const float* in_deg_emb   = (const float*)d_in[4];
    const float* out_deg_emb  = (const float*)d_in[5];
    const float* dist_bias    = (const float*)d_in[6];
    const float* edge_proj_w  = (const float*)d_in[7];
    const float* edge_proj_b  = (const float*)d_in[8];
    const float* cls_token    = (const float*)d_in[9];
    const float* q_w = (const float*)d_in[10];
    const float* q_b = (const float*)d_in[11];
    const float* k_w = (const float*)d_in[12];
    const float* k_b = (const float*)d_in[13];
    const float* v_w = (const float*)d_in[14];
    const float* v_b = (const float*)d_in[15];
    const float* o_w = (const float*)d_in[16];
    const float* o_b = (const float*)d_in[17];
    const float* ffn1_w = (const float*)d_in[18];
    const float* ffn1_b = (const float*)d_in[19];
    const float* ffn2_w = (const float*)d_in[20];
    const float* ffn2_b = (const float*)d_in[21];
    const float* ln1_s = (const float*)d_in[22];
    const float* ln1_b = (const float*)d_in[23];
    const float* ln2_s = (const float*)d_in[24];
    const float* ln2_b = (const float*)d_in[25];
    const float* fn_s = (const float*)d_in[26];
    const float* fn_b = (const float*)d_in[27];
    const int* edge_index  = (const int*)d_in[28];
    const int* dist_matrix = (const int*)d_in[29];
    float* out = (float*)d_out;

    float *h, *hn, *q, *k, *v, *o, *ffn, *bias;
    cudaGetSymbolAddress((void**)&h, g_h);
    cudaGetSymbolAddress((void**)&hn, g_hn);
    cudaGetSymbolAddress((void**)&q, g_q);
    cudaGetSymbolAddress((void**)&k, g_k);
    cudaGetSymbolAddress((void**)&v, g_v);
    cudaGetSymbolAddress((void**)&o, g_o);
    cudaGetSymbolAddress((void**)&ffn, g_ffn);
    cudaGetSymbolAddress((void**)&bias, g_bias);

    zero_deg_kernel<<<(NN + 255) / 256, 256>>>();
    count_deg_kernel<<<(EE + 255) / 256, 256>>>(edge_index);
    node_embed_kernel<<<NN, 256>>>(x, node_proj_w, node_proj_b, in_deg_emb, out_deg_emb);
    cls_kernel<<<1, 256>>>(cls_token);

    size_t nf2 = (size_t)NFT * NFT;
    bias_fill_kernel<<<(unsigned)((nf2 + 255) / 256), 256>>>(dist_matrix, dist_bias);
    edge_bias_kernel<<<(EE + 255) / 256, 256>>>(edge_attr, edge_proj_w, edge_proj_b,
                                                edge_index);

    dim3 gemmD(4, 33);    // Ncol=256, M=2049
    dim3 gemmF1(16, 33);  // Ncol=1024
    dim3 attnG(33, 8);

    for (int l = 0; l < LL; l++) {
        ln_kernel<<<NFT, 256>>>(h, hn, ln1_s + l * DD, ln1_b + l * DD);
        gemm_tf32_kernel<0><<<gemmD, 256>>>(hn, q_w + (size_t)l * DD * DD, q_b + l * DD,
                                            nullptr, q, NFT, DD, DD);
        gemm_tf32_kernel<0><<<gemmD, 256>>>(hn, k_w + (size_t)l * DD * DD, k_b + l * DD,
                                            nullptr, k, NFT, DD, DD);
        gemm_tf32_kernel<0><<<gemmD, 256>>>(hn, v_w + (size_t)l * DD * DD, v_b + l * DD,
                                            nullptr, v, NFT, DD, DD);
        attn_kernel<<<attnG, 256>>>(q, k, v, bias, o);
        gemm_tf32_kernel<1><<<gemmD, 256>>>(o, o_w + (size_t)l * DD * DD, o_b + l * DD,
                                            h, h, NFT, DD, DD);
        ln_kernel<<<NFT, 256>>>(h, hn, ln2_s + l * DD, ln2_b + l * DD);
        gemm_tf32_kernel<2><<<gemmF1, 256>>>(hn, ffn1_w + (size_t)l * FFND * DD,
                                             ffn1_b + l * FFND, nullptr, ffn, NFT, FFND, DD);
        gemm_tf32_kernel<1><<<gemmD, 256>>>(ffn, ffn2_w + (size_t)l * DD * FFND,
                                            ffn2_b + l * DD, h, h, NFT, DD, FFND);
    }

    ln_kernel<<<NFT, 256>>>(h, q, fn_s, fn_b);
    size_t total = (size_t)NFT * DD;
    if ((size_t)out_size >= total + DD) {
        cudaMemcpyAsync(out, q, total * sizeof(float), cudaMemcpyDeviceToDevice);
        cudaMemcpyAsync(out + total, q, DD * sizeof(float), cudaMemcpyDeviceToDevice);
    } else if ((size_t)out_size >= total) {
        cudaMemcpyAsync(out, q, total * sizeof(float), cudaMemcpyDeviceToDevice);
    } else {
        cudaMemcpyAsync(out, q, (size_t)out_size * sizeof(float),
                        cudaMemcpyDeviceToDevice);
    }
}

// round 4
// speedup vs baseline: 2.4846x; 1.6089x over previous
#include <cuda_runtime.h>
#include <cuda_bf16.h>
#include <math.h>
#include <stdint.h>

#define NN 2048
#define NFEAT 64
#define DD 256
#define HH 8
#define HDD 32
#define LL 6
#define FFND 1024
#define EE 32768
#define EFD 16
#define NFT 2049
#define MAXDEGC 64

__device__ float g_h[NFT * DD];
__device__ float g_hn[NFT * DD];
__device__ float g_q[NFT * DD];
__device__ float g_k[NFT * DD];
__device__ float g_v[NFT * DD];
__device__ float g_o[NFT * DD];
__device__ float g_ffn[NFT * FFND];
__device__ float g_bias[(size_t)HH * NFT * NFT];
__device__ int g_indeg[NN];
__device__ int g_outdeg[NN];

static const size_t NF2H = (size_t)NFT * NFT;

// ---------------------------------------------------------------------------
// bf16 split helpers: x = hi + lo (hi,lo bf16), packed pairs (x0->low, x1->high)
// ---------------------------------------------------------------------------
__device__ __forceinline__ void split2(float x0, float x1, uint32_t& hi, uint32_t& lo) {
    __nv_bfloat16 h0 = __float2bfloat16_rn(x0);
    __nv_bfloat16 h1 = __float2bfloat16_rn(x1);
    float r0 = x0 - __bfloat162float(h0);
    float r1 = x1 - __bfloat162float(h1);
    __nv_bfloat16 l0 = __float2bfloat16_rn(r0);
    __nv_bfloat16 l1 = __float2bfloat16_rn(r1);
    union { __nv_bfloat162 v; uint32_t u; } a, b;
    a.v = __halves2bfloat162(h0, h1);
    b.v = __halves2bfloat162(l0, l1);
    hi = a.u; lo = b.u;
}

__device__ __forceinline__ void mma_bf16(float c[4], uint32_t a0, uint32_t a1,
                                         uint32_t a2, uint32_t a3,
                                         uint32_t b0, uint32_t b1) {
    asm volatile(
        "mma.sync.aligned.m16n8k16.row.col.f32.bf16.bf16.f32 "
        "{%0,%1,%2,%3}, {%4,%5,%6,%7}, {%8,%9}, {%0,%1,%2,%3};"
        : "+f"(c[0]), "+f"(c[1]), "+f"(c[2]), "+f"(c[3])
        : "r"(a0), "r"(a1), "r"(a2), "r"(a3), "r"(b0), "r"(b1));
}

// ---------------------------------------------------------------------------
// degree counting
// ---------------------------------------------------------------------------
__global__ void zero_deg_kernel() {
    int i = blockIdx.x * blockDim.x + threadIdx.x;
    if (i < NN) { g_indeg[i] = 0; g_outdeg[i] = 0; }
}

__global__ void count_deg_kernel(const int* __restrict__ edge_index) {
    int e = blockIdx.x * blockDim.x + threadIdx.x;
    if (e < EE) {
        atomicAdd(&g_outdeg[edge_index[e]], 1);
        atomicAdd(&g_indeg[edge_index[EE + e]], 1);
    }
}

// ---------------------------------------------------------------------------
// node embedding
// ---------------------------------------------------------------------------
__global__ void node_embed_kernel(const float* __restrict__ x,
                                  const float* __restrict__ W,
                                  const float* __restrict__ b,
                                  const float* __restrict__ inemb,
                                  const float* __restrict__ outemb) {
    int row = blockIdx.x;
    int col = threadIdx.x;
    __shared__ float xs[NFEAT];
    if (col < NFEAT) xs[col] = x[row * NFEAT + col];
    __syncthreads();
    float acc = 0.f;
#pragma unroll
    for (int k = 0; k < NFEAT; k++) acc += xs[k] * W[col * NFEAT + k];
    int ind = min(g_indeg[row], MAXDEGC);
    int outd = min(g_outdeg[row], MAXDEGC);
    g_h[(size_t)(row + 1) * DD + col] =
        acc + b[col] + inemb[ind * DD + col] + outemb[outd * DD + col];
}

__global__ void cls_kernel(const float* __restrict__ cls) {
    g_h[threadIdx.x] = cls[threadIdx.x];
}

// ---------------------------------------------------------------------------
// spatial bias fill + edge-feature scatter add
// ---------------------------------------------------------------------------
__global__ void bias_fill_kernel(const int* __restrict__ dist,
                                 const float* __restrict__ dist_bias) {
    size_t idx = (size_t)blockIdx.x * blockDim.x + threadIdx.x;
    if (idx >= NF2H) return;
    int i = (int)(idx / NFT);
    int j = (int)(idx % NFT);
    int d = 0;
    if (i > 0 && j > 0) {
        d = dist[(size_t)(i - 1) * NN + (j - 1)];
        d = max(0, min(d, 9));
    }
#pragma unroll
    for (int h = 0; h < HH; h++) {
        g_bias[(size_t)h * NF2H + idx] = dist_bias[d * HH + h];
    }
}

__global__ void edge_bias_kernel(const float* __restrict__ edge_attr,
                                 const float* __restrict__ epw,
                                 const float* __restrict__ epb,
                                 const int* __restrict__ edge_index) {
    int e = blockIdx.x * blockDim.x + threadIdx.x;
    if (e >= EE) return;
    const float* ea = edge_attr + (size_t)e * EFD;
    int src = edge_index[e];
    int dst = edge_index[EE + e];
    size_t base = (size_t)(src + 1) * NFT + (dst + 1);
#pragma unroll
    for (int h = 0; h < HH; h++) {
        float p = epb[h];
#pragma unroll
        for (int k = 0; k < EFD; k++) p += ea[k] * epw[h * EFD + k];
        atomicAdd(&g_bias[(size_t)h * NF2H + base], p);
    }
}

// ---------------------------------------------------------------------------
// layernorm
// ---------------------------------------------------------------------------
__global__ void ln_kernel(const float* __restrict__ in, float* __restrict__ out,
                          const float* __restrict__ s, const float* __restrict__ b) {
    int row = blockIdx.x;
    int c = threadIdx.x;
    float v = in[(size_t)row * DD + c];
    __shared__ float red[256];
    red[c] = v;
    __syncthreads();
    for (int off = 128; off > 0; off >>= 1) {
        if (c < off) red[c] += red[c + off];
        __syncthreads();
    }
    float mean = red[0] / DD;
    __syncthreads();
    float d = v - mean;
    red[c] = d * d;
    __syncthreads();
    for (int off = 128; off > 0; off >>= 1) {
        if (c < off) red[c] += red[c + off];
        __syncthreads();
    }
    float var = red[0] / DD;
    out[(size_t)row * DD + c] = d * rsqrtf(var + 1e-5f) * s[c] + b[c];
}

// ---------------------------------------------------------------------------
// split-bf16 tensor-core GEMM: out[M,N] = A[M,K] @ W[N,K]^T + bias (+res/gelu)
// 64x64 block tile, 8 warps (warpM: 16 rows, warpN: 32 cols), k-step 32.
// 3-MMA decomposition: ~fp32-accurate.
// ---------------------------------------------------------------------------
template <int MODE>
__global__ void gemm_bf16_kernel(const float* __restrict__ A, const float* __restrict__ W,
                                 const float* __restrict__ bias,
                                 const float* __restrict__ res,
                                 float* __restrict__ out, int M, int Ncol, int K) {
    __shared__ uint32_t Ah[64][20], Al[64][20];
    __shared__ uint32_t Bh[64][20], Bl[64][20];
    int tid = threadIdx.x;
    int lane = tid & 31, wid = tid >> 5;
    int warpM = wid & 3, warpN = wid >> 2;
    int m0 = blockIdx.y * 64, n0 = blockIdx.x * 64;
    int g = lane >> 2, t = lane & 3;

    float c[4][4] = {};

    int lr = tid >> 3;        // 0..31
    int lk = (tid & 7) * 4;   // 0..28
    int lp = lk >> 1;         // pair index 0..14

    float4 ra[2], rb[2];
#pragma unroll
    for (int p = 0; p < 2; p++) {
        int r = lr + p * 32;
        ra[p] = make_float4(0.f, 0.f, 0.f, 0.f);
        if (m0 + r < M) ra[p] = *(const float4*)&A[(size_t)(m0 + r) * K + lk];
        rb[p] = *(const float4*)&W[(size_t)(n0 + r) * K + lk];
    }

    for (int k0 = 0; k0 < K; k0 += 32) {
        __syncthreads();
#pragma unroll
        for (int p = 0; p < 2; p++) {
            int r = lr + p * 32;
            uint32_t h, lo;
            split2(ra[p].x, ra[p].y, h, lo); Ah[r][lp] = h;     Al[r][lp] = lo;
            split2(ra[p].z, ra[p].w, h, lo); Ah[r][lp + 1] = h; Al[r][lp + 1] = lo;
            split2(rb[p].x, rb[p].y, h, lo); Bh[r][lp] = h;     Bl[r][lp] = lo;
            split2(rb[p].z, rb[p].w, h, lo); Bh[r][lp + 1] = h; Bl[r][lp + 1] = lo;
        }
        __syncthreads();
        if (k0 + 32 < K) {
#pragma unroll
            for (int p = 0; p < 2; p++) {
                int r = lr + p * 32;
                ra[p] = make_float4(0.f, 0.f, 0.f, 0.f);
                if (m0 + r < M)
                    ra[p] = *(const float4*)&A[(size_t)(m0 + r) * K + k0 + 32 + lk];
                rb[p] = *(const float4*)&W[(size_t)(n0 + r) * K + k0 + 32 + lk];
            }
        }
#pragma unroll
        for (int kk = 0; kk < 2; kk++) {
            int ar = warpM * 16 + g;
            uint32_t ah0 = Ah[ar][kk * 8 + t],     ah1 = Ah[ar + 8][kk * 8 + t];
            uint32_t ah2 = Ah[ar][kk * 8 + t + 4], ah3 = Ah[ar + 8][kk * 8 + t + 4];
            uint32_t al0 = Al[ar][kk * 8 + t],     al1 = Al[ar + 8][kk * 8 + t];
            uint32_t al2 = Al[ar][kk * 8 + t + 4], al3 = Al[ar + 8][kk * 8 + t + 4];
#pragma unroll
            for (int ni = 0; ni < 4; ni++) {
                int br = warpN * 32 + ni * 8 + g;
                uint32_t b0h = Bh[br][kk * 8 + t], b1h = Bh[br][kk * 8 + t + 4];
                uint32_t b0l = Bl[br][kk * 8 + t], b1l = Bl[br][kk * 8 + t + 4];
                mma_bf16(c[ni], ah0, ah1, ah2, ah3, b0h, b1h);
                mma_bf16(c[ni], ah0, ah1, ah2, ah3, b0l, b1l);
                mma_bf16(c[ni], al0, al1, al2, al3, b0h, b1h);
            }
        }
    }

#pragma unroll
    for (int ni = 0; ni < 4; ni++) {
        int col = n0 + warpN * 32 + ni * 8 + t * 2;
#pragma unroll
        for (int half = 0; half < 2; half++) {
            int r = m0 + warpM * 16 + g + half * 8;
            if (r >= M) continue;
#pragma unroll
            for (int jj = 0; jj < 2; jj++) {
                float v = c[ni][half * 2 + jj] + bias[col + jj];
                if (MODE == 2) v = 0.5f * v * (1.0f + erff(v * 0.7071067811865475f));
                if (MODE == 1) v += res[(size_t)r * Ncol + col + jj];
                out[(size_t)r * Ncol + col + jj] = v;
            }
        }
    }
}

// ---------------------------------------------------------------------------
// fused flash attention, split-bf16 MMA.
// Block: 128 q-rows x 1 head, 8 warps; each warp: 16 rows x all 64 keys/tile.
// P fragment reused directly from S C-fragment (layouts match).
// ---------------------------------------------------------------------------
__global__ void attn_kernel(const float* __restrict__ Q, const float* __restrict__ K,
                            const float* __restrict__ V, const float* __restrict__ bias,
                            float* __restrict__ O) {
    __shared__ uint32_t Kh[64][20], Kl[64][20];   // [key][hd-pair], 16 used
    __shared__ uint32_t Vh[32][36], Vl[32][36];   // [hd][key-pair], 32 used

    int tid = threadIdx.x;
    int lane = tid & 31, w = tid >> 5;
    int g = lane >> 2, t = lane & 3;
    int z = blockIdx.y;
    int i0 = blockIdx.x * 128;
    int r0 = i0 + w * 16 + g;
    int r1 = r0 + 8;

    // Q fragments (hi/lo), held in registers for the whole block
    uint32_t qh[2][4], ql[2][4];
#pragma unroll
    for (int kk = 0; kk < 2; kk++) {
#pragma unroll
        for (int j = 0; j < 4; j++) {
            int rr = r0 + (j & 1) * 8;
            int cc = z * HDD + kk * 16 + (j >> 1) * 8 + t * 2;
            float2 qv = make_float2(0.f, 0.f);
            if (rr < NFT) qv = *(const float2*)&Q[(size_t)rr * DD + cc];
            split2(qv.x, qv.y, qh[kk][j], ql[kk][j]);
        }
    }

    float m[2] = {-1e30f, -1e30f}, l[2] = {0.f, 0.f};
    float co[4][4] = {};

    int lkey = tid >> 3;        // 0..31
    int lk4 = (tid & 7) * 4;    // 0..28
    int lp = lk4 >> 1;

    const float inv = 0.17677669529663687f;  // 1/sqrt(32)
    int br0 = min(r0, NFT - 1), br1 = min(r1, NFT - 1);
    const float* bp0 = bias + (size_t)z * NF2H + (size_t)br0 * NFT;
    const float* bp1 = bias + (size_t)z * NF2H + (size_t)br1 * NFT;

    float4 rka, rkb, rva, rvb;
    {
        rka = rkb = rva = rvb = make_float4(0.f, 0.f, 0.f, 0.f);
        if (lkey < NFT) rka = *(const float4*)&K[(size_t)lkey * DD + z * HDD + lk4];
        rkb = *(const float4*)&K[(size_t)(lkey + 32) * DD + z * HDD + lk4];
        rva = *(const float4*)&V[(size_t)(2 * lkey) * DD + z * HDD + lk4];
        rvb = *(const float4*)&V[(size_t)(2 * lkey + 1) * DD + z * HDD + lk4];
    }

    for (int jt = 0; jt < 33; jt++) {
        int j0 = jt * 64;
        __syncthreads();
        {
            uint32_t h, lo;
            split2(rka.x, rka.y, h, lo); Kh[lkey][lp] = h;          Kl[lkey][lp] = lo;
            split2(rka.z, rka.w, h, lo); Kh[lkey][lp + 1] = h;      Kl[lkey][lp + 1] = lo;
            split2(rkb.x, rkb.y, h, lo); Kh[lkey + 32][lp] = h;     Kl[lkey + 32][lp] = lo;
            split2(rkb.z, rkb.w, h, lo); Kh[lkey + 32][lp + 1] = h; Kl[lkey + 32][lp + 1] = lo;
            split2(rva.x, rvb.x, h, lo); Vh[lk4 + 0][lkey] = h;     Vl[lk4 + 0][lkey] = lo;
            split2(rva.y, rvb.y, h, lo); Vh[lk4 + 1][lkey] = h;     Vl[lk4 + 1][lkey] = lo;
            split2(rva.z, rvb.z, h, lo); Vh[lk4 + 2][lkey] = h;     Vl[lk4 + 2][lkey] = lo;
            split2(rva.w, rvb.w, h, lo); Vh[lk4 + 3][lkey] = h;     Vl[lk4 + 3][lkey] = lo;
        }
        __syncthreads();
        if (jt + 1 < 33) {
            int n0 = (jt + 1) * 64;
            rka = rkb = rva = rvb = make_float4(0.f, 0.f, 0.f, 0.f);
            if (n0 + lkey < NFT)
                rka = *(const float4*)&K[(size_t)(n0 + lkey) * DD + z * HDD + lk4];
            if (n0 + lkey + 32 < NFT)
                rkb = *(const float4*)&K[(size_t)(n0 + lkey + 32) * DD + z * HDD + lk4];
            if (n0 + 2 * lkey < NFT)
                rva = *(const float4*)&V[(size_t)(n0 + 2 * lkey) * DD + z * HDD + lk4];
            if (n0 + 2 * lkey + 1 < NFT)
                rvb = *(const float4*)&V[(size_t)(n0 + 2 * lkey + 1) * DD + z * HDD + lk4];
        }

        // S = Q @ K^T (split-bf16, 3 MMAs per tile)
        float cs[8][4] = {};
#pragma unroll
        for (int kk = 0; kk < 2; kk++) {
#pragma unroll
            for (int ni = 0; ni < 8; ni++) {
                int br = ni * 8 + g;
                uint32_t b0h = Kh[br][kk * 8 + t], b1h = Kh[br][kk * 8 + t + 4];
                uint32_t b0l = Kl[br][kk * 8 + t], b1l = Kl[br][kk * 8 + t + 4];
                mma_bf16(cs[ni], qh[kk][0], qh[kk][1], qh[kk][2], qh[kk][3], b0h, b1h);
                mma_bf16(cs[ni], qh[kk][0], qh[kk][1], qh[kk][2], qh[kk][3], b0l, b1l);
                mma_bf16(cs[ni], ql[kk][0], ql[kk][1], ql[kk][2], ql[kk][3], b0h, b1h);
            }
        }

        // scale + bias + col guards
#pragma unroll
        for (int ni = 0; ni < 8; ni++) {
            int col = j0 + ni * 8 + t * 2;
            bool v0 = col < NFT, v1 = col + 1 < NFT;
            float b00 = bp0[col], b01 = bp0[col + 1];
            float b10 = bp1[col], b11 = bp1[col + 1];
            cs[ni][0] = v0 ? cs[ni][0] * inv + b00 : -1e30f;
            cs[ni][1] = v1 ? cs[ni][1] * inv + b01 : -1e30f;
            cs[ni][2] = v0 ? cs[ni][2] * inv + b10 : -1e30f;
            cs[ni][3] = v1 ? cs[ni][3] * inv + b11 : -1e30f;
        }

        // online softmax (two row-halves per thread)
#pragma unroll
        for (int hh = 0; hh < 2; hh++) {
            int c0 = hh * 2;
            float mx = -1e30f;
#pragma unroll
            for (int ni = 0; ni < 8; ni++)
                mx = fmaxf(mx, fmaxf(cs[ni][c0], cs[ni][c0 + 1]));
            mx = fmaxf(mx, __shfl_xor_sync(0xffffffffu, mx, 1));
            mx = fmaxf(mx, __shfl_xor_sync(0xffffffffu, mx, 2));
            float mn = fmaxf(m[hh], mx);
            float corr = __expf(m[hh] - mn);
            m[hh] = mn;
            l[hh] *= corr;
#pragma unroll
            for (int ni = 0; ni < 4; ni++) {
                co[ni][c0] *= corr;
                co[ni][c0 + 1] *= corr;
            }
            float sum = 0.f;
#pragma unroll
            for (int ni = 0; ni < 8; ni++) {
                float p0 = __expf(cs[ni][c0] - mn);
                float p1 = __expf(cs[ni][c0 + 1] - mn);
                cs[ni][c0] = p0; cs[ni][c0 + 1] = p1;
                sum += p0 + p1;
            }
            sum += __shfl_xor_sync(0xffffffffu, sum, 1);
            sum += __shfl_xor_sync(0xffffffffu, sum, 2);
            l[hh] += sum;
        }

        // O += P @ V  (P fragments built in registers from cs)
#pragma unroll
        for (int kk = 0; kk < 4; kk++) {
            uint32_t ah[4], al[4];
            split2(cs[2 * kk][0], cs[2 * kk][1], ah[0], al[0]);
            split2(cs[2 * kk][2], cs[2 * kk][3], ah[1], al[1]);
            split2(cs[2 * kk + 1][0], cs[2 * kk + 1][1], ah[2], al[2]);
            split2(cs[2 * kk + 1][2], cs[2 * kk + 1][3], ah[3], al[3]);
#pragma unroll
            for (int ni = 0; ni < 4; ni++) {
                int vr = ni * 8 + g;
                uint32_t b0h = Vh[vr][kk * 8 + t], b1h = Vh[vr][kk * 8 + t + 4];
                uint32_t b0l = Vl[vr][kk * 8 + t], b1l = Vl[vr][kk * 8 + t + 4];
                mma_bf16(co[ni], ah[0], ah[1], ah[2], ah[3], b0h, b1h);
                mma_bf16(co[ni], ah[0], ah[1], ah[2], ah[3], b0l, b1l);
                mma_bf16(co[ni], al[0], al[1], al[2], al[3], b0h, b1h);
            }
        }
    }

    float inv0 = 1.f / l[0], inv1 = 1.f / l[1];
#pragma unroll
    for (int ni = 0; ni < 4; ni++) {
        int col = z * HDD + ni * 8 + t * 2;
        if (r0 < NFT) {
            O[(size_t)r0 * DD + col] = co[ni][0] * inv0;
            O[(size_t)r0 * DD + col + 1] = co[ni][1] * inv0;
        }
        if (r1 < NFT) {
            O[(size_t)r1 * DD + col] = co[ni][2] * inv1;
            O[(size_t)r1 * DD + col + 1] = co[ni][3] * inv1;
        }
    }
}

// ---------------------------------------------------------------------------
// launch
// ---------------------------------------------------------------------------
extern "C" void kernel_launch(void* const* d_in, const int* in_sizes, int n_in,
                              void* d_out, int out_size) {
    const float* x            = (const float*)d_in[0];
    const float* edge_attr    = (const float*)d_in[1];
    const float* node_proj_w  = (const float*)d_in[2];
    const float* node_proj_b  = (const float*)d_in[3];
    const float* in_deg_emb   = (const float*)d_in[4];
    const float* out_deg_emb  = (const float*)d_in[5];
    const float* dist_bias    = (const float*)d_in[6];
    const float* edge_proj_w  = (const float*)d_in[7];
    const float* edge_proj_b  = (const float*)d_in[8];
    const float* cls_token    = (const float*)d_in[9];
    const float* q_w = (const float*)d_in[10];
    const float* q_b = (const float*)d_in[11];
    const float* k_w = (const float*)d_in[12];
    const float* k_b = (const float*)d_in[13];
    const float* v_w = (const float*)d_in[14];
    const float* v_b = (const float*)d_in[15];
    const float* o_w = (const float*)d_in[16];
    const float* o_b = (const float*)d_in[17];
    const float* ffn1_w = (const float*)d_in[18];
    const float* ffn1_b = (const float*)d_in[19];
    const float* ffn2_w = (const float*)d_in[20];
    const float* ffn2_b = (const float*)d_in[21];
    const float* ln1_s = (const float*)d_in[22];
    const float* ln1_b = (const float*)d_in[23];
    const float* ln2_s = (const float*)d_in[24];
    const float* ln2_b = (const float*)d_in[25];
    const float* fn_s = (const float*)d_in[26];
    const float* fn_b = (const float*)d_in[27];
    const int* edge_index  = (const int*)d_in[28];
    const int* dist_matrix = (const int*)d_in[29];
    float* out = (float*)d_out;

    float *h, *hn, *q, *k, *v, *o, *ffn, *bias;
    cudaGetSymbolAddress((void**)&h, g_h);
    cudaGetSymbolAddress((void**)&hn, g_hn);
    cudaGetSymbolAddress((void**)&q, g_q);
    cudaGetSymbolAddress((void**)&k, g_k);
    cudaGetSymbolAddress((void**)&v, g_v);
    cudaGetSymbolAddress((void**)&o, g_o);
    cudaGetSymbolAddress((void**)&ffn, g_ffn);
    cudaGetSymbolAddress((void**)&bias, g_bias);

    zero_deg_kernel<<<(NN + 255) / 256, 256>>>();
    count_deg_kernel<<<(EE + 255) / 256, 256>>>(edge_index);
    node_embed_kernel<<<NN, 256>>>(x, node_proj_w, node_proj_b, in_deg_emb, out_deg_emb);
    cls_kernel<<<1, 256>>>(cls_token);

    size_t nf2 = (size_t)NFT * NFT;
    bias_fill_kernel<<<(unsigned)((nf2 + 255) / 256), 256>>>(dist_matrix, dist_bias);
    edge_bias_kernel<<<(EE + 255) / 256, 256>>>(edge_attr, edge_proj_w, edge_proj_b,
                                                edge_index);

    dim3 gemmD(4, 33);    // Ncol=256, M=2049
    dim3 gemmF1(16, 33);  // Ncol=1024
    dim3 attnG(17, 8);    // 128-row i-tiles x heads

    for (int l = 0; l < LL; l++) {
        ln_kernel<<<NFT, 256>>>(h, hn, ln1_s + l * DD, ln1_b + l * DD);
        gemm_bf16_kernel<0><<<gemmD, 256>>>(hn, q_w + (size_t)l * DD * DD, q_b + l * DD,
                                            nullptr, q, NFT, DD, DD);
        gemm_bf16_kernel<0><<<gemmD, 256>>>(hn, k_w + (size_t)l * DD * DD, k_b + l * DD,
                                            nullptr, k, NFT, DD, DD);
        gemm_bf16_kernel<0><<<gemmD, 256>>>(hn, v_w + (size_t)l * DD * DD, v_b + l * DD,
                                            nullptr, v, NFT, DD, DD);
        attn_kernel<<<attnG, 256>>>(q, k, v, bias, o);
        gemm_bf16_kernel<1><<<gemmD, 256>>>(o, o_w + (size_t)l * DD * DD, o_b + l * DD,
                                            h, h, NFT, DD, DD);
        ln_kernel<<<NFT, 256>>>(h, hn, ln2_s + l * DD, ln2_b + l * DD);
        gemm_bf16_kernel<2><<<gemmF1, 256>>>(hn, ffn1_w + (size_t)l * FFND * DD,
                                             ffn1_b + l * FFND, nullptr, ffn, NFT, FFND, DD);
        gemm_bf16_kernel<1><<<gemmD, 256>>>(ffn, ffn2_w + (size_t)l * DD * FFND,
                                            ffn2_b + l * DD, h, h, NFT, DD, FFND);
    }

    ln_kernel<<<NFT, 256>>>(h, q, fn_s, fn_b);
    size_t total = (size_t)NFT * DD;
    if ((size_t)out_size >= total + DD) {
        cudaMemcpyAsync(out, q, total * sizeof(float), cudaMemcpyDeviceToDevice);
        cudaMemcpyAsync(out + total, q, DD * sizeof(float), cudaMemcpyDeviceToDevice);
    } else if ((size_t)out_size >= total) {
        cudaMemcpyAsync(out, q, total * sizeof(float), cudaMemcpyDeviceToDevice);
    } else {
        cudaMemcpyAsync(out, q, (size_t)out_size * sizeof(float),
                        cudaMemcpyDeviceToDevice);
    }
}

// round 5
// speedup vs baseline: 2.7508x; 1.1071x over previous
#include <cuda_runtime.h>
#include <cuda_bf16.h>
#include <math.h>
#include <stdint.h>

#define NN 2048
#define NFEAT 64
#define DD 256
#define HH 8
#define HDD 32
#define LL 6
#define FFND 1024
#define EE 32768
#define EFD 16
#define NFT 2049
#define MAXDEGC 64
#define D2 128
#define F2 512
#define BP 1025   // bias pairs per row (2049 cols -> 1025 pairs, last padded)

__device__ float g_h[NFT * DD];
__device__ float g_fin[NFT * DD];
__device__ uint32_t g_hnh[NFT * D2], g_hnl[NFT * D2];
__device__ uint32_t g_qh[NFT * D2], g_ql[NFT * D2];
__device__ uint32_t g_kh[NFT * D2], g_kl[NFT * D2];
__device__ uint32_t g_vh[NFT * D2], g_vl[NFT * D2];
__device__ uint32_t g_oh[NFT * D2], g_ol[NFT * D2];
__device__ uint32_t g_fh[NFT * F2], g_fl[NFT * F2];
__device__ float g_bias[(size_t)HH * NFT * NFT];
__device__ uint32_t g_biasb[(size_t)HH * NFT * BP];
// packed split weights: q|k|v|o|ffn1|ffn2
#define WOFF_Q 0
#define WOFF_K 196608
#define WOFF_V 393216
#define WOFF_O 589824
#define WOFF_F1 786432
#define WOFF_F2 1572864
#define WTOT 2359296
__device__ uint32_t g_wh[WTOT], g_wl[WTOT];
__device__ int g_indeg[NN];
__device__ int g_outdeg[NN];

static const size_t NF2H = (size_t)NFT * NFT;

// ---------------------------------------------------------------------------
// helpers
// ---------------------------------------------------------------------------
__device__ __forceinline__ void split2(float x0, float x1, uint32_t& hi, uint32_t& lo) {
    __nv_bfloat16 h0 = __float2bfloat16_rn(x0);
    __nv_bfloat16 h1 = __float2bfloat16_rn(x1);
    float r0 = x0 - __bfloat162float(h0);
    float r1 = x1 - __bfloat162float(h1);
    __nv_bfloat16 l0 = __float2bfloat16_rn(r0);
    __nv_bfloat16 l1 = __float2bfloat16_rn(r1);
    union { __nv_bfloat162 v; uint32_t u; } a, b;
    a.v = __halves2bfloat162(h0, h1);
    b.v = __halves2bfloat162(l0, l1);
    hi = a.u; lo = b.u;
}

__device__ __forceinline__ void mma_bf16(float c[4], uint32_t a0, uint32_t a1,
                                         uint32_t a2, uint32_t a3,
                                         uint32_t b0, uint32_t b1) {
    asm volatile(
        "mma.sync.aligned.m16n8k16.row.col.f32.bf16.bf16.f32 "
        "{%0,%1,%2,%3}, {%4,%5,%6,%7}, {%8,%9}, {%0,%1,%2,%3};"
        : "+f"(c[0]), "+f"(c[1]), "+f"(c[2]), "+f"(c[3])
        : "r"(a0), "r"(a1), "r"(a2), "r"(a3), "r"(b0), "r"(b1));
}

// ---------------------------------------------------------------------------
// prep: split fp32 -> packed bf16 hi/lo pairs
// ---------------------------------------------------------------------------
__global__ void split_prep_kernel(const float* __restrict__ src,
                                  uint32_t* __restrict__ dh,
                                  uint32_t* __restrict__ dl, int npairs) {
    int i = blockIdx.x * blockDim.x + threadIdx.x;
    if (i < npairs) {
        float2 v = *(const float2*)&src[2 * i];
        uint32_t h, l;
        split2(v.x, v.y, h, l);
        dh[i] = h; dl[i] = l;
    }
}

// ---------------------------------------------------------------------------
// degree counting
// ---------------------------------------------------------------------------
__global__ void zero_deg_kernel() {
    int i = blockIdx.x * blockDim.x + threadIdx.x;
    if (i < NN) { g_indeg[i] = 0; g_outdeg[i] = 0; }
}

__global__ void count_deg_kernel(const int* __restrict__ edge_index) {
    int e = blockIdx.x * blockDim.x + threadIdx.x;
    if (e < EE) {
        atomicAdd(&g_outdeg[edge_index[e]], 1);
        atomicAdd(&g_indeg[edge_index[EE + e]], 1);
    }
}

// ---------------------------------------------------------------------------
// node embedding
// ---------------------------------------------------------------------------
__global__ void node_embed_kernel(const float* __restrict__ x,
                                  const float* __restrict__ W,
                                  const float* __restrict__ b,
                                  const float* __restrict__ inemb,
                                  const float* __restrict__ outemb) {
    int row = blockIdx.x;
    int col = threadIdx.x;
    __shared__ float xs[NFEAT];
    if (col < NFEAT) xs[col] = x[row * NFEAT + col];
    __syncthreads();
    float acc = 0.f;
#pragma unroll
    for (int k = 0; k < NFEAT; k++) acc += xs[k] * W[col * NFEAT + k];
    int ind = min(g_indeg[row], MAXDEGC);
    int outd = min(g_outdeg[row], MAXDEGC);
    g_h[(size_t)(row + 1) * DD + col] =
        acc + b[col] + inemb[ind * DD + col] + outemb[outd * DD + col];
}

__global__ void cls_kernel(const float* __restrict__ cls) {
    g_h[threadIdx.x] = cls[threadIdx.x];
}

// ---------------------------------------------------------------------------
// spatial bias fill + edge scatter (fp32) + bf16 convert
// ---------------------------------------------------------------------------
__global__ void bias_fill_kernel(const int* __restrict__ dist,
                                 const float* __restrict__ dist_bias) {
    size_t idx = (size_t)blockIdx.x * blockDim.x + threadIdx.x;
    if (idx >= NF2H) return;
    int i = (int)(idx / NFT);
    int j = (int)(idx % NFT);
    int d = 0;
    if (i > 0 && j > 0) {
        d = dist[(size_t)(i - 1) * NN + (j - 1)];
        d = max(0, min(d, 9));
    }
#pragma unroll
    for (int h = 0; h < HH; h++) {
        g_bias[(size_t)h * NF2H + idx] = dist_bias[d * HH + h];
    }
}

__global__ void edge_bias_kernel(const float* __restrict__ edge_attr,
                                 const float* __restrict__ epw,
                                 const float* __restrict__ epb,
                                 const int* __restrict__ edge_index) {
    int e = blockIdx.x * blockDim.x + threadIdx.x;
    if (e >= EE) return;
    const float* ea = edge_attr + (size_t)e * EFD;
    int src = edge_index[e];
    int dst = edge_index[EE + e];
    size_t base = (size_t)(src + 1) * NFT + (dst + 1);
#pragma unroll
    for (int h = 0; h < HH; h++) {
        float p = epb[h];
#pragma unroll
        for (int k = 0; k < EFD; k++) p += ea[k] * epw[h * EFD + k];
        atomicAdd(&g_bias[(size_t)h * NF2H + base], p);
    }
}

__global__ void bias_cvt_kernel() {
    size_t idx = (size_t)blockIdx.x * blockDim.x + threadIdx.x;
    if (idx >= (size_t)HH * NFT * BP) return;
    size_t row = idx / BP;
    int p = (int)(idx % BP);
    const float* br = g_bias + row * NFT;
    float v0 = br[2 * p];
    float v1 = (2 * p + 1 < NFT) ? br[2 * p + 1] : 0.f;
    union { __nv_bfloat162 v; uint32_t u; } a;
    a.v = __halves2bfloat162(__float2bfloat16_rn(v0), __float2bfloat16_rn(v1));
    g_biasb[idx] = a.u;
}

// ---------------------------------------------------------------------------
// layernorm -> packed split output
// ---------------------------------------------------------------------------
__global__ void ln_split_kernel(const float* __restrict__ in,
                                uint32_t* __restrict__ oh, uint32_t* __restrict__ ol,
                                const float* __restrict__ s, const float* __restrict__ b) {
    int row = blockIdx.x;
    int c = threadIdx.x;
    float v = in[(size_t)row * DD + c];
    __shared__ float red[256];
    red[c] = v;
    __syncthreads();
    for (int off = 128; off > 0; off >>= 1) {
        if (c < off) red[c] += red[c + off];
        __syncthreads();
    }
    float mean = red[0] / DD;
    __syncthreads();
    float d = v - mean;
    red[c] = d * d;
    __syncthreads();
    for (int off = 128; off > 0; off >>= 1) {
        if (c < off) red[c] += red[c + off];
        __syncthreads();
    }
    float var = red[0] / DD;
    float outv = d * rsqrtf(var + 1e-5f) * s[c] + b[c];
    __syncthreads();
    red[c] = outv;
    __syncthreads();
    if (c < 128) {
        uint32_t h, l;
        split2(red[2 * c], red[2 * c + 1], h, l);
        oh[(size_t)row * D2 + c] = h;
        ol[(size_t)row * D2 + c] = l;
    }
}

__global__ void ln_f32_kernel(const float* __restrict__ in, float* __restrict__ out,
                              const float* __restrict__ s, const float* __restrict__ b) {
    int row = blockIdx.x;
    int c = threadIdx.x;
    float v = in[(size_t)row * DD + c];
    __shared__ float red[256];
    red[c] = v;
    __syncthreads();
    for (int off = 128; off > 0; off >>= 1) {
        if (c < off) red[c] += red[c + off];
        __syncthreads();
    }
    float mean = red[0] / DD;
    __syncthreads();
    float d = v - mean;
    red[c] = d * d;
    __syncthreads();
    for (int off = 128; off > 0; off >>= 1) {
        if (c < off) red[c] += red[c + off];
        __syncthreads();
    }
    float var = red[0] / DD;
    out[(size_t)row * DD + c] = d * rsqrtf(var + 1e-5f) * s[c] + b[c];
}

// ---------------------------------------------------------------------------
// split GEMM: out[M,N] = A[M,K] @ W[N,K]^T + bias, A/W pre-split packed bf16.
// MODE 0: write split (hi/lo). MODE 1: fp32 + residual. MODE 2: gelu + split.
// ---------------------------------------------------------------------------
template <int MODE>
__global__ void gemm_sp_kernel(const uint32_t* __restrict__ Ahg,
                               const uint32_t* __restrict__ Alg,
                               const uint32_t* __restrict__ Whg,
                               const uint32_t* __restrict__ Wlg,
                               const float* __restrict__ bias,
                               const float* __restrict__ res,
                               float* __restrict__ outf,
                               uint32_t* __restrict__ outh,
                               uint32_t* __restrict__ outl,
                               int M, int Ncol, int K) {
    __shared__ uint32_t Ah[64][20], Al[64][20];
    __shared__ uint32_t Bh[64][20], Bl[64][20];
    int K2 = K >> 1;
    int tid = threadIdx.x;
    int lane = tid & 31, wid = tid >> 5;
    int warpM = wid & 3, warpN = wid >> 2;
    int m0 = blockIdx.y * 64, n0 = blockIdx.x * 64;
    int g = lane >> 2, t = lane & 3;

    float c[4][4] = {};

    int lr = tid >> 2;
    int lq = (tid & 3) * 4;
    bool arow = (m0 + lr) < M;
    const uint4 z4 = make_uint4(0, 0, 0, 0);
    uint4 rah = arow ? *(const uint4*)&Ahg[(size_t)(m0 + lr) * K2 + lq] : z4;
    uint4 ral = arow ? *(const uint4*)&Alg[(size_t)(m0 + lr) * K2 + lq] : z4;
    uint4 rbh = *(const uint4*)&Whg[(size_t)(n0 + lr) * K2 + lq];
    uint4 rbl = *(const uint4*)&Wlg[(size_t)(n0 + lr) * K2 + lq];

    for (int k0 = 0; k0 < K2; k0 += 16) {
        __syncthreads();
        Ah[lr][lq] = rah.x; Ah[lr][lq + 1] = rah.y; Ah[lr][lq + 2] = rah.z; Ah[lr][lq + 3] = rah.w;
        Al[lr][lq] = ral.x; Al[lr][lq + 1] = ral.y; Al[lr][lq + 2] = ral.z; Al[lr][lq + 3] = ral.w;
        Bh[lr][lq] = rbh.x; Bh[lr][lq + 1] = rbh.y; Bh[lr][lq + 2] = rbh.z; Bh[lr][lq + 3] = rbh.w;
        Bl[lr][lq] = rbl.x; Bl[lr][lq + 1] = rbl.y; Bl[lr][lq + 2] = rbl.z; Bl[lr][lq + 3] = rbl.w;
        __syncthreads();
        if (k0 + 16 < K2) {
            rah = arow ? *(const uint4*)&Ahg[(size_t)(m0 + lr) * K2 + k0 + 16 + lq] : z4;
            ral = arow ? *(const uint4*)&Alg[(size_t)(m0 + lr) * K2 + k0 + 16 + lq] : z4;
            rbh = *(const uint4*)&Whg[(size_t)(n0 + lr) * K2 + k0 + 16 + lq];
            rbl = *(const uint4*)&Wlg[(size_t)(n0 + lr) * K2 + k0 + 16 + lq];
        }
#pragma unroll
        for (int kk = 0; kk < 2; kk++) {
            int ar = warpM * 16 + g;
            uint32_t ah0 = Ah[ar][kk * 8 + t],     ah1 = Ah[ar + 8][kk * 8 + t];
            uint32_t ah2 = Ah[ar][kk * 8 + t + 4], ah3 = Ah[ar + 8][kk * 8 + t + 4];
            uint32_t al0 = Al[ar][kk * 8 + t],     al1 = Al[ar + 8][kk * 8 + t];
            uint32_t al2 = Al[ar][kk * 8 + t + 4], al3 = Al[ar + 8][kk * 8 + t + 4];
#pragma unroll
            for (int ni = 0; ni < 4; ni++) {
                int br = warpN * 32 + ni * 8 + g;
                uint32_t b0h = Bh[br][kk * 8 + t], b1h = Bh[br][kk * 8 + t + 4];
                uint32_t b0l = Bl[br][kk * 8 + t], b1l = Bl[br][kk * 8 + t + 4];
                mma_bf16(c[ni], ah0, ah1, ah2, ah3, b0h, b1h);
                mma_bf16(c[ni], ah0, ah1, ah2, ah3, b0l, b1l);
                mma_bf16(c[ni], al0, al1, al2, al3, b0h, b1h);
            }
        }
    }

    int N2 = Ncol >> 1;
#pragma unroll
    for (int ni = 0; ni < 4; ni++) {
        int col = n0 + warpN * 32 + ni * 8 + t * 2;
        float b0 = bias[col], b1 = bias[col + 1];
#pragma unroll
        for (int half = 0; half < 2; half++) {
            int r = m0 + warpM * 16 + g + half * 8;
            if (r >= M) continue;
            float v0 = c[ni][half * 2 + 0] + b0;
            float v1 = c[ni][half * 2 + 1] + b1;
            if (MODE == 2) {
                v0 = 0.5f * v0 * (1.0f + erff(v0 * 0.7071067811865475f));
                v1 = 0.5f * v1 * (1.0f + erff(v1 * 0.7071067811865475f));
            }
            if (MODE == 1) {
                outf[(size_t)r * Ncol + col] = v0 + res[(size_t)r * Ncol + col];
                outf[(size_t)r * Ncol + col + 1] = v1 + res[(size_t)r * Ncol + col + 1];
            } else {
                uint32_t hw, lw;
                split2(v0, v1, hw, lw);
                outh[(size_t)r * N2 + (col >> 1)] = hw;
                outl[(size_t)r * N2 + (col >> 1)] = lw;
            }
        }
    }
}

// ---------------------------------------------------------------------------
// fused flash attention, split-bf16, pre-split Q/K/V, bf16 bias.
// Block: 128 q-rows x 1 head, 8 warps; warp: 16 rows x 64 keys/tile.
// ---------------------------------------------------------------------------
__global__ void attn_kernel(const uint32_t* __restrict__ Qh, const uint32_t* __restrict__ Ql,
                            const uint32_t* __restrict__ Khg, const uint32_t* __restrict__ Klg,
                            const uint32_t* __restrict__ Vhg, const uint32_t* __restrict__ Vlg,
                            const uint32_t* __restrict__ biasb,
                            uint32_t* __restrict__ Oh, uint32_t* __restrict__ Ol) {
    __shared__ uint32_t Ksh[64][20], Ksl[64][20];  // [key][hd-pair]
    __shared__ uint32_t Vsh[32][36], Vsl[32][36];  // [hd][key-pair]

    int tid = threadIdx.x;
    int lane = tid & 31, w = tid >> 5;
    int g = lane >> 2, t = lane & 3;
    int z = blockIdx.y;
    int i0 = blockIdx.x * 128;
    int r0 = i0 + w * 16 + g;
    int r1 = r0 + 8;

    // Q fragments
    uint32_t qh[2][4], ql[2][4];
#pragma unroll
    for (int kk = 0; kk < 2; kk++) {
#pragma unroll
        for (int j = 0; j < 4; j++) {
            int rr = r0 + (j & 1) * 8;
            int pi = z * 16 + kk * 8 + (j >> 1) * 4 + t;
            qh[kk][j] = (rr < NFT) ? Qh[(size_t)rr * D2 + pi] : 0u;
            ql[kk][j] = (rr < NFT) ? Ql[(size_t)rr * D2 + pi] : 0u;
        }
    }

    float m[2] = {-1e30f, -1e30f}, l[2] = {0.f, 0.f};
    float co[4][4] = {};

    // staging thread maps
    int lkey = tid >> 2;           // 0..63 (K rows)
    int lq = (tid & 3) * 4;        // uint4 pair index
    int kp = tid >> 3;             // 0..31 (V key pair)
    int hp2 = (tid & 7) * 2;       // V hd-pair base

    const float inv = 0.17677669529663687f;
    int br0 = min(r0, NFT - 1), br1 = min(r1, NFT - 1);
    const uint32_t* bp0 = biasb + ((size_t)z * NFT + br0) * BP;
    const uint32_t* bp1 = biasb + ((size_t)z * NFT + br1) * BP;

    const uint4 z4 = make_uint4(0, 0, 0, 0);
    const uint2 z2 = make_uint2(0, 0);
    uint4 rkh, rkl;
    uint2 vah, val_, vbh, vbl;
    {
        bool kv = lkey < NFT;
        rkh = kv ? *(const uint4*)&Khg[(size_t)lkey * D2 + z * 16 + lq] : z4;
        rkl = kv ? *(const uint4*)&Klg[(size_t)lkey * D2 + z * 16 + lq] : z4;
        int ra = 2 * kp, rb = 2 * kp + 1;
        vah = (ra < NFT) ? *(const uint2*)&Vhg[(size_t)ra * D2 + z * 16 + hp2] : z2;
        val_ = (ra < NFT) ? *(const uint2*)&Vlg[(size_t)ra * D2 + z * 16 + hp2] : z2;
        vbh = (rb < NFT) ? *(const uint2*)&Vhg[(size_t)rb * D2 + z * 16 + hp2] : z2;
        vbl = (rb < NFT) ? *(const uint2*)&Vlg[(size_t)rb * D2 + z * 16 + hp2] : z2;
    }

    for (int jt = 0; jt < 33; jt++) {
        int j0 = jt * 64;
        __syncthreads();
        {
            Ksh[lkey][lq] = rkh.x; Ksh[lkey][lq + 1] = rkh.y;
            Ksh[lkey][lq + 2] = rkh.z; Ksh[lkey][lq + 3] = rkh.w;
            Ksl[lkey][lq] = rkl.x; Ksl[lkey][lq + 1] = rkl.y;
            Ksl[lkey][lq + 2] = rkl.z; Ksl[lkey][lq + 3] = rkl.w;
            Vsh[2 * hp2 + 0][kp] = __byte_perm(vah.x, vbh.x, 0x5410);
            Vsh[2 * hp2 + 1][kp] = __byte_perm(vah.x, vbh.x, 0x7632);
            Vsh[2 * hp2 + 2][kp] = __byte_perm(vah.y, vbh.y, 0x5410);
            Vsh[2 * hp2 + 3][kp] = __byte_perm(vah.y, vbh.y, 0x7632);
            Vsl[2 * hp2 + 0][kp] = __byte_perm(val_.x, vbl.x, 0x5410);
            Vsl[2 * hp2 + 1][kp] = __byte_perm(val_.x, vbl.x, 0x7632);
            Vsl[2 * hp2 + 2][kp] = __byte_perm(val_.y, vbl.y, 0x5410);
            Vsl[2 * hp2 + 3][kp] = __byte_perm(val_.y, vbl.y, 0x7632);
        }
        __syncthreads();
        if (jt + 1 < 33) {
            int n0 = (jt + 1) * 64;
            bool kv = n0 + lkey < NFT;
            rkh = kv ? *(const uint4*)&Khg[(size_t)(n0 + lkey) * D2 + z * 16 + lq] : z4;
            rkl = kv ? *(const uint4*)&Klg[(size_t)(n0 + lkey) * D2 + z * 16 + lq] : z4;
            int ra = n0 + 2 * kp, rb = ra + 1;
            vah = (ra < NFT) ? *(const uint2*)&Vhg[(size_t)ra * D2 + z * 16 + hp2] : z2;
            val_ = (ra < NFT) ? *(const uint2*)&Vlg[(size_t)ra * D2 + z * 16 + hp2] : z2;
            vbh = (rb < NFT) ? *(const uint2*)&Vhg[(size_t)rb * D2 + z * 16 + hp2] : z2;
            vbl = (rb < NFT) ? *(const uint2*)&Vlg[(size_t)rb * D2 + z * 16 + hp2] : z2;
        }

        // S = Q @ K^T
        float cs[8][4] = {};
#pragma unroll
        for (int kk = 0; kk < 2; kk++) {
#pragma unroll
            for (int ni = 0; ni < 8; ni++) {
                int br = ni * 8 + g;
                uint32_t b0h = Ksh[br][kk * 8 + t], b1h = Ksh[br][kk * 8 + t + 4];
                uint32_t b0l = Ksl[br][kk * 8 + t], b1l = Ksl[br][kk * 8 + t + 4];
                mma_bf16(cs[ni], qh[kk][0], qh[kk][1], qh[kk][2], qh[kk][3], b0h, b1h);
                mma_bf16(cs[ni], qh[kk][0], qh[kk][1], qh[kk][2], qh[kk][3], b0l, b1l);
                mma_bf16(cs[ni], ql[kk][0], ql[kk][1], ql[kk][2], ql[kk][3], b0h, b1h);
            }
        }

        // scale + bias + col guards
#pragma unroll
        for (int ni = 0; ni < 8; ni++) {
            int col = j0 + ni * 8 + t * 2;
            int pidx = (col >> 1);
            union { uint32_t u; __nv_bfloat162 v; } w0, w1;
            w0.u = bp0[pidx]; w1.u = bp1[pidx];
            float2 f0 = __bfloat1622float2(w0.v);
            float2 f1 = __bfloat1622float2(w1.v);
            bool v0 = col < NFT, v1 = col + 1 < NFT;
            cs[ni][0] = v0 ? cs[ni][0] * inv + f0.x : -1e30f;
            cs[ni][1] = v1 ? cs[ni][1] * inv + f0.y : -1e30f;
            cs[ni][2] = v0 ? cs[ni][2] * inv + f1.x : -1e30f;
            cs[ni][3] = v1 ? cs[ni][3] * inv + f1.y : -1e30f;
        }

        // online softmax
#pragma unroll
        for (int hh = 0; hh < 2; hh++) {
            int c0 = hh * 2;
            float mx = -1e30f;
#pragma unroll
            for (int ni = 0; ni < 8; ni++)
                mx = fmaxf(mx, fmaxf(cs[ni][c0], cs[ni][c0 + 1]));
            mx = fmaxf(mx, __shfl_xor_sync(0xffffffffu, mx, 1));
            mx = fmaxf(mx, __shfl_xor_sync(0xffffffffu, mx, 2));
            float mn = fmaxf(m[hh], mx);
            float corr = __expf(m[hh] - mn);
            m[hh] = mn;
            l[hh] *= corr;
#pragma unroll
            for (int ni = 0; ni < 4; ni++) {
                co[ni][c0] *= corr;
                co[ni][c0 + 1] *= corr;
            }
            float sum = 0.f;
#pragma unroll
            for (int ni = 0; ni < 8; ni++) {
                float p0 = __expf(cs[ni][c0] - mn);
                float p1 = __expf(cs[ni][c0 + 1] - mn);
                cs[ni][c0] = p0; cs[ni][c0 + 1] = p1;
                sum += p0 + p1;
            }
            sum += __shfl_xor_sync(0xffffffffu, sum, 1);
            sum += __shfl_xor_sync(0xffffffffu, sum, 2);
            l[hh] += sum;
        }

        // O += P @ V
#pragma unroll
        for (int kk = 0; kk < 4; kk++) {
            uint32_t ah[4], al[4];
            split2(cs[2 * kk][0], cs[2 * kk][1], ah[0], al[0]);
            split2(cs[2 * kk][2], cs[2 * kk][3], ah[1], al[1]);
            split2(cs[2 * kk + 1][0], cs[2 * kk + 1][1], ah[2], al[2]);
            split2(cs[2 * kk + 1][2], cs[2 * kk + 1][3], ah[3], al[3]);
#pragma unroll
            for (int ni = 0; ni < 4; ni++) {
                int vr = ni * 8 + g;
                uint32_t b0h = Vsh[vr][kk * 8 + t], b1h = Vsh[vr][kk * 8 + t + 4];
                uint32_t b0l = Vsl[vr][kk * 8 + t], b1l = Vsl[vr][kk * 8 + t + 4];
                mma_bf16(co[ni], ah[0], ah[1], ah[2], ah[3], b0h, b1h);
                mma_bf16(co[ni], ah[0], ah[1], ah[2], ah[3], b0l, b1l);
                mma_bf16(co[ni], al[0], al[1], al[2], al[3], b0h, b1h);
            }
        }
    }

    float inv0 = 1.f / l[0], inv1 = 1.f / l[1];
#pragma unroll
    for (int ni = 0; ni < 4; ni++) {
        int pi = z * 16 + ni * 4 + t;
        if (r0 < NFT) {
            uint32_t hw, lw;
            split2(co[ni][0] * inv0, co[ni][1] * inv0, hw, lw);
            Oh[(size_t)r0 * D2 + pi] = hw;
            Ol[(size_t)r0 * D2 + pi] = lw;
        }
        if (r1 < NFT) {
            uint32_t hw, lw;
            split2(co[ni][2] * inv1, co[ni][3] * inv1, hw, lw);
            Oh[(size_t)r1 * D2 + pi] = hw;
            Ol[(size_t)r1 * D2 + pi] = lw;
        }
    }
}

// ---------------------------------------------------------------------------
// launch
// ---------------------------------------------------------------------------
extern "C" void kernel_launch(void* const* d_in, const int* in_sizes, int n_in,
                              void* d_out, int out_size) {
    const float* x            = (const float*)d_in[0];
    const float* edge_attr    = (const float*)d_in[1];
    const float* node_proj_w  = (const float*)d_in[2];
    const float* node_proj_b  = (const float*)d_in[3];
    const float* in_deg_emb   = (const float*)d_in[4];
    const float* out_deg_emb  = (const float*)d_in[5];
    const float* dist_bias    = (const float*)d_in[6];
    const float* edge_proj_w  = (const float*)d_in[7];
    const float* edge_proj_b  = (const float*)d_in[8];
    const float* cls_token    = (const float*)d_in[9];
    const float* q_w = (const float*)d_in[10];
    const float* q_b = (const float*)d_in[11];
    const float* k_w = (const float*)d_in[12];
    const float* k_b = (const float*)d_in[13];
    const float* v_w = (const float*)d_in[14];
    const float* v_b = (const float*)d_in[15];
    const float* o_w = (const float*)d_in[16];
    const float* o_b = (const float*)d_in[17];
    const float* ffn1_w = (const float*)d_in[18];
    const float* ffn1_b = (const float*)d_in[19];
    const float* ffn2_w = (const float*)d_in[20];
    const float* ffn2_b = (const float*)d_in[21];
    const float* ln1_s = (const float*)d_in[22];
    const float* ln1_b = (const float*)d_in[23];
    const float* ln2_s = (const float*)d_in[24];
    const float* ln2_b = (const float*)d_in[25];
    const float* fn_s = (const float*)d_in[26];
    const float* fn_b = (const float*)d_in[27];
    const int* edge_index  = (const int*)d_in[28];
    const int* dist_matrix = (const int*)d_in[29];
    float* out = (float*)d_out;

    float *h, *fin;
    uint32_t *hnh, *hnl, *qh, *ql, *kh, *kl, *vh, *vl, *oh, *ol, *fh, *fl;
    uint32_t *wh, *wl, *biasb;
    cudaGetSymbolAddress((void**)&h, g_h);
    cudaGetSymbolAddress((void**)&fin, g_fin);
    cudaGetSymbolAddress((void**)&hnh, g_hnh); cudaGetSymbolAddress((void**)&hnl, g_hnl);
    cudaGetSymbolAddress((void**)&qh, g_qh); cudaGetSymbolAddress((void**)&ql, g_ql);
    cudaGetSymbolAddress((void**)&kh, g_kh); cudaGetSymbolAddress((void**)&kl, g_kl);
    cudaGetSymbolAddress((void**)&vh, g_vh); cudaGetSymbolAddress((void**)&vl, g_vl);
    cudaGetSymbolAddress((void**)&oh, g_oh); cudaGetSymbolAddress((void**)&ol, g_ol);
    cudaGetSymbolAddress((void**)&fh, g_fh); cudaGetSymbolAddress((void**)&fl, g_fl);
    cudaGetSymbolAddress((void**)&wh, g_wh); cudaGetSymbolAddress((void**)&wl, g_wl);
    cudaGetSymbolAddress((void**)&biasb, g_biasb);

    // weight split prep
    const int DQ = LL * DD * DD / 2;       // 196608 pairs per qkvo tensor
    const int DF = LL * FFND * DD / 2;     // 786432 pairs per ffn tensor
    split_prep_kernel<<<(DQ + 255) / 256, 256>>>(q_w, wh + WOFF_Q, wl + WOFF_Q, DQ);
    split_prep_kernel<<<(DQ + 255) / 256, 256>>>(k_w, wh + WOFF_K, wl + WOFF_K, DQ);
    split_prep_kernel<<<(DQ + 255) / 256, 256>>>(v_w, wh + WOFF_V, wl + WOFF_V, DQ);
    split_prep_kernel<<<(DQ + 255) / 256, 256>>>(o_w, wh + WOFF_O, wl + WOFF_O, DQ);
    split_prep_kernel<<<(DF + 255) / 256, 256>>>(ffn1_w, wh + WOFF_F1, wl + WOFF_F1, DF);
    split_prep_kernel<<<(DF + 255) / 256, 256>>>(ffn2_w, wh + WOFF_F2, wl + WOFF_F2, DF);

    zero_deg_kernel<<<(NN + 255) / 256, 256>>>();
    count_deg_kernel<<<(EE + 255) / 256, 256>>>(edge_index);
    node_embed_kernel<<<NN, 256>>>(x, node_proj_w, node_proj_b, in_deg_emb, out_deg_emb);
    cls_kernel<<<1, 256>>>(cls_token);

    size_t nf2 = (size_t)NFT * NFT;
    bias_fill_kernel<<<(unsigned)((nf2 + 255) / 256), 256>>>(dist_matrix, dist_bias);
    edge_bias_kernel<<<(EE + 255) / 256, 256>>>(edge_attr, edge_proj_w, edge_proj_b,
                                                edge_index);
    size_t nbp = (size_t)HH * NFT * BP;
    bias_cvt_kernel<<<(unsigned)((nbp + 255) / 256), 256>>>();

    dim3 gemmD(4, 33);
    dim3 gemmF1(16, 33);
    dim3 attnG(17, 8);

    for (int l = 0; l < LL; l++) {
        ln_split_kernel<<<NFT, 256>>>(h, hnh, hnl, ln1_s + l * DD, ln1_b + l * DD);
        gemm_sp_kernel<0><<<gemmD, 256>>>(hnh, hnl,
                                          wh + WOFF_Q + (size_t)l * 32768,
                                          wl + WOFF_Q + (size_t)l * 32768,
                                          q_b + l * DD, nullptr, nullptr, qh, ql,
                                          NFT, DD, DD);
        gemm_sp_kernel<0><<<gemmD, 256>>>(hnh, hnl,
                                          wh + WOFF_K + (size_t)l * 32768,
                                          wl + WOFF_K + (size_t)l * 32768,
                                          k_b + l * DD, nullptr, nullptr, kh, kl,
                                          NFT, DD, DD);
        gemm_sp_kernel<0><<<gemmD, 256>>>(hnh, hnl,
                                          wh + WOFF_V + (size_t)l * 32768,
                                          wl + WOFF_V + (size_t)l * 32768,
                                          v_b + l * DD, nullptr, nullptr, vh, vl,
                                          NFT, DD, DD);
        attn_kernel<<<attnG, 256>>>(qh, ql, kh, kl, vh, vl, biasb, oh, ol);
        gemm_sp_kernel<1><<<gemmD, 256>>>(oh, ol,
                                          wh + WOFF_O + (size_t)l * 32768,
                                          wl + WOFF_O + (size_t)l * 32768,
                                          o_b + l * DD, h, h, nullptr, nullptr,
                                          NFT, DD, DD);
        ln_split_kernel<<<NFT, 256>>>(h, hnh, hnl, ln2_s + l * DD, ln2_b + l * DD);
        gemm_sp_kernel<2><<<gemmF1, 256>>>(hnh, hnl,
                                           wh + WOFF_F1 + (size_t)l * 131072,
                                           wl + WOFF_F1 + (size_t)l * 131072,
                                           ffn1_b + l * FFND, nullptr, nullptr, fh, fl,
                                           NFT, FFND, DD);
        gemm_sp_kernel<1><<<gemmD, 256>>>(fh, fl,
                                          wh + WOFF_F2 + (size_t)l * 131072,
                                          wl + WOFF_F2 + (size_t)l * 131072,
                                          ffn2_b + l * DD, h, h, nullptr, nullptr,
                                          NFT, DD, FFND);
    }

    ln_f32_kernel<<<NFT, 256>>>(h, fin, fn_s, fn_b);
    size_t total = (size_t)NFT * DD;
    if ((size_t)out_size >= total + DD) {
        cudaMemcpyAsync(out, fin, total * sizeof(float), cudaMemcpyDeviceToDevice);
        cudaMemcpyAsync(out + total, fin, DD * sizeof(float), cudaMemcpyDeviceToDevice);
    } else if ((size_t)out_size >= total) {
        cudaMemcpyAsync(out, fin, total * sizeof(float), cudaMemcpyDeviceToDevice);
    } else {
        cudaMemcpyAsync(out, fin, (size_t)out_size * sizeof(float),
                        cudaMemcpyDeviceToDevice);
    }
}

// round 6
// speedup vs baseline: 2.8467x; 1.0349x over previous
#include <cuda_runtime.h>
#include <cuda_bf16.h>
#include <math.h>
#include <stdint.h>

#define NN 2048
#define NFEAT 64
#define DD 256
#define HH 8
#define HDD 32
#define LL 6
#define FFND 1024
#define EE 32768
#define EFD 16
#define NFT 2049
#define MAXDEGC 64
#define D2 128
#define F2 512
#define BP 1025

__device__ float g_h[NFT * DD];
__device__ float g_fin[NFT * DD];
__device__ uint32_t g_hnh[NFT * D2], g_hnl[NFT * D2];
__device__ uint32_t g_qh[NFT * D2], g_ql[NFT * D2];
__device__ uint32_t g_kh[NFT * D2], g_kl[NFT * D2];
__device__ uint32_t g_vh[NFT * D2], g_vl[NFT * D2];
__device__ uint32_t g_oh[NFT * D2], g_ol[NFT * D2];
__device__ uint32_t g_fh[NFT * F2], g_fl[NFT * F2];
__device__ uint32_t g_biasb[(size_t)HH * NFT * BP];
// packed split weights: fused qkv | o | ffn1 | ffn2
#define WOFF_QKV 0
#define WOFF_O 589824
#define WOFF_F1 786432
#define WOFF_F2 1572864
#define WTOT 2359296
__device__ uint32_t g_wh[WTOT], g_wl[WTOT];
__device__ float g_qkvb[LL * 768];
__device__ int g_indeg[NN];
__device__ int g_outdeg[NN];

// ---------------------------------------------------------------------------
// helpers
// ---------------------------------------------------------------------------
__device__ __forceinline__ void split2(float x0, float x1, uint32_t& hi, uint32_t& lo) {
    __nv_bfloat16 h0 = __float2bfloat16_rn(x0);
    __nv_bfloat16 h1 = __float2bfloat16_rn(x1);
    float r0 = x0 - __bfloat162float(h0);
    float r1 = x1 - __bfloat162float(h1);
    __nv_bfloat16 l0 = __float2bfloat16_rn(r0);
    __nv_bfloat16 l1 = __float2bfloat16_rn(r1);
    union { __nv_bfloat162 v; uint32_t u; } a, b;
    a.v = __halves2bfloat162(h0, h1);
    b.v = __halves2bfloat162(l0, l1);
    hi = a.u; lo = b.u;
}

__device__ __forceinline__ void mma_bf16(float c[4], uint32_t a0, uint32_t a1,
                                         uint32_t a2, uint32_t a3,
                                         uint32_t b0, uint32_t b1) {
    asm volatile(
        "mma.sync.aligned.m16n8k16.row.col.f32.bf16.bf16.f32 "
        "{%0,%1,%2,%3}, {%4,%5,%6,%7}, {%8,%9}, {%0,%1,%2,%3};"
        : "+f"(c[0]), "+f"(c[1]), "+f"(c[2]), "+f"(c[3])
        : "r"(a0), "r"(a1), "r"(a2), "r"(a3), "r"(b0), "r"(b1));
}

// ---------------------------------------------------------------------------
// prep kernels
// ---------------------------------------------------------------------------
__global__ void split_prep_kernel(const float* __restrict__ src,
                                  uint32_t* __restrict__ dh,
                                  uint32_t* __restrict__ dl, int npairs) {
    int i = blockIdx.x * blockDim.x + threadIdx.x;
    if (i < npairs) {
        float2 v = *(const float2*)&src[2 * i];
        uint32_t h, l;
        split2(v.x, v.y, h, l);
        dh[i] = h; dl[i] = l;
    }
}

__global__ void split_qkv_kernel(const float* __restrict__ q_w,
                                 const float* __restrict__ k_w,
                                 const float* __restrict__ v_w,
                                 uint32_t* __restrict__ dh,
                                 uint32_t* __restrict__ dl) {
    int i = blockIdx.x * blockDim.x + threadIdx.x;  // pair idx over LL*768*128
    if (i >= LL * 768 * 128) return;
    int l = i / (768 * 128);
    int rem = i - l * 768 * 128;
    int row = rem >> 7;           // 0..767
    int p = rem & 127;
    const float* src = (row < 256) ? q_w : (row < 512) ? k_w : v_w;
    int rr = row & 255;
    const float* sp = src + (size_t)l * DD * DD + (size_t)rr * DD + 2 * p;
    uint32_t h, lo;
    split2(sp[0], sp[1], h, lo);
    dh[i] = h; dl[i] = lo;
}

__global__ void qkvb_prep_kernel(const float* __restrict__ q_b,
                                 const float* __restrict__ k_b,
                                 const float* __restrict__ v_b) {
    int i = blockIdx.x * blockDim.x + threadIdx.x;
    if (i >= LL * 768) return;
    int l = i / 768, c = i % 768;
    float v = (c < 256) ? q_b[l * 256 + c]
            : (c < 512) ? k_b[l * 256 + (c - 256)]
                        : v_b[l * 256 + (c - 512)];
    g_qkvb[i] = v;
}

// ---------------------------------------------------------------------------
// degree counting
// ---------------------------------------------------------------------------
__global__ void zero_deg_kernel() {
    int i = blockIdx.x * blockDim.x + threadIdx.x;
    if (i < NN) { g_indeg[i] = 0; g_outdeg[i] = 0; }
}

__global__ void count_deg_kernel(const int* __restrict__ edge_index) {
    int e = blockIdx.x * blockDim.x + threadIdx.x;
    if (e < EE) {
        atomicAdd(&g_outdeg[edge_index[e]], 1);
        atomicAdd(&g_indeg[edge_index[EE + e]], 1);
    }
}

// ---------------------------------------------------------------------------
// node embedding
// ---------------------------------------------------------------------------
__global__ void node_embed_kernel(const float* __restrict__ x,
                                  const float* __restrict__ W,
                                  const float* __restrict__ b,
                                  const float* __restrict__ inemb,
                                  const float* __restrict__ outemb) {
    int row = blockIdx.x;
    int col = threadIdx.x;
    __shared__ float xs[NFEAT];
    if (col < NFEAT) xs[col] = x[row * NFEAT + col];
    __syncthreads();
    float acc = 0.f;
#pragma unroll
    for (int k = 0; k < NFEAT; k++) acc += xs[k] * W[col * NFEAT + k];
    int ind = min(g_indeg[row], MAXDEGC);
    int outd = min(g_outdeg[row], MAXDEGC);
    g_h[(size_t)(row + 1) * DD + col] =
        acc + b[col] + inemb[ind * DD + col] + outemb[outd * DD + col];
}

__global__ void cls_kernel(const float* __restrict__ cls) {
    g_h[threadIdx.x] = cls[threadIdx.x];
}

// ---------------------------------------------------------------------------
// bias: direct bf16 fill + 16-bit CAS edge scatter
// ---------------------------------------------------------------------------
__global__ void bias_fillb_kernel(const int* __restrict__ dist,
                                  const float* __restrict__ dist_bias) {
    size_t idx = (size_t)blockIdx.x * blockDim.x + threadIdx.x;
    if (idx >= (size_t)HH * NFT * BP) return;
    int h = (int)(idx / ((size_t)NFT * BP));
    size_t rem = idx - (size_t)h * NFT * BP;
    int i = (int)(rem / BP);
    int p = (int)(rem % BP);
    int j0 = 2 * p, j1 = 2 * p + 1;
    int d0 = 0, d1 = 0;
    if (i > 0) {
        if (j0 > 0) {
            d0 = dist[(size_t)(i - 1) * NN + (j0 - 1)];
            d0 = max(0, min(d0, 9));
        }
        if (j1 > 0 && j1 < NFT) {
            d1 = dist[(size_t)(i - 1) * NN + (j1 - 1)];
            d1 = max(0, min(d1, 9));
        }
    }
    float v0 = dist_bias[d0 * HH + h];
    float v1 = (j1 < NFT) ? dist_bias[d1 * HH + h] : 0.f;
    union { __nv_bfloat162 v; uint32_t u; } a;
    a.v = __halves2bfloat162(__float2bfloat16_rn(v0), __float2bfloat16_rn(v1));
    g_biasb[idx] = a.u;
}

__device__ __forceinline__ void atomic_add_bf16half(uint32_t* addr, int hi, float val) {
    uint32_t old = *addr, assumed;
    do {
        assumed = old;
        unsigned short bits = hi ? (unsigned short)(assumed >> 16)
                                 : (unsigned short)(assumed & 0xffffu);
        __nv_bfloat16_raw r; r.x = bits;
        float cur = __bfloat162float((__nv_bfloat16)r);
        __nv_bfloat16 nb = __float2bfloat16_rn(cur + val);
        __nv_bfloat16_raw nr = static_cast<__nv_bfloat16_raw>(nb);
        uint32_t nw = hi ? ((assumed & 0x0000ffffu) | ((uint32_t)nr.x << 16))
                         : ((assumed & 0xffff0000u) | (uint32_t)nr.x);
        old = atomicCAS(addr, assumed, nw);
    } while (old != assumed);
}

__global__ void edge_bias_kernel(const float* __restrict__ edge_attr,
                                 const float* __restrict__ epw,
                                 const float* __restrict__ epb,
                                 const int* __restrict__ edge_index) {
    int e = blockIdx.x * blockDim.x + threadIdx.x;
    if (e >= EE) return;
    const float* ea = edge_attr + (size_t)e * EFD;
    int src = edge_index[e];
    int dst = edge_index[EE + e];
    int col = dst + 1;
    int p = col >> 1, hi = col & 1;
#pragma unroll
    for (int h = 0; h < HH; h++) {
        float pr = epb[h];
#pragma unroll
        for (int k = 0; k < EFD; k++) pr += ea[k] * epw[h * EFD + k];
        uint32_t* addr = &g_biasb[((size_t)h * NFT + src + 1) * BP + p];
        atomic_add_bf16half(addr, hi, pr);
    }
}

// ---------------------------------------------------------------------------
// warp-per-row layernorm (8 rows per 256-thread block, no block syncs)
// ---------------------------------------------------------------------------
template <int SPLIT>
__global__ void ln_warp_kernel(const float* __restrict__ in,
                               float* __restrict__ outf,
                               uint32_t* __restrict__ oh, uint32_t* __restrict__ ol,
                               const float* __restrict__ s, const float* __restrict__ b) {
    int w = threadIdx.x >> 5, lane = threadIdx.x & 31;
    int row = blockIdx.x * 8 + w;
    if (row >= NFT) return;
    const float* p = in + (size_t)row * DD;
    float4 a = *(const float4*)&p[lane * 4];
    float4 c = *(const float4*)&p[128 + lane * 4];
    float sum = a.x + a.y + a.z + a.w + c.x + c.y + c.z + c.w;
#pragma unroll
    for (int o = 16; o > 0; o >>= 1) sum += __shfl_xor_sync(0xffffffffu, sum, o);
    float mean = sum * (1.0f / DD);
    float d0 = a.x - mean, d1 = a.y - mean, d2 = a.z - mean, d3 = a.w - mean;
    float d4 = c.x - mean, d5 = c.y - mean, d6 = c.z - mean, d7 = c.w - mean;
    float vs = d0 * d0 + d1 * d1 + d2 * d2 + d3 * d3 +
               d4 * d4 + d5 * d5 + d6 * d6 + d7 * d7;
#pragma unroll
    for (int o = 16; o > 0; o >>= 1) vs += __shfl_xor_sync(0xffffffffu, vs, o);
    float rstd = rsqrtf(vs * (1.0f / DD) + 1e-5f);
    int c0 = lane * 4, c1 = 128 + lane * 4;
    float o0 = d0 * rstd * s[c0 + 0] + b[c0 + 0];
    float o1 = d1 * rstd * s[c0 + 1] + b[c0 + 1];
    float o2 = d2 * rstd * s[c0 + 2] + b[c0 + 2];
    float o3 = d3 * rstd * s[c0 + 3] + b[c0 + 3];
    float o4 = d4 * rstd * s[c1 + 0] + b[c1 + 0];
    float o5 = d5 * rstd * s[c1 + 1] + b[c1 + 1];
    float o6 = d6 * rstd * s[c1 + 2] + b[c1 + 2];
    float o7 = d7 * rstd * s[c1 + 3] + b[c1 + 3];
    if (SPLIT) {
        uint32_t h, l;
        size_t base = (size_t)row * D2;
        split2(o0, o1, h, l); oh[base + 2 * lane] = h;      ol[base + 2 * lane] = l;
        split2(o2, o3, h, l); oh[base + 2 * lane + 1] = h;  ol[base + 2 * lane + 1] = l;
        split2(o4, o5, h, l); oh[base + 64 + 2 * lane] = h; ol[base + 64 + 2 * lane] = l;
        split2(o6, o7, h, l); oh[base + 65 + 2 * lane] = h; ol[base + 65 + 2 * lane] = l;
    } else {
        float* q = outf + (size_t)row * DD;
        *(float4*)&q[c0] = make_float4(o0, o1, o2, o3);
        *(float4*)&q[c1] = make_float4(o4, o5, o6, o7);
    }
}

// ---------------------------------------------------------------------------
// split GEMM. MODE 0: split out. MODE 1: fp32 + residual. MODE 2: gelu+split.
// MODE 3: fused-QKV epilogue (col>>8 selects q/k/v output buffer).
// ---------------------------------------------------------------------------
template <int MODE>
__global__ void gemm_sp_kernel(const uint32_t* __restrict__ Ahg,
                               const uint32_t* __restrict__ Alg,
                               const uint32_t* __restrict__ Whg,
                               const uint32_t* __restrict__ Wlg,
                               const float* __restrict__ bias,
                               const float* __restrict__ res,
                               float* __restrict__ outf,
                               uint32_t* __restrict__ outh,
                               uint32_t* __restrict__ outl,
                               uint32_t* __restrict__ kh_, uint32_t* __restrict__ kl_,
                               uint32_t* __restrict__ vh_, uint32_t* __restrict__ vl_,
                               int M, int Ncol, int K) {
    __shared__ uint32_t Ah[64][20], Al[64][20];
    __shared__ uint32_t Bh[64][20], Bl[64][20];
    int K2 = K >> 1;
    int tid = threadIdx.x;
    int lane = tid & 31, wid = tid >> 5;
    int warpM = wid & 3, warpN = wid >> 2;
    int m0 = blockIdx.y * 64, n0 = blockIdx.x * 64;
    int g = lane >> 2, t = lane & 3;

    float c[4][4] = {};

    int lr = tid >> 2;
    int lq = (tid & 3) * 4;
    bool arow = (m0 + lr) < M;
    const uint4 z4 = make_uint4(0, 0, 0, 0);
    uint4 rah = arow ? *(const uint4*)&Ahg[(size_t)(m0 + lr) * K2 + lq] : z4;
    uint4 ral = arow ? *(const uint4*)&Alg[(size_t)(m0 + lr) * K2 + lq] : z4;
    uint4 rbh = *(const uint4*)&Whg[(size_t)(n0 + lr) * K2 + lq];
    uint4 rbl = *(const uint4*)&Wlg[(size_t)(n0 + lr) * K2 + lq];

    for (int k0 = 0; k0 < K2; k0 += 16) {
        __syncthreads();
        Ah[lr][lq] = rah.x; Ah[lr][lq + 1] = rah.y; Ah[lr][lq + 2] = rah.z; Ah[lr][lq + 3] = rah.w;
        Al[lr][lq] = ral.x; Al[lr][lq + 1] = ral.y; Al[lr][lq + 2] = ral.z; Al[lr][lq + 3] = ral.w;
        Bh[lr][lq] = rbh.x; Bh[lr][lq + 1] = rbh.y; Bh[lr][lq + 2] = rbh.z; Bh[lr][lq + 3] = rbh.w;
        Bl[lr][lq] = rbl.x; Bl[lr][lq + 1] = rbl.y; Bl[lr][lq + 2] = rbl.z; Bl[lr][lq + 3] = rbl.w;
        __syncthreads();
        if (k0 + 16 < K2) {
            rah = arow ? *(const uint4*)&Ahg[(size_t)(m0 + lr) * K2 + k0 + 16 + lq] : z4;
            ral = arow ? *(const uint4*)&Alg[(size_t)(m0 + lr) * K2 + k0 + 16 + lq] : z4;
            rbh = *(const uint4*)&Whg[(size_t)(n0 + lr) * K2 + k0 + 16 + lq];
            rbl = *(const uint4*)&Wlg[(size_t)(n0 + lr) * K2 + k0 + 16 + lq];
        }
#pragma unroll
        for (int kk = 0; kk < 2; kk++) {
            int ar = warpM * 16 + g;
            uint32_t ah0 = Ah[ar][kk * 8 + t],     ah1 = Ah[ar + 8][kk * 8 + t];
            uint32_t ah2 = Ah[ar][kk * 8 + t + 4], ah3 = Ah[ar + 8][kk * 8 + t + 4];
            uint32_t al0 = Al[ar][kk * 8 + t],     al1 = Al[ar + 8][kk * 8 + t];
            uint32_t al2 = Al[ar][kk * 8 + t + 4], al3 = Al[ar + 8][kk * 8 + t + 4];
#pragma unroll
            for (int ni = 0; ni < 4; ni++) {
                int br = warpN * 32 + ni * 8 + g;
                uint32_t b0h = Bh[br][kk * 8 + t], b1h = Bh[br][kk * 8 + t + 4];
                uint32_t b0l = Bl[br][kk * 8 + t], b1l = Bl[br][kk * 8 + t + 4];
                mma_bf16(c[ni], ah0, ah1, ah2, ah3, b0h, b1h);
                mma_bf16(c[ni], ah0, ah1, ah2, ah3, b0l, b1l);
                mma_bf16(c[ni], al0, al1, al2, al3, b0h, b1h);
            }
        }
    }

    int N2 = Ncol >> 1;
#pragma unroll
    for (int ni = 0; ni < 4; ni++) {
        int col = n0 + warpN * 32 + ni * 8 + t * 2;
        float b0 = bias[col], b1 = bias[col + 1];
#pragma unroll
        for (int half = 0; half < 2; half++) {
            int r = m0 + warpM * 16 + g + half * 8;
            if (r >= M) continue;
            float v0 = c[ni][half * 2 + 0] + b0;
            float v1 = c[ni][half * 2 + 1] + b1;
            if (MODE == 2) {
                v0 = 0.5f * v0 * (1.0f + erff(v0 * 0.7071067811865475f));
                v1 = 0.5f * v1 * (1.0f + erff(v1 * 0.7071067811865475f));
            }
            if (MODE == 1) {
                outf[(size_t)r * Ncol + col] = v0 + res[(size_t)r * Ncol + col];
                outf[(size_t)r * Ncol + col + 1] = v1 + res[(size_t)r * Ncol + col + 1];
            } else if (MODE == 3) {
                int buf = col >> 8, cc = col & 255;
                uint32_t* ph = (buf == 0) ? outh : (buf == 1) ? kh_ : vh_;
                uint32_t* pl = (buf == 0) ? outl : (buf == 1) ? kl_ : vl_;
                uint32_t hw, lw;
                split2(v0, v1, hw, lw);
                ph[(size_t)r * D2 + (cc >> 1)] = hw;
                pl[(size_t)r * D2 + (cc >> 1)] = lw;
            } else {
                uint32_t hw, lw;
                split2(v0, v1, hw, lw);
                outh[(size_t)r * N2 + (col >> 1)] = hw;
                outl[(size_t)r * N2 + (col >> 1)] = lw;
            }
        }
    }
}

// ---------------------------------------------------------------------------
// fused flash attention: 64 q-rows x 1 head per block, 128 threads (4 warps).
// Higher blocks/SM -> MMA of one block overlaps softmax of another.
// ---------------------------------------------------------------------------
__global__ void __launch_bounds__(128)
attn_kernel(const uint32_t* __restrict__ Qh, const uint32_t* __restrict__ Ql,
            const uint32_t* __restrict__ Khg, const uint32_t* __restrict__ Klg,
            const uint32_t* __restrict__ Vhg, const uint32_t* __restrict__ Vlg,
            const uint32_t* __restrict__ biasb,
            uint32_t* __restrict__ Oh, uint32_t* __restrict__ Ol) {
    __shared__ uint32_t Ksh[64][20], Ksl[64][20];  // [key][hd-pair]
    __shared__ uint32_t Vsh[32][36], Vsl[32][36];  // [hd][key-pair]

    int tid = threadIdx.x;
    int lane = tid & 31, w = tid >> 5;
    int g = lane >> 2, t = lane & 3;
    int z = blockIdx.y;
    int i0 = blockIdx.x * 64;
    int r0 = i0 + w * 16 + g;
    int r1 = r0 + 8;

    uint32_t qh[2][4], ql[2][4];
#pragma unroll
    for (int kk = 0; kk < 2; kk++) {
#pragma unroll
        for (int j = 0; j < 4; j++) {
            int rr = r0 + (j & 1) * 8;
            int pi = z * 16 + kk * 8 + (j >> 1) * 4 + t;
            qh[kk][j] = (rr < NFT) ? Qh[(size_t)rr * D2 + pi] : 0u;
            ql[kk][j] = (rr < NFT) ? Ql[(size_t)rr * D2 + pi] : 0u;
        }
    }

    float m[2] = {-1e30f, -1e30f}, l[2] = {0.f, 0.f};
    float co[4][4] = {};

    // staging maps (128 threads)
    int lkey = tid >> 1;          // 0..63 K row
    int lhalf = (tid & 1) * 8;    // hd-pair base (0 or 8)
    int kp = tid >> 2;            // 0..31 V key-pair
    int hp = (tid & 3) * 4;       // V hd-pair base

    const float inv = 0.17677669529663687f;
    int br0 = min(r0, NFT - 1), br1 = min(r1, NFT - 1);
    const uint32_t* bp0 = biasb + ((size_t)z * NFT + br0) * BP;
    const uint32_t* bp1 = biasb + ((size_t)z * NFT + br1) * BP;

    const uint4 z4 = make_uint4(0, 0, 0, 0);
    uint4 rkh0, rkh1, rkl0, rkl1, vah, val_, vbh, vbl;
    {
        bool kv = lkey < NFT;
        const uint32_t* kb = &Khg[(size_t)lkey * D2 + z * 16 + lhalf];
        const uint32_t* lb = &Klg[(size_t)lkey * D2 + z * 16 + lhalf];
        rkh0 = kv ? *(const uint4*)kb : z4;
        rkh1 = kv ? *(const uint4*)(kb + 4) : z4;
        rkl0 = kv ? *(const uint4*)lb : z4;
        rkl1 = kv ? *(const uint4*)(lb + 4) : z4;
        int ra = 2 * kp, rb = 2 * kp + 1;
        vah = (ra < NFT) ? *(const uint4*)&Vhg[(size_t)ra * D2 + z * 16 + hp] : z4;
        val_ = (ra < NFT) ? *(const uint4*)&Vlg[(size_t)ra * D2 + z * 16 + hp] : z4;
        vbh = (rb < NFT) ? *(const uint4*)&Vhg[(size_t)rb * D2 + z * 16 + hp] : z4;
        vbl = (rb < NFT) ? *(const uint4*)&Vlg[(size_t)rb * D2 + z * 16 + hp] : z4;
    }

    for (int jt = 0; jt < 33; jt++) {
        int j0 = jt * 64;
        __syncthreads();
        {
            Ksh[lkey][lhalf + 0] = rkh0.x; Ksh[lkey][lhalf + 1] = rkh0.y;
            Ksh[lkey][lhalf + 2] = rkh0.z; Ksh[lkey][lhalf + 3] = rkh0.w;
            Ksh[lkey][lhalf + 4] = rkh1.x; Ksh[lkey][lhalf + 5] = rkh1.y;
            Ksh[lkey][lhalf + 6] = rkh1.z; Ksh[lkey][lhalf + 7] = rkh1.w;
            Ksl[lkey][lhalf + 0] = rkl0.x; Ksl[lkey][lhalf + 1] = rkl0.y;
            Ksl[lkey][lhalf + 2] = rkl0.z; Ksl[lkey][lhalf + 3] = rkl0.w;
            Ksl[lkey][lhalf + 4] = rkl1.x; Ksl[lkey][lhalf + 5] = rkl1.y;
            Ksl[lkey][lhalf + 6] = rkl1.z; Ksl[lkey][lhalf + 7] = rkl1.w;
            Vsh[2 * hp + 0][kp] = __byte_perm(vah.x, vbh.x, 0x5410);
            Vsh[2 * hp + 1][kp] = __byte_perm(vah.x, vbh.x, 0x7632);
            Vsh[2 * hp + 2][kp] = __byte_perm(vah.y, vbh.y, 0x5410);
            Vsh[2 * hp + 3][kp] = __byte_perm(vah.y, vbh.y, 0x7632);
            Vsh[2 * hp + 4][kp] = __byte_perm(vah.z, vbh.z, 0x5410);
            Vsh[2 * hp + 5][kp] = __byte_perm(vah.z, vbh.z, 0x7632);
            Vsh[2 * hp + 6][kp] = __byte_perm(vah.w, vbh.w, 0x5410);
            Vsh[2 * hp + 7][kp] = __byte_perm(vah.w, vbh.w, 0x7632);
            Vsl[2 * hp + 0][kp] = __byte_perm(val_.x, vbl.x, 0x5410);
            Vsl[2 * hp + 1][kp] = __byte_perm(val_.x, vbl.x, 0x7632);
            Vsl[2 * hp + 2][kp] = __byte_perm(val_.y, vbl.y, 0x5410);
            Vsl[2 * hp + 3][kp] = __byte_perm(val_.y, vbl.y, 0x7632);
            Vsl[2 * hp + 4][kp] = __byte_perm(val_.z, vbl.z, 0x5410);
            Vsl[2 * hp + 5][kp] = __byte_perm(val_.z, vbl.z, 0x7632);
            Vsl[2 * hp + 6][kp] = __byte_perm(val_.w, vbl.w, 0x5410);
            Vsl[2 * hp + 7][kp] = __byte_perm(val_.w, vbl.w, 0x7632);
        }
        __syncthreads();
        if (jt + 1 < 33) {
            int n0 = (jt + 1) * 64;
            bool kv = n0 + lkey < NFT;
            const uint32_t* kb = &Khg[(size_t)(n0 + lkey) * D2 + z * 16 + lhalf];
            const uint32_t* lb = &Klg[(size_t)(n0 + lkey) * D2 + z * 16 + lhalf];
            rkh0 = kv ? *(const uint4*)kb : z4;
            rkh1 = kv ? *(const uint4*)(kb + 4) : z4;
            rkl0 = kv ? *(const uint4*)lb : z4;
            rkl1 = kv ? *(const uint4*)(lb + 4) : z4;
            int ra = n0 + 2 * kp, rb = ra + 1;
            vah = (ra < NFT) ? *(const uint4*)&Vhg[(size_t)ra * D2 + z * 16 + hp] : z4;
            val_ = (ra < NFT) ? *(const uint4*)&Vlg[(size_t)ra * D2 + z * 16 + hp] : z4;
            vbh = (rb < NFT) ? *(const uint4*)&Vhg[(size_t)rb * D2 + z * 16 + hp] : z4;
            vbl = (rb < NFT) ? *(const uint4*)&Vlg[(size_t)rb * D2 + z * 16 + hp] : z4;
        }

        // S = Q @ K^T
        float cs[8][4] = {};
#pragma unroll
        for (int kk = 0; kk < 2; kk++) {
#pragma unroll
            for (int ni = 0; ni < 8; ni++) {
                int br = ni * 8 + g;
                uint32_t b0h = Ksh[br][kk * 8 + t], b1h = Ksh[br][kk * 8 + t + 4];
                uint32_t b0l = Ksl[br][kk * 8 + t], b1l = Ksl[br][kk * 8 + t + 4];
                mma_bf16(cs[ni], qh[kk][0], qh[kk][1], qh[kk][2], qh[kk][3], b0h, b1h);
                mma_bf16(cs[ni], qh[kk][0], qh[kk][1], qh[kk][2], qh[kk][3], b0l, b1l);
                mma_bf16(cs[ni], ql[kk][0], ql[kk][1], ql[kk][2], ql[kk][3], b0h, b1h);
            }
        }

        // scale + bias + guards
#pragma unroll
        for (int ni = 0; ni < 8; ni++) {
            int col = j0 + ni * 8 + t * 2;
            int pidx = (col >> 1);
            union { uint32_t u; __nv_bfloat162 v; } w0, w1;
            w0.u = bp0[pidx]; w1.u = bp1[pidx];
            float2 f0 = __bfloat1622float2(w0.v);
            float2 f1 = __bfloat1622float2(w1.v);
            bool v0 = col < NFT, v1 = col + 1 < NFT;
            cs[ni][0] = v0 ? cs[ni][0] * inv + f0.x : -1e30f;
            cs[ni][1] = v1 ? cs[ni][1] * inv + f0.y : -1e30f;
            cs[ni][2] = v0 ? cs[ni][2] * inv + f1.x : -1e30f;
            cs[ni][3] = v1 ? cs[ni][3] * inv + f1.y : -1e30f;
        }

        // online softmax
#pragma unroll
        for (int hh = 0; hh < 2; hh++) {
            int c0 = hh * 2;
            float mx = -1e30f;
#pragma unroll
            for (int ni = 0; ni < 8; ni++)
                mx = fmaxf(mx, fmaxf(cs[ni][c0], cs[ni][c0 + 1]));
            mx = fmaxf(mx, __shfl_xor_sync(0xffffffffu, mx, 1));
            mx = fmaxf(mx, __shfl_xor_sync(0xffffffffu, mx, 2));
            float mn = fmaxf(m[hh], mx);
            float corr = __expf(m[hh] - mn);
            m[hh] = mn;
            l[hh] *= corr;
#pragma unroll
            for (int ni = 0; ni < 4; ni++) {
                co[ni][c0] *= corr;
                co[ni][c0 + 1] *= corr;
            }
            float sum = 0.f;
#pragma unroll
            for (int ni = 0; ni < 8; ni++) {
                float p0 = __expf(cs[ni][c0] - mn);
                float p1 = __expf(cs[ni][c0 + 1] - mn);
                cs[ni][c0] = p0; cs[ni][c0 + 1] = p1;
                sum += p0 + p1;
            }
            sum += __shfl_xor_sync(0xffffffffu, sum, 1);
            sum += __shfl_xor_sync(0xffffffffu, sum, 2);
            l[hh] += sum;
        }

        // O += P @ V
#pragma unroll
        for (int kk = 0; kk < 4; kk++) {
            uint32_t ah[4], al[4];
            split2(cs[2 * kk][0], cs[2 * kk][1], ah[0], al[0]);
            split2(cs[2 * kk][2], cs[2 * kk][3], ah[1], al[1]);
            split2(cs[2 * kk + 1][0], cs[2 * kk + 1][1], ah[2], al[2]);
            split2(cs[2 * kk + 1][2], cs[2 * kk + 1][3], ah[3], al[3]);
#pragma unroll
            for (int ni = 0; ni < 4; ni++) {
                int vr = ni * 8 + g;
                uint32_t b0h = Vsh[vr][kk * 8 + t], b1h = Vsh[vr][kk * 8 + t + 4];
                uint32_t b0l = Vsl[vr][kk * 8 + t], b1l = Vsl[vr][kk * 8 + t + 4];
                mma_bf16(co[ni], ah[0], ah[1], ah[2], ah[3], b0h, b1h);
                mma_bf16(co[ni], ah[0], ah[1], ah[2], ah[3], b0l, b1l);
                mma_bf16(co[ni], al[0], al[1], al[2], al[3], b0h, b1h);
            }
        }
    }

    float inv0 = 1.f / l[0], inv1 = 1.f / l[1];
#pragma unroll
    for (int ni = 0; ni < 4; ni++) {
        int pi = z * 16 + ni * 4 + t;
        if (r0 < NFT) {
            uint32_t hw, lw;
            split2(co[ni][0] * inv0, co[ni][1] * inv0, hw, lw);
            Oh[(size_t)r0 * D2 + pi] = hw;
            Ol[(size_t)r0 * D2 + pi] = lw;
        }
        if (r1 < NFT) {
            uint32_t hw, lw;
            split2(co[ni][2] * inv1, co[ni][3] * inv1, hw, lw);
            Oh[(size_t)r1 * D2 + pi] = hw;
            Ol[(size_t)r1 * D2 + pi] = lw;
        }
    }
}

// ---------------------------------------------------------------------------
// launch
// ---------------------------------------------------------------------------
extern "C" void kernel_launch(void* const* d_in, const int* in_sizes, int n_in,
                              void* d_out, int out_size) {
    const float* x            = (const float*)d_in[0];
    const float* edge_attr    = (const float*)d_in[1];
    const float* node_proj_w  = (const float*)d_in[2];
    const float* node_proj_b  = (const float*)d_in[3];
    const float* in_deg_emb   = (const float*)d_in[4];
    const float* out_deg_emb  = (const float*)d_in[5];
    const float* dist_bias    = (const float*)d_in[6];
    const float* edge_proj_w  = (const float*)d_in[7];
    const float* edge_proj_b  = (const float*)d_in[8];
    const float* cls_token    = (const float*)d_in[9];
    const float* q_w = (const float*)d_in[10];
    const float* q_b = (const float*)d_in[11];
    const float* k_w = (const float*)d_in[12];
    const float* k_b = (const float*)d_in[13];
    const float* v_w = (const float*)d_in[14];
    const float* v_b = (const float*)d_in[15];
    const float* o_w = (const float*)d_in[16];
    const float* o_b = (const float*)d_in[17];
    const float* ffn1_w = (const float*)d_in[18];
    const float* ffn1_b = (const float*)d_in[19];
    const float* ffn2_w = (const float*)d_in[20];
    const float* ffn2_b = (const float*)d_in[21];
    const float* ln1_s = (const float*)d_in[22];
    const float* ln1_b = (const float*)d_in[23];
    const float* ln2_s = (const float*)d_in[24];
    const float* ln2_b = (const float*)d_in[25];
    const float* fn_s = (const float*)d_in[26];
    const float* fn_b = (const float*)d_in[27];
    const int* edge_index  = (const int*)d_in[28];
    const int* dist_matrix = (const int*)d_in[29];
    float* out = (float*)d_out;

    float *h, *fin, *qkvb;
    uint32_t *hnh, *hnl, *qh, *ql, *kh, *kl, *vh, *vl, *oh, *ol, *fh, *fl;
    uint32_t *wh, *wl, *biasb;
    cudaGetSymbolAddress((void**)&h, g_h);
    cudaGetSymbolAddress((void**)&fin, g_fin);
    cudaGetSymbolAddress((void**)&hnh, g_hnh); cudaGetSymbolAddress((void**)&hnl, g_hnl);
    cudaGetSymbolAddress((void**)&qh, g_qh); cudaGetSymbolAddress((void**)&ql, g_ql);
    cudaGetSymbolAddress((void**)&kh, g_kh); cudaGetSymbolAddress((void**)&kl, g_kl);
    cudaGetSymbolAddress((void**)&vh, g_vh); cudaGetSymbolAddress((void**)&vl, g_vl);
    cudaGetSymbolAddress((void**)&oh, g_oh); cudaGetSymbolAddress((void**)&ol, g_ol);
    cudaGetSymbolAddress((void**)&fh, g_fh); cudaGetSymbolAddress((void**)&fl, g_fl);
    cudaGetSymbolAddress((void**)&wh, g_wh); cudaGetSymbolAddress((void**)&wl, g_wl);
    cudaGetSymbolAddress((void**)&biasb, g_biasb);
    cudaGetSymbolAddress((void**)&qkvb, g_qkvb);

    // weight prep
    const int PQKV = LL * 768 * 128;
    const int DQ = LL * DD * DD / 2;
    const int DF = LL * FFND * DD / 2;
    split_qkv_kernel<<<(PQKV + 255) / 256, 256>>>(q_w, k_w, v_w, wh + WOFF_QKV, wl + WOFF_QKV);
    qkvb_prep_kernel<<<(LL * 768 + 255) / 256, 256>>>(q_b, k_b, v_b);
    split_prep_kernel<<<(DQ + 255) / 256, 256>>>(o_w, wh + WOFF_O, wl + WOFF_O, DQ);
    split_prep_kernel<<<(DF + 255) / 256, 256>>>(ffn1_w, wh + WOFF_F1, wl + WOFF_F1, DF);
    split_prep_kernel<<<(DF + 255) / 256, 256>>>(ffn2_w, wh + WOFF_F2, wl + WOFF_F2, DF);

    zero_deg_kernel<<<(NN + 255) / 256, 256>>>();
    count_deg_kernel<<<(EE + 255) / 256, 256>>>(edge_index);
    node_embed_kernel<<<NN, 256>>>(x, node_proj_w, node_proj_b, in_deg_emb, out_deg_emb);
    cls_kernel<<<1, 256>>>(cls_token);

    size_t nbp = (size_t)HH * NFT * BP;
    bias_fillb_kernel<<<(unsigned)((nbp + 255) / 256), 256>>>(dist_matrix, dist_bias);
    edge_bias_kernel<<<(EE + 255) / 256, 256>>>(edge_attr, edge_proj_w, edge_proj_b,
                                                edge_index);

    dim3 gemmQKV(12, 33);
    dim3 gemmD(4, 33);
    dim3 gemmF1(16, 33);
    dim3 attnG(33, 8);
    int lnG = (NFT + 7) / 8;

    for (int l = 0; l < LL; l++) {
        ln_warp_kernel<1><<<lnG, 256>>>(h, nullptr, hnh, hnl,
                                        ln1_s + l * DD, ln1_b + l * DD);
        gemm_sp_kernel<3><<<gemmQKV, 256>>>(hnh, hnl,
                                            wh + WOFF_QKV + (size_t)l * 98304,
                                            wl + WOFF_QKV + (size_t)l * 98304,
                                            qkvb + l * 768, nullptr, nullptr,
                                            qh, ql, kh, kl, vh, vl,
                                            NFT, 768, DD);
        attn_kernel<<<attnG, 128>>>(qh, ql, kh, kl, vh, vl, biasb, oh, ol);
        gemm_sp_kernel<1><<<gemmD, 256>>>(oh, ol,
                                          wh + WOFF_O + (size_t)l * 32768,
                                          wl + WOFF_O + (size_t)l * 32768,
                                          o_b + l * DD, h, h, nullptr, nullptr,
                                          nullptr, nullptr, nullptr, nullptr,
                                          NFT, DD, DD);
        ln_warp_kernel<1><<<lnG, 256>>>(h, nullptr, hnh, hnl,
                                        ln2_s + l * DD, ln2_b + l * DD);
        gemm_sp_kernel<2><<<gemmF1, 256>>>(hnh, hnl,
                                           wh + WOFF_F1 + (size_t)l * 131072,
                                           wl + WOFF_F1 + (size_t)l * 131072,
                                           ffn1_b + l * FFND, nullptr, nullptr, fh, fl,
                                           nullptr, nullptr, nullptr, nullptr,
                                           NFT, FFND, DD);
        gemm_sp_kernel<1><<<gemmD, 256>>>(fh, fl,
                                          wh + WOFF_F2 + (size_t)l * 131072,
                                          wl + WOFF_F2 + (size_t)l * 131072,
                                          ffn2_b + l * DD, h, h, nullptr, nullptr,
                                          nullptr, nullptr, nullptr, nullptr,
                                          NFT, DD, FFND);
    }

    ln_warp_kernel<0><<<lnG, 256>>>(h, fin, nullptr, nullptr, fn_s, fn_b);
    size_t total = (size_t)NFT * DD;
    if ((size_t)out_size >= total + DD) {
        cudaMemcpyAsync(out, fin, total * sizeof(float), cudaMemcpyDeviceToDevice);
        cudaMemcpyAsync(out + total, fin, DD * sizeof(float), cudaMemcpyDeviceToDevice);
    } else if ((size_t)out_size >= total) {
        cudaMemcpyAsync(out, fin, total * sizeof(float), cudaMemcpyDeviceToDevice);
    } else {
        cudaMemcpyAsync(out, fin, (size_t)out_size * sizeof(float),
                        cudaMemcpyDeviceToDevice);
    }
}

// round 7
// speedup vs baseline: 3.0072x; 1.0564x over previous
#include <cuda_runtime.h>
#include <cuda_bf16.h>
#include <math.h>
#include <stdint.h>

#define NN 2048
#define NFEAT 64
#define DD 256
#define HH 8
#define HDD 32
#define LL 6
#define FFND 1024
#define EE 32768
#define EFD 16
#define NFT 2049
#define MAXDEGC 64
#define D2 128
#define F2 512
#define BP 1025

__device__ float g_h[NFT * DD];
__device__ float g_fin[NFT * DD];
__device__ uint32_t g_hnh[NFT * D2], g_hnl[NFT * D2];
__device__ uint32_t g_qh[NFT * D2], g_ql[NFT * D2];
__device__ uint32_t g_kh[NFT * D2], g_kl[NFT * D2];
__device__ uint32_t g_vh[NFT * D2], g_vl[NFT * D2];
__device__ uint32_t g_oh[NFT * D2], g_ol[NFT * D2];
__device__ uint32_t g_fh[NFT * F2], g_fl[NFT * F2];
__device__ uint32_t g_biasb[(size_t)HH * NFT * BP];
#define WOFF_QKV 0
#define WOFF_O 589824
#define WOFF_F1 786432
#define WOFF_F2 1572864
#define WTOT 2359296
__device__ uint32_t g_wh[WTOT], g_wl[WTOT];
__device__ float g_qkvb[LL * 768];
__device__ int g_indeg[NN];
__device__ int g_outdeg[NN];

// ---------------------------------------------------------------------------
// helpers
// ---------------------------------------------------------------------------
__device__ __forceinline__ void split2(float x0, float x1, uint32_t& hi, uint32_t& lo) {
    __nv_bfloat16 h0 = __float2bfloat16_rn(x0);
    __nv_bfloat16 h1 = __float2bfloat16_rn(x1);
    float r0 = x0 - __bfloat162float(h0);
    float r1 = x1 - __bfloat162float(h1);
    __nv_bfloat16 l0 = __float2bfloat16_rn(r0);
    __nv_bfloat16 l1 = __float2bfloat16_rn(r1);
    union { __nv_bfloat162 v; uint32_t u; } a, b;
    a.v = __halves2bfloat162(h0, h1);
    b.v = __halves2bfloat162(l0, l1);
    hi = a.u; lo = b.u;
}

__device__ __forceinline__ void mma_bf16(float c[4], uint32_t a0, uint32_t a1,
                                         uint32_t a2, uint32_t a3,
                                         uint32_t b0, uint32_t b1) {
    asm volatile(
        "mma.sync.aligned.m16n8k16.row.col.f32.bf16.bf16.f32 "
        "{%0,%1,%2,%3}, {%4,%5,%6,%7}, {%8,%9}, {%0,%1,%2,%3};"
        : "+f"(c[0]), "+f"(c[1]), "+f"(c[2]), "+f"(c[3])
        : "r"(a0), "r"(a1), "r"(a2), "r"(a3), "r"(b0), "r"(b1));
}

__device__ __forceinline__ uint32_t smem_u32(const void* p) {
    return (uint32_t)__cvta_generic_to_shared(p);
}

__device__ __forceinline__ void ldsm_x4(uint32_t& r0, uint32_t& r1,
                                        uint32_t& r2, uint32_t& r3, uint32_t addr) {
    asm volatile("ldmatrix.sync.aligned.m8n8.x4.shared.b16 {%0,%1,%2,%3}, [%4];"
                 : "=r"(r0), "=r"(r1), "=r"(r2), "=r"(r3) : "r"(addr));
}

// ---------------------------------------------------------------------------
// prep kernels
// ---------------------------------------------------------------------------
__global__ void split_prep_kernel(const float* __restrict__ src,
                                  uint32_t* __restrict__ dh,
                                  uint32_t* __restrict__ dl, int npairs) {
    int i = blockIdx.x * blockDim.x + threadIdx.x;
    if (i < npairs) {
        float2 v = *(const float2*)&src[2 * i];
        uint32_t h, l;
        split2(v.x, v.y, h, l);
        dh[i] = h; dl[i] = l;
    }
}

__global__ void split_qkv_kernel(const float* __restrict__ q_w,
                                 const float* __restrict__ k_w,
                                 const float* __restrict__ v_w,
                                 uint32_t* __restrict__ dh,
                                 uint32_t* __restrict__ dl) {
    int i = blockIdx.x * blockDim.x + threadIdx.x;
    if (i >= LL * 768 * 128) return;
    int l = i / (768 * 128);
    int rem = i - l * 768 * 128;
    int row = rem >> 7;
    int p = rem & 127;
    const float* src = (row < 256) ? q_w : (row < 512) ? k_w : v_w;
    int rr = row & 255;
    const float* sp = src + (size_t)l * DD * DD + (size_t)rr * DD + 2 * p;
    uint32_t h, lo;
    split2(sp[0], sp[1], h, lo);
    dh[i] = h; dl[i] = lo;
}

__global__ void qkvb_prep_kernel(const float* __restrict__ q_b,
                                 const float* __restrict__ k_b,
                                 const float* __restrict__ v_b) {
    int i = blockIdx.x * blockDim.x + threadIdx.x;
    if (i >= LL * 768) return;
    int l = i / 768, c = i % 768;
    float v = (c < 256) ? q_b[l * 256 + c]
            : (c < 512) ? k_b[l * 256 + (c - 256)]
                        : v_b[l * 256 + (c - 512)];
    g_qkvb[i] = v;
}

// ---------------------------------------------------------------------------
// degree counting / node embedding
// ---------------------------------------------------------------------------
__global__ void zero_deg_kernel() {
    int i = blockIdx.x * blockDim.x + threadIdx.x;
    if (i < NN) { g_indeg[i] = 0; g_outdeg[i] = 0; }
}

__global__ void count_deg_kernel(const int* __restrict__ edge_index) {
    int e = blockIdx.x * blockDim.x + threadIdx.x;
    if (e < EE) {
        atomicAdd(&g_outdeg[edge_index[e]], 1);
        atomicAdd(&g_indeg[edge_index[EE + e]], 1);
    }
}

__global__ void node_embed_kernel(const float* __restrict__ x,
                                  const float* __restrict__ W,
                                  const float* __restrict__ b,
                                  const float* __restrict__ inemb,
                                  const float* __restrict__ outemb) {
    int row = blockIdx.x;
    int col = threadIdx.x;
    __shared__ float xs[NFEAT];
    if (col < NFEAT) xs[col] = x[row * NFEAT + col];
    __syncthreads();
    float acc = 0.f;
#pragma unroll
    for (int k = 0; k < NFEAT; k++) acc += xs[k] * W[col * NFEAT + k];
    int ind = min(g_indeg[row], MAXDEGC);
    int outd = min(g_outdeg[row], MAXDEGC);
    g_h[(size_t)(row + 1) * DD + col] =
        acc + b[col] + inemb[ind * DD + col] + outemb[outd * DD + col];
}

__global__ void cls_kernel(const float* __restrict__ cls) {
    g_h[threadIdx.x] = cls[threadIdx.x];
}

// ---------------------------------------------------------------------------
// bias: direct bf16 fill + 16-bit CAS edge scatter
// ---------------------------------------------------------------------------
__global__ void bias_fillb_kernel(const int* __restrict__ dist,
                                  const float* __restrict__ dist_bias) {
    size_t idx = (size_t)blockIdx.x * blockDim.x + threadIdx.x;
    if (idx >= (size_t)HH * NFT * BP) return;
    int h = (int)(idx / ((size_t)NFT * BP));
    size_t rem = idx - (size_t)h * NFT * BP;
    int i = (int)(rem / BP);
    int p = (int)(rem % BP);
    int j0 = 2 * p, j1 = 2 * p + 1;
    int d0 = 0, d1 = 0;
    if (i > 0) {
        if (j0 > 0) {
            d0 = dist[(size_t)(i - 1) * NN + (j0 - 1)];
            d0 = max(0, min(d0, 9));
        }
        if (j1 > 0 && j1 < NFT) {
            d1 = dist[(size_t)(i - 1) * NN + (j1 - 1)];
            d1 = max(0, min(d1, 9));
        }
    }
    float v0 = dist_bias[d0 * HH + h];
    float v1 = (j1 < NFT) ? dist_bias[d1 * HH + h] : 0.f;
    union { __nv_bfloat162 v; uint32_t u; } a;
    a.v = __halves2bfloat162(__float2bfloat16_rn(v0), __float2bfloat16_rn(v1));
    g_biasb[idx] = a.u;
}

__device__ __forceinline__ void atomic_add_bf16half(uint32_t* addr, int hi, float val) {
    uint32_t old = *addr, assumed;
    do {
        assumed = old;
        unsigned short bits = hi ? (unsigned short)(assumed >> 16)
                                 : (unsigned short)(assumed & 0xffffu);
        __nv_bfloat16_raw r; r.x = bits;
        float cur = __bfloat162float((__nv_bfloat16)r);
        __nv_bfloat16 nb = __float2bfloat16_rn(cur + val);
        __nv_bfloat16_raw nr = static_cast<__nv_bfloat16_raw>(nb);
        uint32_t nw = hi ? ((assumed & 0x0000ffffu) | ((uint32_t)nr.x << 16))
                         : ((assumed & 0xffff0000u) | (uint32_t)nr.x);
        old = atomicCAS(addr, assumed, nw);
    } while (old != assumed);
}

__global__ void edge_bias_kernel(const float* __restrict__ edge_attr,
                                 const float* __restrict__ epw,
                                 const float* __restrict__ epb,
                                 const int* __restrict__ edge_index) {
    int e = blockIdx.x * blockDim.x + threadIdx.x;
    if (e >= EE) return;
    const float* ea = edge_attr + (size_t)e * EFD;
    int src = edge_index[e];
    int dst = edge_index[EE + e];
    int col = dst + 1;
    int p = col >> 1, hi = col & 1;
#pragma unroll
    for (int h = 0; h < HH; h++) {
        float pr = epb[h];
#pragma unroll
        for (int k = 0; k < EFD; k++) pr += ea[k] * epw[h * EFD + k];
        uint32_t* addr = &g_biasb[((size_t)h * NFT + src + 1) * BP + p];
        atomic_add_bf16half(addr, hi, pr);
    }
}

// ---------------------------------------------------------------------------
// warp-per-row layernorm
// ---------------------------------------------------------------------------
template <int SPLIT>
__global__ void ln_warp_kernel(const float* __restrict__ in,
                               float* __restrict__ outf,
                               uint32_t* __restrict__ oh, uint32_t* __restrict__ ol,
                               const float* __restrict__ s, const float* __restrict__ b) {
    int w = threadIdx.x >> 5, lane = threadIdx.x & 31;
    int row = blockIdx.x * 8 + w;
    if (row >= NFT) return;
    const float* p = in + (size_t)row * DD;
    float4 a = *(const float4*)&p[lane * 4];
    float4 c = *(const float4*)&p[128 + lane * 4];
    float sum = a.x + a.y + a.z + a.w + c.x + c.y + c.z + c.w;
#pragma unroll
    for (int o = 16; o > 0; o >>= 1) sum += __shfl_xor_sync(0xffffffffu, sum, o);
    float mean = sum * (1.0f / DD);
    float d0 = a.x - mean, d1 = a.y - mean, d2 = a.z - mean, d3 = a.w - mean;
    float d4 = c.x - mean, d5 = c.y - mean, d6 = c.z - mean, d7 = c.w - mean;
    float vs = d0 * d0 + d1 * d1 + d2 * d2 + d3 * d3 +
               d4 * d4 + d5 * d5 + d6 * d6 + d7 * d7;
#pragma unroll
    for (int o = 16; o > 0; o >>= 1) vs += __shfl_xor_sync(0xffffffffu, vs, o);
    float rstd = rsqrtf(vs * (1.0f / DD) + 1e-5f);
    int c0 = lane * 4, c1 = 128 + lane * 4;
    float o0 = d0 * rstd * s[c0 + 0] + b[c0 + 0];
    float o1 = d1 * rstd * s[c0 + 1] + b[c0 + 1];
    float o2 = d2 * rstd * s[c0 + 2] + b[c0 + 2];
    float o3 = d3 * rstd * s[c0 + 3] + b[c0 + 3];
    float o4 = d4 * rstd * s[c1 + 0] + b[c1 + 0];
    float o5 = d5 * rstd * s[c1 + 1] + b[c1 + 1];
    float o6 = d6 * rstd * s[c1 + 2] + b[c1 + 2];
    float o7 = d7 * rstd * s[c1 + 3] + b[c1 + 3];
    if (SPLIT) {
        uint32_t h, l;
        size_t base = (size_t)row * D2;
        split2(o0, o1, h, l); oh[base + 2 * lane] = h;      ol[base + 2 * lane] = l;
        split2(o2, o3, h, l); oh[base + 2 * lane + 1] = h;  ol[base + 2 * lane + 1] = l;
        split2(o4, o5, h, l); oh[base + 64 + 2 * lane] = h; ol[base + 64 + 2 * lane] = l;
        split2(o6, o7, h, l); oh[base + 65 + 2 * lane] = h; ol[base + 65 + 2 * lane] = l;
    } else {
        float* q = outf + (size_t)row * DD;
        *(float4*)&q[c0] = make_float4(o0, o1, o2, o3);
        *(float4*)&q[c1] = make_float4(o4, o5, o6, o7);
    }
}

// ---------------------------------------------------------------------------
// split GEMM with ldmatrix fragment loads.
// MODE 0: split out. 1: fp32+res. 2: gelu+split. 3: fused-QKV epilogue.
// ---------------------------------------------------------------------------
template <int MODE>
__global__ void gemm_sp_kernel(const uint32_t* __restrict__ Ahg,
                               const uint32_t* __restrict__ Alg,
                               const uint32_t* __restrict__ Whg,
                               const uint32_t* __restrict__ Wlg,
                               const float* __restrict__ bias,
                               const float* __restrict__ res,
                               float* __restrict__ outf,
                               uint32_t* __restrict__ outh,
                               uint32_t* __restrict__ outl,
                               uint32_t* __restrict__ kh_, uint32_t* __restrict__ kl_,
                               uint32_t* __restrict__ vh_, uint32_t* __restrict__ vl_,
                               int M, int Ncol, int K) {
    __shared__ __align__(16) uint32_t Ah[64][20], Al[64][20];
    __shared__ __align__(16) uint32_t Bh[64][20], Bl[64][20];
    int K2 = K >> 1;
    int tid = threadIdx.x;
    int lane = tid & 31, wid = tid >> 5;
    int warpM = wid & 3, warpN = wid >> 2;
    int m0 = blockIdx.y * 64, n0 = blockIdx.x * 64;
    int g = lane >> 2, t = lane & 3;

    float c[4][4] = {};

    int lr = tid >> 2;
    int lq = (tid & 3) * 4;
    bool arow = (m0 + lr) < M;
    const uint4 z4 = make_uint4(0, 0, 0, 0);
    uint4 rah = arow ? *(const uint4*)&Ahg[(size_t)(m0 + lr) * K2 + lq] : z4;
    uint4 ral = arow ? *(const uint4*)&Alg[(size_t)(m0 + lr) * K2 + lq] : z4;
    uint4 rbh = *(const uint4*)&Whg[(size_t)(n0 + lr) * K2 + lq];
    uint4 rbl = *(const uint4*)&Wlg[(size_t)(n0 + lr) * K2 + lq];

    // ldmatrix base addresses
    uint32_t a_h = smem_u32(&Ah[warpM * 16 + (lane & 15)][(lane >> 4) * 4]);
    uint32_t a_l = smem_u32(&Al[warpM * 16 + (lane & 15)][(lane >> 4) * 4]);
    int brow = warpN * 32 + (lane >> 4) * 8 + (lane & 7);
    int bseg = ((lane >> 3) & 1) * 4;
    uint32_t b_h0 = smem_u32(&Bh[brow][bseg]);
    uint32_t b_h1 = smem_u32(&Bh[brow + 16][bseg]);
    uint32_t b_l0 = smem_u32(&Bl[brow][bseg]);
    uint32_t b_l1 = smem_u32(&Bl[brow + 16][bseg]);

    for (int k0 = 0; k0 < K2; k0 += 16) {
        __syncthreads();
        Ah[lr][lq] = rah.x; Ah[lr][lq + 1] = rah.y; Ah[lr][lq + 2] = rah.z; Ah[lr][lq + 3] = rah.w;
        Al[lr][lq] = ral.x; Al[lr][lq + 1] = ral.y; Al[lr][lq + 2] = ral.z; Al[lr][lq + 3] = ral.w;
        Bh[lr][lq] = rbh.x; Bh[lr][lq + 1] = rbh.y; Bh[lr][lq + 2] = rbh.z; Bh[lr][lq + 3] = rbh.w;
        Bl[lr][lq] = rbl.x; Bl[lr][lq + 1] = rbl.y; Bl[lr][lq + 2] = rbl.z; Bl[lr][lq + 3] = rbl.w;
        __syncthreads();
        if (k0 + 16 < K2) {
            rah = arow ? *(const uint4*)&Ahg[(size_t)(m0 + lr) * K2 + k0 + 16 + lq] : z4;
            ral = arow ? *(const uint4*)&Alg[(size_t)(m0 + lr) * K2 + k0 + 16 + lq] : z4;
            rbh = *(const uint4*)&Whg[(size_t)(n0 + lr) * K2 + k0 + 16 + lq];
            rbl = *(const uint4*)&Wlg[(size_t)(n0 + lr) * K2 + k0 + 16 + lq];
        }
#pragma unroll
        for (int kk = 0; kk < 2; kk++) {
            uint32_t koff = kk * 32;
            uint32_t ah0, ah1, ah2, ah3, al0, al1, al2, al3;
            ldsm_x4(ah0, ah1, ah2, ah3, a_h + koff);
            ldsm_x4(al0, al1, al2, al3, a_l + koff);
            uint32_t bh[8], bl[8];
            ldsm_x4(bh[0], bh[1], bh[2], bh[3], b_h0 + koff);
            ldsm_x4(bh[4], bh[5], bh[6], bh[7], b_h1 + koff);
            ldsm_x4(bl[0], bl[1], bl[2], bl[3], b_l0 + koff);
            ldsm_x4(bl[4], bl[5], bl[6], bl[7], b_l1 + koff);
#pragma unroll
            for (int ni = 0; ni < 4; ni++) {
                uint32_t b0h = bh[ni * 2], b1h = bh[ni * 2 + 1];
                uint32_t b0l = bl[ni * 2], b1l = bl[ni * 2 + 1];
                mma_bf16(c[ni], ah0, ah1, ah2, ah3, b0h, b1h);
                mma_bf16(c[ni], ah0, ah1, ah2, ah3, b0l, b1l);
                mma_bf16(c[ni], al0, al1, al2, al3, b0h, b1h);
            }
        }
    }

    int N2 = Ncol >> 1;
#pragma unroll
    for (int ni = 0; ni < 4; ni++) {
        int col = n0 + warpN * 32 + ni * 16 + (lane >> 4) * 8 + t * 2;
        // NOTE: fragment ni now maps to n-offset ni*2 groups interleaved by ldsm
        // order: bh[ni*2] covers rows (warpN*32 + (ni<2?0:16) + ... )
        col = n0 + warpN * 32 + ((ni < 2) ? 0 : 16) + (ni & 1) * 8 + t * 2;
        float b0 = bias[col], b1 = bias[col + 1];
#pragma unroll
        for (int half = 0; half < 2; half++) {
            int r = m0 + warpM * 16 + g + half * 8;
            if (r >= M) continue;
            float v0 = c[ni][half * 2 + 0] + b0;
            float v1 = c[ni][half * 2 + 1] + b1;
            if (MODE == 2) {
                v0 = 0.5f * v0 * (1.0f + erff(v0 * 0.7071067811865475f));
                v1 = 0.5f * v1 * (1.0f + erff(v1 * 0.7071067811865475f));
            }
            if (MODE == 1) {
                outf[(size_t)r * Ncol + col] = v0 + res[(size_t)r * Ncol + col];
                outf[(size_t)r * Ncol + col + 1] = v1 + res[(size_t)r * Ncol + col + 1];
            } else if (MODE == 3) {
                int buf = col >> 8, cc = col & 255;
                uint32_t* ph = (buf == 0) ? outh : (buf == 1) ? kh_ : vh_;
                uint32_t* pl = (buf == 0) ? outl : (buf == 1) ? kl_ : vl_;
                uint32_t hw, lw;
                split2(v0, v1, hw, lw);
                ph[(size_t)r * D2 + (cc >> 1)] = hw;
                pl[(size_t)r * D2 + (cc >> 1)] = lw;
            } else {
                uint32_t hw, lw;
                split2(v0, v1, hw, lw);
                outh[(size_t)r * N2 + (col >> 1)] = hw;
                outl[(size_t)r * N2 + (col >> 1)] = lw;
            }
        }
    }
}

// ---------------------------------------------------------------------------
// fused flash attention with ldmatrix K/V fragment loads.
// 64 q-rows x 1 head per block, 128 threads.
// ---------------------------------------------------------------------------
__global__ void __launch_bounds__(128)
attn_kernel(const uint32_t* __restrict__ Qh, const uint32_t* __restrict__ Ql,
            const uint32_t* __restrict__ Khg, const uint32_t* __restrict__ Klg,
            const uint32_t* __restrict__ Vhg, const uint32_t* __restrict__ Vlg,
            const uint32_t* __restrict__ biasb,
            uint32_t* __restrict__ Oh, uint32_t* __restrict__ Ol) {
    __shared__ __align__(16) uint32_t Ksh[64][20], Ksl[64][20];
    __shared__ __align__(16) uint32_t Vsh[32][36], Vsl[32][36];

    int tid = threadIdx.x;
    int lane = tid & 31, w = tid >> 5;
    int g = lane >> 2, t = lane & 3;
    int z = blockIdx.y;
    int i0 = blockIdx.x * 64;
    int r0 = i0 + w * 16 + g;
    int r1 = r0 + 8;

    uint32_t qh[2][4], ql[2][4];
#pragma unroll
    for (int kk = 0; kk < 2; kk++) {
#pragma unroll
        for (int j = 0; j < 4; j++) {
            int rr = r0 + (j & 1) * 8;
            int pi = z * 16 + kk * 8 + (j >> 1) * 4 + t;
            qh[kk][j] = (rr < NFT) ? Qh[(size_t)rr * D2 + pi] : 0u;
            ql[kk][j] = (rr < NFT) ? Ql[(size_t)rr * D2 + pi] : 0u;
        }
    }

    float m[2] = {-1e30f, -1e30f}, l[2] = {0.f, 0.f};
    float co[4][4] = {};

    int lkey = tid >> 1;
    int lhalf = (tid & 1) * 8;
    int kp = tid >> 2;
    int hp = (tid & 3) * 4;

    const float inv = 0.17677669529663687f;
    int br0 = min(r0, NFT - 1), br1 = min(r1, NFT - 1);
    const uint32_t* bp0 = biasb + ((size_t)z * NFT + br0) * BP;
    const uint32_t* bp1 = biasb + ((size_t)z * NFT + br1) * BP;

    // ldmatrix base addresses
    int krow = (lane >> 4) * 8 + (lane & 7);
    int kseg = ((lane >> 3) & 1) * 4;
    uint32_t k_h[4], k_l[4];
#pragma unroll
    for (int gg = 0; gg < 4; gg++) {
        k_h[gg] = smem_u32(&Ksh[gg * 16 + krow][kseg]);
        k_l[gg] = smem_u32(&Ksl[gg * 16 + krow][kseg]);
    }
    uint32_t v_h[2], v_l[2];
#pragma unroll
    for (int gg = 0; gg < 2; gg++) {
        v_h[gg] = smem_u32(&Vsh[gg * 16 + krow][kseg]);
        v_l[gg] = smem_u32(&Vsl[gg * 16 + krow][kseg]);
    }

    const uint4 z4 = make_uint4(0, 0, 0, 0);
    uint4 rkh0, rkh1, rkl0, rkl1, vah, val_, vbh, vbl;
    {
        bool kv = lkey < NFT;
        const uint32_t* kb = &Khg[(size_t)lkey * D2 + z * 16 + lhalf];
        const uint32_t* lb = &Klg[(size_t)lkey * D2 + z * 16 + lhalf];
        rkh0 = kv ? *(const uint4*)kb : z4;
        rkh1 = kv ? *(const uint4*)(kb + 4) : z4;
        rkl0 = kv ? *(const uint4*)lb : z4;
        rkl1 = kv ? *(const uint4*)(lb + 4) : z4;
        int ra = 2 * kp, rb = 2 * kp + 1;
        vah = (ra < NFT) ? *(const uint4*)&Vhg[(size_t)ra * D2 + z * 16 + hp] : z4;
        val_ = (ra < NFT) ? *(const uint4*)&Vlg[(size_t)ra * D2 + z * 16 + hp] : z4;
        vbh = (rb < NFT) ? *(const uint4*)&Vhg[(size_t)rb * D2 + z * 16 + hp] : z4;
        vbl = (rb < NFT) ? *(const uint4*)&Vlg[(size_t)rb * D2 + z * 16 + hp] : z4;
    }

    for (int jt = 0; jt < 33; jt++) {
        int j0 = jt * 64;
        __syncthreads();
        {
            Ksh[lkey][lhalf + 0] = rkh0.x; Ksh[lkey][lhalf + 1] = rkh0.y;
            Ksh[lkey][lhalf + 2] = rkh0.z; Ksh[lkey][lhalf + 3] = rkh0.w;
            Ksh[lkey][lhalf + 4] = rkh1.x; Ksh[lkey][lhalf + 5] = rkh1.y;
            Ksh[lkey][lhalf + 6] = rkh1.z; Ksh[lkey][lhalf + 7] = rkh1.w;
            Ksl[lkey][lhalf + 0] = rkl0.x; Ksl[lkey][lhalf + 1] = rkl0.y;
            Ksl[lkey][lhalf + 2] = rkl0.z; Ksl[lkey][lhalf + 3] = rkl0.w;
            Ksl[lkey][lhalf + 4] = rkl1.x; Ksl[lkey][lhalf + 5] = rkl1.y;
            Ksl[lkey][lhalf + 6] = rkl1.z; Ksl[lkey][lhalf + 7] = rkl1.w;
            Vsh[2 * hp + 0][kp] = __byte_perm(vah.x, vbh.x, 0x5410);
            Vsh[2 * hp + 1][kp] = __byte_perm(vah.x, vbh.x, 0x7632);
            Vsh[2 * hp + 2][kp] = __byte_perm(vah.y, vbh.y, 0x5410);
            Vsh[2 * hp + 3][kp] = __byte_perm(vah.y, vbh.y, 0x7632);
            Vsh[2 * hp + 4][kp] = __byte_perm(vah.z, vbh.z, 0x5410);
            Vsh[2 * hp + 5][kp] = __byte_perm(vah.z, vbh.z, 0x7632);
            Vsh[2 * hp + 6][kp] = __byte_perm(vah.w, vbh.w, 0x5410);
            Vsh[2 * hp + 7][kp] = __byte_perm(vah.w, vbh.w, 0x7632);
            Vsl[2 * hp + 0][kp] = __byte_perm(val_.x, vbl.x, 0x5410);
            Vsl[2 * hp + 1][kp] = __byte_perm(val_.x, vbl.x, 0x7632);
            Vsl[2 * hp + 2][kp] = __byte_perm(val_.y, vbl.y, 0x5410);
            Vsl[2 * hp + 3][kp] = __byte_perm(val_.y, vbl.y, 0x7632);
            Vsl[2 * hp + 4][kp] = __byte_perm(val_.z, vbl.z, 0x5410);
            Vsl[2 * hp + 5][kp] = __byte_perm(val_.z, vbl.z, 0x7632);
            Vsl[2 * hp + 6][kp] = __byte_perm(val_.w, vbl.w, 0x5410);
            Vsl[2 * hp + 7][kp] = __byte_perm(val_.w, vbl.w, 0x7632);
        }
        __syncthreads();
        if (jt + 1 < 33) {
            int n0 = (jt + 1) * 64;
            bool kv = n0 + lkey < NFT;
            const uint32_t* kb = &Khg[(size_t)(n0 + lkey) * D2 + z * 16 + lhalf];
            const uint32_t* lb = &Klg[(size_t)(n0 + lkey) * D2 + z * 16 + lhalf];
            rkh0 = kv ? *(const uint4*)kb : z4;
            rkh1 = kv ? *(const uint4*)(kb + 4) : z4;
            rkl0 = kv ? *(const uint4*)lb : z4;
            rkl1 = kv ? *(const uint4*)(lb + 4) : z4;
            int ra = n0 + 2 * kp, rb = ra + 1;
            vah = (ra < NFT) ? *(const uint4*)&Vhg[(size_t)ra * D2 + z * 16 + hp] : z4;
            val_ = (ra < NFT) ? *(const uint4*)&Vlg[(size_t)ra * D2 + z * 16 + hp] : z4;
            vbh = (rb < NFT) ? *(const uint4*)&Vhg[(size_t)rb * D2 + z * 16 + hp] : z4;
            vbl = (rb < NFT) ? *(const uint4*)&Vlg[(size_t)rb * D2 + z * 16 + hp] : z4;
        }

        // S = Q @ K^T  (fragments via ldmatrix; group gg covers ni=2gg,2gg+1)
        float cs[8][4] = {};
#pragma unroll
        for (int kk = 0; kk < 2; kk++) {
            uint32_t koff = kk * 32;
#pragma unroll
            for (int gg = 0; gg < 4; gg++) {
                uint32_t f0, f1, f2, f3, e0, e1, e2, e3;
                ldsm_x4(f0, f1, f2, f3, k_h[gg] + koff);
                ldsm_x4(e0, e1, e2, e3, k_l[gg] + koff);
                mma_bf16(cs[2 * gg], qh[kk][0], qh[kk][1], qh[kk][2], qh[kk][3], f0, f1);
                mma_bf16(cs[2 * gg], qh[kk][0], qh[kk][1], qh[kk][2], qh[kk][3], e0, e1);
                mma_bf16(cs[2 * gg], ql[kk][0], ql[kk][1], ql[kk][2], ql[kk][3], f0, f1);
                mma_bf16(cs[2 * gg + 1], qh[kk][0], qh[kk][1], qh[kk][2], qh[kk][3], f2, f3);
                mma_bf16(cs[2 * gg + 1], qh[kk][0], qh[kk][1], qh[kk][2], qh[kk][3], e2, e3);
                mma_bf16(cs[2 * gg + 1], ql[kk][0], ql[kk][1], ql[kk][2], ql[kk][3], f2, f3);
            }
        }

        // scale + bias + guards (fragment 2gg -> keys gg*16.., 2gg+1 -> gg*16+8..)
#pragma unroll
        for (int ni = 0; ni < 8; ni++) {
            int gg = ni >> 1;
            int col = j0 + gg * 16 + (ni & 1) * 8 + t * 2;
            int pidx = (col >> 1);
            union { uint32_t u; __nv_bfloat162 v; } w0, w1;
            w0.u = bp0[pidx]; w1.u = bp1[pidx];
            float2 f0 = __bfloat1622float2(w0.v);
            float2 f1 = __bfloat1622float2(w1.v);
            bool v0 = col < NFT, v1 = col + 1 < NFT;
            cs[ni][0] = v0 ? cs[ni][0] * inv + f0.x : -1e30f;
            cs[ni][1] = v1 ? cs[ni][1] * inv + f0.y : -1e30f;
            cs[ni][2] = v0 ? cs[ni][2] * inv + f1.x : -1e30f;
            cs[ni][3] = v1 ? cs[ni][3] * inv + f1.y : -1e30f;
        }

        // online softmax
#pragma unroll
        for (int hh = 0; hh < 2; hh++) {
            int c0 = hh * 2;
            float mx = -1e30f;
#pragma unroll
            for (int ni = 0; ni < 8; ni++)
                mx = fmaxf(mx, fmaxf(cs[ni][c0], cs[ni][c0 + 1]));
            mx = fmaxf(mx, __shfl_xor_sync(0xffffffffu, mx, 1));
            mx = fmaxf(mx, __shfl_xor_sync(0xffffffffu, mx, 2));
            float mn = fmaxf(m[hh], mx);
            float corr = __expf(m[hh] - mn);
            m[hh] = mn;
            l[hh] *= corr;
#pragma unroll
            for (int ni = 0; ni < 4; ni++) {
                co[ni][c0] *= corr;
                co[ni][c0 + 1] *= corr;
            }
            float sum = 0.f;
#pragma unroll
            for (int ni = 0; ni < 8; ni++) {
                float p0 = __expf(cs[ni][c0] - mn);
                float p1 = __expf(cs[ni][c0 + 1] - mn);
                cs[ni][c0] = p0; cs[ni][c0 + 1] = p1;
                sum += p0 + p1;
            }
            sum += __shfl_xor_sync(0xffffffffu, sum, 1);
            sum += __shfl_xor_sync(0xffffffffu, sum, 2);
            l[hh] += sum;
        }

        // O += P @ V ; P fragment kk covers keys kk*16..kk*16+15
        // cs fragment holding keys kk*16+0..7 is ni=2*(kk>>... ) -> gg=kk? No:
        // key block of 16 for P-A-fragment kk maps to cs[2*kk] (k 0-7 -> cols of
        // fragment 2*kk? fragment 2*gg covers keys gg*16+0..7, 2*gg+1 covers +8..15.
#pragma unroll
        for (int kk = 0; kk < 4; kk++) {
            uint32_t ah[4], al[4];
            // A fragment for keys kk*16..+15: a0/a1 from cs[2kk] (k0-7),
            // a2/a3 from cs[2kk+1] (k8-15)
            split2(cs[2 * kk][0], cs[2 * kk][1], ah[0], al[0]);
            split2(cs[2 * kk][2], cs[2 * kk][3], ah[1], al[1]);
            split2(cs[2 * kk + 1][0], cs[2 * kk + 1][1], ah[2], al[2]);
            split2(cs[2 * kk + 1][2], cs[2 * kk + 1][3], ah[3], al[3]);
            uint32_t koff = kk * 32;
#pragma unroll
            for (int gg = 0; gg < 2; gg++) {
                uint32_t f0, f1, f2, f3, e0, e1, e2, e3;
                ldsm_x4(f0, f1, f2, f3, v_h[gg] + koff);
                ldsm_x4(e0, e1, e2, e3, v_l[gg] + koff);
                mma_bf16(co[2 * gg], ah[0], ah[1], ah[2], ah[3], f0, f1);
                mma_bf16(co[2 * gg], ah[0], ah[1], ah[2], ah[3], e0, e1);
                mma_bf16(co[2 * gg], al[0], al[1], al[2], al[3], f0, f1);
                mma_bf16(co[2 * gg + 1], ah[0], ah[1], ah[2], ah[3], f2, f3);
                mma_bf16(co[2 * gg + 1], ah[0], ah[1], ah[2], ah[3], e2, e3);
                mma_bf16(co[2 * gg + 1], al[0], al[1], al[2], al[3], f2, f3);
            }
        }
    }

    float inv0 = 1.f / l[0], inv1 = 1.f / l[1];
#pragma unroll
    for (int ni = 0; ni < 4; ni++) {
        // co fragment ni: hd cols = (ni>>1)*16 + (ni&1)*8 + t*2
        int cc = (ni >> 1) * 16 + (ni & 1) * 8 + t * 2;
        int pi = z * 16 + (cc >> 1);
        if (r0 < NFT) {
            uint32_t hw, lw;
            split2(co[ni][0] * inv0, co[ni][1] * inv0, hw, lw);
            Oh[(size_t)r0 * D2 + pi] = hw;
            Ol[(size_t)r0 * D2 + pi] = lw;
        }
        if (r1 < NFT) {
            uint32_t hw, lw;
            split2(co[ni][2] * inv1, co[ni][3] * inv1, hw, lw);
            Oh[(size_t)r1 * D2 + pi] = hw;
            Ol[(size_t)r1 * D2 + pi] = lw;
        }
    }
}

// ---------------------------------------------------------------------------
// launch
// ---------------------------------------------------------------------------
extern "C" void kernel_launch(void* const* d_in, const int* in_sizes, int n_in,
                              void* d_out, int out_size) {
    const float* x            = (const float*)d_in[0];
    const float* edge_attr    = (const float*)d_in[1];
    const float* node_proj_w  = (const float*)d_in[2];
    const float* node_proj_b  = (const float*)d_in[3];
    const float* in_deg_emb   = (const float*)d_in[4];
    const float* out_deg_emb  = (const float*)d_in[5];
    const float* dist_bias    = (const float*)d_in[6];
    const float* edge_proj_w  = (const float*)d_in[7];
    const float* edge_proj_b  = (const float*)d_in[8];
    const float* cls_token    = (const float*)d_in[9];
    const float* q_w = (const float*)d_in[10];
    const float* q_b = (const float*)d_in[11];
    const float* k_w = (const float*)d_in[12];
    const float* k_b = (const float*)d_in[13];
    const float* v_w = (const float*)d_in[14];
    const float* v_b = (const float*)d_in[15];
    const float* o_w = (const float*)d_in[16];
    const float* o_b = (const float*)d_in[17];
    const float* ffn1_w = (const float*)d_in[18];
    const float* ffn1_b = (const float*)d_in[19];
    const float* ffn2_w = (const float*)d_in[20];
    const float* ffn2_b = (const float*)d_in[21];
    const float* ln1_s = (const float*)d_in[22];
    const float* ln1_b = (const float*)d_in[23];
    const float* ln2_s = (const float*)d_in[24];
    const float* ln2_b = (const float*)d_in[25];
    const float* fn_s = (const float*)d_in[26];
    const float* fn_b = (const float*)d_in[27];
    const int* edge_index  = (const int*)d_in[28];
    const int* dist_matrix = (const int*)d_in[29];
    float* out = (float*)d_out;

    float *h, *fin, *qkvb;
    uint32_t *hnh, *hnl, *qh, *ql, *kh, *kl, *vh, *vl, *oh, *ol, *fh, *fl;
    uint32_t *wh, *wl, *biasb;
    cudaGetSymbolAddress((void**)&h, g_h);
    cudaGetSymbolAddress((void**)&fin, g_fin);
    cudaGetSymbolAddress((void**)&hnh, g_hnh); cudaGetSymbolAddress((void**)&hnl, g_hnl);
    cudaGetSymbolAddress((void**)&qh, g_qh); cudaGetSymbolAddress((void**)&ql, g_ql);
    cudaGetSymbolAddress((void**)&kh, g_kh); cudaGetSymbolAddress((void**)&kl, g_kl);
    cudaGetSymbolAddress((void**)&vh, g_vh); cudaGetSymbolAddress((void**)&vl, g_vl);
    cudaGetSymbolAddress((void**)&oh, g_oh); cudaGetSymbolAddress((void**)&ol, g_ol);
    cudaGetSymbolAddress((void**)&fh, g_fh); cudaGetSymbolAddress((void**)&fl, g_fl);
    cudaGetSymbolAddress((void**)&wh, g_wh); cudaGetSymbolAddress((void**)&wl, g_wl);
    cudaGetSymbolAddress((void**)&biasb, g_biasb);
    cudaGetSymbolAddress((void**)&qkvb, g_qkvb);

    const int PQKV = LL * 768 * 128;
    const int DQ = LL * DD * DD / 2;
    const int DF = LL * FFND * DD / 2;
    split_qkv_kernel<<<(PQKV + 255) / 256, 256>>>(q_w, k_w, v_w, wh + WOFF_QKV, wl + WOFF_QKV);
    qkvb_prep_kernel<<<(LL * 768 + 255) / 256, 256>>>(q_b, k_b, v_b);
    split_prep_kernel<<<(DQ + 255) / 256, 256>>>(o_w, wh + WOFF_O, wl + WOFF_O, DQ);
    split_prep_kernel<<<(DF + 255) / 256, 256>>>(ffn1_w, wh + WOFF_F1, wl + WOFF_F1, DF);
    split_prep_kernel<<<(DF + 255) / 256, 256>>>(ffn2_w, wh + WOFF_F2, wl + WOFF_F2, DF);

    zero_deg_kernel<<<(NN + 255) / 256, 256>>>();
    count_deg_kernel<<<(EE + 255) / 256, 256>>>(edge_index);
    node_embed_kernel<<<NN, 256>>>(x, node_proj_w, node_proj_b, in_deg_emb, out_deg_emb);
    cls_kernel<<<1, 256>>>(cls_token);

    size_t nbp = (size_t)HH * NFT * BP;
    bias_fillb_kernel<<<(unsigned)((nbp + 255) / 256), 256>>>(dist_matrix, dist_bias);
    edge_bias_kernel<<<(EE + 255) / 256, 256>>>(edge_attr, edge_proj_w, edge_proj_b,
                                                edge_index);

    dim3 gemmQKV(12, 33);
    dim3 gemmD(4, 33);
    dim3 gemmF1(16, 33);
    dim3 attnG(33, 8);
    int lnG = (NFT + 7) / 8;

    for (int l = 0; l < LL; l++) {
        ln_warp_kernel<1><<<lnG, 256>>>(h, nullptr, hnh, hnl,
                                        ln1_s + l * DD, ln1_b + l * DD);
        gemm_sp_kernel<3><<<gemmQKV, 256>>>(hnh, hnl,
                                            wh + WOFF_QKV + (size_t)l * 98304,
                                            wl + WOFF_QKV + (size_t)l * 98304,
                                            qkvb + l * 768, nullptr, nullptr,
                                            qh, ql, kh, kl, vh, vl,
                                            NFT, 768, DD);
        attn_kernel<<<attnG, 128>>>(qh, ql, kh, kl, vh, vl, biasb, oh, ol);
        gemm_sp_kernel<1><<<gemmD, 256>>>(oh, ol,
                                          wh + WOFF_O + (size_t)l * 32768,
                                          wl + WOFF_O + (size_t)l * 32768,
                                          o_b + l * DD, h, h, nullptr, nullptr,
                                          nullptr, nullptr, nullptr, nullptr,
                                          NFT, DD, DD);
        ln_warp_kernel<1><<<lnG, 256>>>(h, nullptr, hnh, hnl,
                                        ln2_s + l * DD, ln2_b + l * DD);
        gemm_sp_kernel<2><<<gemmF1, 256>>>(hnh, hnl,
                                           wh + WOFF_F1 + (size_t)l * 131072,
                                           wl + WOFF_F1 + (size_t)l * 131072,
                                           ffn1_b + l * FFND, nullptr, nullptr, fh, fl,
                                           nullptr, nullptr, nullptr, nullptr,
                                           NFT, FFND, DD);
        gemm_sp_kernel<1><<<gemmD, 256>>>(fh, fl,
                                          wh + WOFF_F2 + (size_t)l * 131072,
                                          wl + WOFF_F2 + (size_t)l * 131072,
                                          ffn2_b + l * DD, h, h, nullptr, nullptr,
                                          nullptr, nullptr, nullptr, nullptr,
                                          NFT, DD, FFND);
    }

    ln_warp_kernel<0><<<lnG, 256>>>(h, fin, nullptr, nullptr, fn_s, fn_b);
    size_t total = (size_t)NFT * DD;
    if ((size_t)out_size >= total + DD) {
        cudaMemcpyAsync(out, fin, total * sizeof(float), cudaMemcpyDeviceToDevice);
        cudaMemcpyAsync(out + total, fin, DD * sizeof(float), cudaMemcpyDeviceToDevice);
    } else if ((size_t)out_size >= total) {
        cudaMemcpyAsync(out, fin, total * sizeof(float), cudaMemcpyDeviceToDevice);
    } else {
        cudaMemcpyAsync(out, fin, (size_t)out_size * sizeof(float),
                        cudaMemcpyDeviceToDevice);
    }
}

// round 8
// speedup vs baseline: 3.1903x; 1.0609x over previous
#include <cuda_runtime.h>
#include <cuda_fp16.h>
#include <cuda_bf16.h>
#include <math.h>
#include <stdint.h>

#define NN 2048
#define NFEAT 64
#define DD 256
#define HH 8
#define HDD 32
#define LL 6
#define FFND 1024
#define EE 32768
#define EFD 16
#define NFT 2049
#define MAXDEGC 64
#define D2 128
#define F2 512
#define BP 1025

__device__ float g_h[NFT * DD];
__device__ float g_fin[NFT * DD];
__device__ uint32_t g_hnh[NFT * D2], g_hnl[NFT * D2];
__device__ uint32_t g_qh[NFT * D2], g_ql[NFT * D2];
__device__ uint32_t g_kh[NFT * D2], g_kl[NFT * D2];
__device__ uint32_t g_vh[NFT * D2], g_vl[NFT * D2];
__device__ uint32_t g_oh[NFT * D2], g_ol[NFT * D2];
__device__ uint32_t g_fh[NFT * F2], g_fl[NFT * F2];
__device__ uint32_t g_biasb[(size_t)HH * NFT * BP];
#define WOFF_QKV 0
#define WOFF_O 589824
#define WOFF_F1 786432
#define WOFF_F2 1572864
#define WTOT 2359296
__device__ uint32_t g_wh[WTOT], g_wl[WTOT];
__device__ float g_qkvb[LL * 768];
__device__ int g_indeg[NN];
__device__ int g_outdeg[NN];

// ---------------------------------------------------------------------------
// helpers: fp16 hi/lo split (effective ~22-bit mantissa with 3-term MMA)
// ---------------------------------------------------------------------------
__device__ __forceinline__ void split2(float x0, float x1, uint32_t& hi, uint32_t& lo) {
    __half h0 = __float2half_rn(x0);
    __half h1 = __float2half_rn(x1);
    float r0 = x0 - __half2float(h0);
    float r1 = x1 - __half2float(h1);
    union { __half2 v; uint32_t u; } a, b;
    a.v = __halves2half2(h0, h1);
    b.v = __halves2half2(__float2half_rn(r0), __float2half_rn(r1));
    hi = a.u; lo = b.u;
}

__device__ __forceinline__ uint32_t pack_h2(float x0, float x1) {
    union { __half2 v; uint32_t u; } a;
    a.v = __floats2half2_rn(x0, x1);
    return a.u;
}

__device__ __forceinline__ void mma_hf(float c[4], uint32_t a0, uint32_t a1,
                                       uint32_t a2, uint32_t a3,
                                       uint32_t b0, uint32_t b1) {
    asm volatile(
        "mma.sync.aligned.m16n8k16.row.col.f32.f16.f16.f32 "
        "{%0,%1,%2,%3}, {%4,%5,%6,%7}, {%8,%9}, {%0,%1,%2,%3};"
        : "+f"(c[0]), "+f"(c[1]), "+f"(c[2]), "+f"(c[3])
        : "r"(a0), "r"(a1), "r"(a2), "r"(a3), "r"(b0), "r"(b1));
}

__device__ __forceinline__ uint32_t smem_u32(const void* p) {
    return (uint32_t)__cvta_generic_to_shared(p);
}

__device__ __forceinline__ void ldsm_x4(uint32_t& r0, uint32_t& r1,
                                        uint32_t& r2, uint32_t& r3, uint32_t addr) {
    asm volatile("ldmatrix.sync.aligned.m8n8.x4.shared.b16 {%0,%1,%2,%3}, [%4];"
                 : "=r"(r0), "=r"(r1), "=r"(r2), "=r"(r3) : "r"(addr));
}

// ---------------------------------------------------------------------------
// prep kernels
// ---------------------------------------------------------------------------
__global__ void split_prep_kernel(const float* __restrict__ src,
                                  uint32_t* __restrict__ dh,
                                  uint32_t* __restrict__ dl, int npairs) {
    int i = blockIdx.x * blockDim.x + threadIdx.x;
    if (i < npairs) {
        float2 v = *(const float2*)&src[2 * i];
        uint32_t h, l;
        split2(v.x, v.y, h, l);
        dh[i] = h; dl[i] = l;
    }
}

__global__ void split_qkv_kernel(const float* __restrict__ q_w,
                                 const float* __restrict__ k_w,
                                 const float* __restrict__ v_w,
                                 uint32_t* __restrict__ dh,
                                 uint32_t* __restrict__ dl) {
    int i = blockIdx.x * blockDim.x + threadIdx.x;
    if (i >= LL * 768 * 128) return;
    int l = i / (768 * 128);
    int rem = i - l * 768 * 128;
    int row = rem >> 7;
    int p = rem & 127;
    const float* src = (row < 256) ? q_w : (row < 512) ? k_w : v_w;
    int rr = row & 255;
    const float* sp = src + (size_t)l * DD * DD + (size_t)rr * DD + 2 * p;
    uint32_t h, lo;
    split2(sp[0], sp[1], h, lo);
    dh[i] = h; dl[i] = lo;
}

__global__ void qkvb_prep_kernel(const float* __restrict__ q_b,
                                 const float* __restrict__ k_b,
                                 const float* __restrict__ v_b) {
    int i = blockIdx.x * blockDim.x + threadIdx.x;
    if (i >= LL * 768) return;
    int l = i / 768, c = i % 768;
    float v = (c < 256) ? q_b[l * 256 + c]
            : (c < 512) ? k_b[l * 256 + (c - 256)]
                        : v_b[l * 256 + (c - 512)];
    g_qkvb[i] = v;
}

// ---------------------------------------------------------------------------
// degree counting / node embedding
// ---------------------------------------------------------------------------
__global__ void zero_deg_kernel() {
    int i = blockIdx.x * blockDim.x + threadIdx.x;
    if (i < NN) { g_indeg[i] = 0; g_outdeg[i] = 0; }
}

__global__ void count_deg_kernel(const int* __restrict__ edge_index) {
    int e = blockIdx.x * blockDim.x + threadIdx.x;
    if (e < EE) {
        atomicAdd(&g_outdeg[edge_index[e]], 1);
        atomicAdd(&g_indeg[edge_index[EE + e]], 1);
    }
}

__global__ void node_embed_kernel(const float* __restrict__ x,
                                  const float* __restrict__ W,
                                  const float* __restrict__ b,
                                  const float* __restrict__ inemb,
                                  const float* __restrict__ outemb) {
    int row = blockIdx.x;
    int col = threadIdx.x;
    __shared__ float xs[NFEAT];
    if (col < NFEAT) xs[col] = x[row * NFEAT + col];
    __syncthreads();
    float acc = 0.f;
#pragma unroll
    for (int k = 0; k < NFEAT; k++) acc += xs[k] * W[col * NFEAT + k];
    int ind = min(g_indeg[row], MAXDEGC);
    int outd = min(g_outdeg[row], MAXDEGC);
    g_h[(size_t)(row + 1) * DD + col] =
        acc + b[col] + inemb[ind * DD + col] + outemb[outd * DD + col];
}

__global__ void cls_kernel(const float* __restrict__ cls) {
    g_h[threadIdx.x] = cls[threadIdx.x];
}

// ---------------------------------------------------------------------------
// bias: direct bf16 fill + 16-bit CAS edge scatter
// ---------------------------------------------------------------------------
__global__ void bias_fillb_kernel(const int* __restrict__ dist,
                                  const float* __restrict__ dist_bias) {
    size_t idx = (size_t)blockIdx.x * blockDim.x + threadIdx.x;
    if (idx >= (size_t)HH * NFT * BP) return;
    int h = (int)(idx / ((size_t)NFT * BP));
    size_t rem = idx - (size_t)h * NFT * BP;
    int i = (int)(rem / BP);
    int p = (int)(rem % BP);
    int j0 = 2 * p, j1 = 2 * p + 1;
    int d0 = 0, d1 = 0;
    if (i > 0) {
        if (j0 > 0) {
            d0 = dist[(size_t)(i - 1) * NN + (j0 - 1)];
            d0 = max(0, min(d0, 9));
        }
        if (j1 > 0 && j1 < NFT) {
            d1 = dist[(size_t)(i - 1) * NN + (j1 - 1)];
            d1 = max(0, min(d1, 9));
        }
    }
    float v0 = dist_bias[d0 * HH + h];
    float v1 = (j1 < NFT) ? dist_bias[d1 * HH + h] : 0.f;
    union { __nv_bfloat162 v; uint32_t u; } a;
    a.v = __halves2bfloat162(__float2bfloat16_rn(v0), __float2bfloat16_rn(v1));
    g_biasb[idx] = a.u;
}

__device__ __forceinline__ void atomic_add_bf16half(uint32_t* addr, int hi, float val) {
    uint32_t old = *addr, assumed;
    do {
        assumed = old;
        unsigned short bits = hi ? (unsigned short)(assumed >> 16)
                                 : (unsigned short)(assumed & 0xffffu);
        __nv_bfloat16_raw r; r.x = bits;
        float cur = __bfloat162float((__nv_bfloat16)r);
        __nv_bfloat16 nb = __float2bfloat16_rn(cur + val);
        __nv_bfloat16_raw nr = static_cast<__nv_bfloat16_raw>(nb);
        uint32_t nw = hi ? ((assumed & 0x0000ffffu) | ((uint32_t)nr.x << 16))
                         : ((assumed & 0xffff0000u) | (uint32_t)nr.x);
        old = atomicCAS(addr, assumed, nw);
    } while (old != assumed);
}

__global__ void edge_bias_kernel(const float* __restrict__ edge_attr,
                                 const float* __restrict__ epw,
                                 const float* __restrict__ epb,
                                 const int* __restrict__ edge_index) {
    int e = blockIdx.x * blockDim.x + threadIdx.x;
    if (e >= EE) return;
    const float* ea = edge_attr + (size_t)e * EFD;
    int src = edge_index[e];
    int dst = edge_index[EE + e];
    int col = dst + 1;
    int p = col >> 1, hi = col & 1;
#pragma unroll
    for (int h = 0; h < HH; h++) {
        float pr = epb[h];
#pragma unroll
        for (int k = 0; k < EFD; k++) pr += ea[k] * epw[h * EFD + k];
        uint32_t* addr = &g_biasb[((size_t)h * NFT + src + 1) * BP + p];
        atomic_add_bf16half(addr, hi, pr);
    }
}

// ---------------------------------------------------------------------------
// warp-per-row layernorm
// ---------------------------------------------------------------------------
template <int SPLIT>
__global__ void ln_warp_kernel(const float* __restrict__ in,
                               float* __restrict__ outf,
                               uint32_t* __restrict__ oh, uint32_t* __restrict__ ol,
                               const float* __restrict__ s, const float* __restrict__ b) {
    int w = threadIdx.x >> 5, lane = threadIdx.x & 31;
    int row = blockIdx.x * 8 + w;
    if (row >= NFT) return;
    const float* p = in + (size_t)row * DD;
    float4 a = *(const float4*)&p[lane * 4];
    float4 c = *(const float4*)&p[128 + lane * 4];
    float sum = a.x + a.y + a.z + a.w + c.x + c.y + c.z + c.w;
#pragma unroll
    for (int o = 16; o > 0; o >>= 1) sum += __shfl_xor_sync(0xffffffffu, sum, o);
    float mean = sum * (1.0f / DD);
    float d0 = a.x - mean, d1 = a.y - mean, d2 = a.z - mean, d3 = a.w - mean;
    float d4 = c.x - mean, d5 = c.y - mean, d6 = c.z - mean, d7 = c.w - mean;
    float vs = d0 * d0 + d1 * d1 + d2 * d2 + d3 * d3 +
               d4 * d4 + d5 * d5 + d6 * d6 + d7 * d7;
#pragma unroll
    for (int o = 16; o > 0; o >>= 1) vs += __shfl_xor_sync(0xffffffffu, vs, o);
    float rstd = rsqrtf(vs * (1.0f / DD) + 1e-5f);
    int c0 = lane * 4, c1 = 128 + lane * 4;
    float o0 = d0 * rstd * s[c0 + 0] + b[c0 + 0];
    float o1 = d1 * rstd * s[c0 + 1] + b[c0 + 1];
    float o2 = d2 * rstd * s[c0 + 2] + b[c0 + 2];
    float o3 = d3 * rstd * s[c0 + 3] + b[c0 + 3];
    float o4 = d4 * rstd * s[c1 + 0] + b[c1 + 0];
    float o5 = d5 * rstd * s[c1 + 1] + b[c1 + 1];
    float o6 = d6 * rstd * s[c1 + 2] + b[c1 + 2];
    float o7 = d7 * rstd * s[c1 + 3] + b[c1 + 3];
    if (SPLIT) {
        uint32_t h, l;
        size_t base = (size_t)row * D2;
        split2(o0, o1, h, l); oh[base + 2 * lane] = h;      ol[base + 2 * lane] = l;
        split2(o2, o3, h, l); oh[base + 2 * lane + 1] = h;  ol[base + 2 * lane + 1] = l;
        split2(o4, o5, h, l); oh[base + 64 + 2 * lane] = h; ol[base + 64 + 2 * lane] = l;
        split2(o6, o7, h, l); oh[base + 65 + 2 * lane] = h; ol[base + 65 + 2 * lane] = l;
    } else {
        float* q = outf + (size_t)row * DD;
        *(float4*)&q[c0] = make_float4(o0, o1, o2, o3);
        *(float4*)&q[c1] = make_float4(o4, o5, o6, o7);
    }
}

// ---------------------------------------------------------------------------
// split GEMM with ldmatrix fragment loads (fp16 split, 3-MMA).
// MODE 0: split out. 1: fp32+res. 2: gelu+split. 3: fused-QKV epilogue.
// ---------------------------------------------------------------------------
template <int MODE>
__global__ void gemm_sp_kernel(const uint32_t* __restrict__ Ahg,
                               const uint32_t* __restrict__ Alg,
                               const uint32_t* __restrict__ Whg,
                               const uint32_t* __restrict__ Wlg,
                               const float* __restrict__ bias,
                               const float* __restrict__ res,
                               float* __restrict__ outf,
                               uint32_t* __restrict__ outh,
                               uint32_t* __restrict__ outl,
                               uint32_t* __restrict__ kh_, uint32_t* __restrict__ kl_,
                               uint32_t* __restrict__ vh_, uint32_t* __restrict__ vl_,
                               int M, int Ncol, int K) {
    __shared__ __align__(16) uint32_t Ah[64][20], Al[64][20];
    __shared__ __align__(16) uint32_t Bh[64][20], Bl[64][20];
    int K2 = K >> 1;
    int tid = threadIdx.x;
    int lane = tid & 31, wid = tid >> 5;
    int warpM = wid & 3, warpN = wid >> 2;
    int m0 = blockIdx.y * 64, n0 = blockIdx.x * 64;
    int g = lane >> 2, t = lane & 3;

    float c[4][4] = {};

    int lr = tid >> 2;
    int lq = (tid & 3) * 4;
    bool arow = (m0 + lr) < M;
    const uint4 z4 = make_uint4(0, 0, 0, 0);
    uint4 rah = arow ? *(const uint4*)&Ahg[(size_t)(m0 + lr) * K2 + lq] : z4;
    uint4 ral = arow ? *(const uint4*)&Alg[(size_t)(m0 + lr) * K2 + lq] : z4;
    uint4 rbh = *(const uint4*)&Whg[(size_t)(n0 + lr) * K2 + lq];
    uint4 rbl = *(const uint4*)&Wlg[(size_t)(n0 + lr) * K2 + lq];

    uint32_t a_h = smem_u32(&Ah[warpM * 16 + (lane & 15)][(lane >> 4) * 4]);
    uint32_t a_l = smem_u32(&Al[warpM * 16 + (lane & 15)][(lane >> 4) * 4]);
    int brow = warpN * 32 + (lane >> 4) * 8 + (lane & 7);
    int bseg = ((lane >> 3) & 1) * 4;
    uint32_t b_h0 = smem_u32(&Bh[brow][bseg]);
    uint32_t b_h1 = smem_u32(&Bh[brow + 16][bseg]);
    uint32_t b_l0 = smem_u32(&Bl[brow][bseg]);
    uint32_t b_l1 = smem_u32(&Bl[brow + 16][bseg]);

    for (int k0 = 0; k0 < K2; k0 += 16) {
        __syncthreads();
        Ah[lr][lq] = rah.x; Ah[lr][lq + 1] = rah.y; Ah[lr][lq + 2] = rah.z; Ah[lr][lq + 3] = rah.w;
        Al[lr][lq] = ral.x; Al[lr][lq + 1] = ral.y; Al[lr][lq + 2] = ral.z; Al[lr][lq + 3] = ral.w;
        Bh[lr][lq] = rbh.x; Bh[lr][lq + 1] = rbh.y; Bh[lr][lq + 2] = rbh.z; Bh[lr][lq + 3] = rbh.w;
        Bl[lr][lq] = rbl.x; Bl[lr][lq + 1] = rbl.y; Bl[lr][lq + 2] = rbl.z; Bl[lr][lq + 3] = rbl.w;
        __syncthreads();
        if (k0 + 16 < K2) {
            rah = arow ? *(const uint4*)&Ahg[(size_t)(m0 + lr) * K2 + k0 + 16 + lq] : z4;
            ral = arow ? *(const uint4*)&Alg[(size_t)(m0 + lr) * K2 + k0 + 16 + lq] : z4;
            rbh = *(const uint4*)&Whg[(size_t)(n0 + lr) * K2 + k0 + 16 + lq];
            rbl = *(const uint4*)&Wlg[(size_t)(n0 + lr) * K2 + k0 + 16 + lq];
        }
#pragma unroll
        for (int kk = 0; kk < 2; kk++) {
            uint32_t koff = kk * 32;
            uint32_t ah0, ah1, ah2, ah3, al0, al1, al2, al3;
            ldsm_x4(ah0, ah1, ah2, ah3, a_h + koff);
            ldsm_x4(al0, al1, al2, al3, a_l + koff);
            uint32_t bh[8], bl[8];
            ldsm_x4(bh[0], bh[1], bh[2], bh[3], b_h0 + koff);
            ldsm_x4(bh[4], bh[5], bh[6], bh[7], b_h1 + koff);
            ldsm_x4(bl[0], bl[1], bl[2], bl[3], b_l0 + koff);
            ldsm_x4(bl[4], bl[5], bl[6], bl[7], b_l1 + koff);
#pragma unroll
            for (int ni = 0; ni < 4; ni++) {
                uint32_t b0h = bh[ni * 2], b1h = bh[ni * 2 + 1];
                uint32_t b0l = bl[ni * 2], b1l = bl[ni * 2 + 1];
                mma_hf(c[ni], ah0, ah1, ah2, ah3, b0h, b1h);
                mma_hf(c[ni], ah0, ah1, ah2, ah3, b0l, b1l);
                mma_hf(c[ni], al0, al1, al2, al3, b0h, b1h);
            }
        }
    }

    int N2 = Ncol >> 1;
#pragma unroll
    for (int ni = 0; ni < 4; ni++) {
        int col = n0 + warpN * 32 + ((ni < 2) ? 0 : 16) + (ni & 1) * 8 + t * 2;
        float b0 = bias[col], b1 = bias[col + 1];
#pragma unroll
        for (int half = 0; half < 2; half++) {
            int r = m0 + warpM * 16 + g + half * 8;
            if (r >= M) continue;
            float v0 = c[ni][half * 2 + 0] + b0;
            float v1 = c[ni][half * 2 + 1] + b1;
            if (MODE == 2) {
                v0 = 0.5f * v0 * (1.0f + erff(v0 * 0.7071067811865475f));
                v1 = 0.5f * v1 * (1.0f + erff(v1 * 0.7071067811865475f));
            }
            if (MODE == 1) {
                outf[(size_t)r * Ncol + col] = v0 + res[(size_t)r * Ncol + col];
                outf[(size_t)r * Ncol + col + 1] = v1 + res[(size_t)r * Ncol + col + 1];
            } else if (MODE == 3) {
                int buf = col >> 8, cc = col & 255;
                uint32_t* ph = (buf == 0) ? outh : (buf == 1) ? kh_ : vh_;
                uint32_t* pl = (buf == 0) ? outl : (buf == 1) ? kl_ : vl_;
                uint32_t hw, lw;
                split2(v0, v1, hw, lw);
                ph[(size_t)r * D2 + (cc >> 1)] = hw;
                pl[(size_t)r * D2 + (cc >> 1)] = lw;
            } else {
                uint32_t hw, lw;
                split2(v0, v1, hw, lw);
                outh[(size_t)r * N2 + (col >> 1)] = hw;
                outl[(size_t)r * N2 + (col >> 1)] = lw;
            }
        }
    }
}

// ---------------------------------------------------------------------------
// fused flash attention (fp16 split; P direct fp16, no split -> 16 PV MMAs)
// ---------------------------------------------------------------------------
__global__ void __launch_bounds__(128)
attn_kernel(const uint32_t* __restrict__ Qh, const uint32_t* __restrict__ Ql,
            const uint32_t* __restrict__ Khg, const uint32_t* __restrict__ Klg,
            const uint32_t* __restrict__ Vhg, const uint32_t* __restrict__ Vlg,
            const uint32_t* __restrict__ biasb,
            uint32_t* __restrict__ Oh, uint32_t* __restrict__ Ol) {
    __shared__ __align__(16) uint32_t Ksh[64][20], Ksl[64][20];
    __shared__ __align__(16) uint32_t Vsh[32][36], Vsl[32][36];

    int tid = threadIdx.x;
    int lane = tid & 31, w = tid >> 5;
    int g = lane >> 2, t = lane & 3;
    int z = blockIdx.y;
    int i0 = blockIdx.x * 64;
    int r0 = i0 + w * 16 + g;
    int r1 = r0 + 8;

    uint32_t qh[2][4], ql[2][4];
#pragma unroll
    for (int kk = 0; kk < 2; kk++) {
#pragma unroll
        for (int j = 0; j < 4; j++) {
            int rr = r0 + (j & 1) * 8;
            int pi = z * 16 + kk * 8 + (j >> 1) * 4 + t;
            qh[kk][j] = (rr < NFT) ? Qh[(size_t)rr * D2 + pi] : 0u;
            ql[kk][j] = (rr < NFT) ? Ql[(size_t)rr * D2 + pi] : 0u;
        }
    }

    float m[2] = {-1e30f, -1e30f}, l[2] = {0.f, 0.f};
    float co[4][4] = {};

    int lkey = tid >> 1;
    int lhalf = (tid & 1) * 8;
    int kp = tid >> 2;
    int hp = (tid & 3) * 4;

    const float inv = 0.17677669529663687f;
    int br0 = min(r0, NFT - 1), br1 = min(r1, NFT - 1);
    const uint32_t* bp0 = biasb + ((size_t)z * NFT + br0) * BP;
    const uint32_t* bp1 = biasb + ((size_t)z * NFT + br1) * BP;

    int krow = (lane >> 4) * 8 + (lane & 7);
    int kseg = ((lane >> 3) & 1) * 4;
    uint32_t k_h[4], k_l[4];
#pragma unroll
    for (int gg = 0; gg < 4; gg++) {
        k_h[gg] = smem_u32(&Ksh[gg * 16 + krow][kseg]);
        k_l[gg] = smem_u32(&Ksl[gg * 16 + krow][kseg]);
    }
    uint32_t v_h[2], v_l[2];
#pragma unroll
    for (int gg = 0; gg < 2; gg++) {
        v_h[gg] = smem_u32(&Vsh[gg * 16 + krow][kseg]);
        v_l[gg] = smem_u32(&Vsl[gg * 16 + krow][kseg]);
    }

    const uint4 z4 = make_uint4(0, 0, 0, 0);
    uint4 rkh0, rkh1, rkl0, rkl1, vah, val_, vbh, vbl;
    {
        bool kv = lkey < NFT;
        const uint32_t* kb = &Khg[(size_t)lkey * D2 + z * 16 + lhalf];
        const uint32_t* lb = &Klg[(size_t)lkey * D2 + z * 16 + lhalf];
        rkh0 = kv ? *(const uint4*)kb : z4;
        rkh1 = kv ? *(const uint4*)(kb + 4) : z4;
        rkl0 = kv ? *(const uint4*)lb : z4;
        rkl1 = kv ? *(const uint4*)(lb + 4) : z4;
        int ra = 2 * kp, rb = 2 * kp + 1;
        vah = (ra < NFT) ? *(const uint4*)&Vhg[(size_t)ra * D2 + z * 16 + hp] : z4;
        val_ = (ra < NFT) ? *(const uint4*)&Vlg[(size_t)ra * D2 + z * 16 + hp] : z4;
        vbh = (rb < NFT) ? *(const uint4*)&Vhg[(size_t)rb * D2 + z * 16 + hp] : z4;
        vbl = (rb < NFT) ? *(const uint4*)&Vlg[(size_t)rb * D2 + z * 16 + hp] : z4;
    }

    for (int jt = 0; jt < 33; jt++) {
        int j0 = jt * 64;
        __syncthreads();
        {
            Ksh[lkey][lhalf + 0] = rkh0.x; Ksh[lkey][lhalf + 1] = rkh0.y;
            Ksh[lkey][lhalf + 2] = rkh0.z; Ksh[lkey][lhalf + 3] = rkh0.w;
            Ksh[lkey][lhalf + 4] = rkh1.x; Ksh[lkey][lhalf + 5] = rkh1.y;
            Ksh[lkey][lhalf + 6] = rkh1.z; Ksh[lkey][lhalf + 7] = rkh1.w;
            Ksl[lkey][lhalf + 0] = rkl0.x; Ksl[lkey][lhalf + 1] = rkl0.y;
            Ksl[lkey][lhalf + 2] = rkl0.z; Ksl[lkey][lhalf + 3] = rkl0.w;
            Ksl[lkey][lhalf + 4] = rkl1.x; Ksl[lkey][lhalf + 5] = rkl1.y;
            Ksl[lkey][lhalf + 6] = rkl1.z; Ksl[lkey][lhalf + 7] = rkl1.w;
            Vsh[2 * hp + 0][kp] = __byte_perm(vah.x, vbh.x, 0x5410);
            Vsh[2 * hp + 1][kp] = __byte_perm(vah.x, vbh.x, 0x7632);
            Vsh[2 * hp + 2][kp] = __byte_perm(vah.y, vbh.y, 0x5410);
            Vsh[2 * hp + 3][kp] = __byte_perm(vah.y, vbh.y, 0x7632);
            Vsh[2 * hp + 4][kp] = __byte_perm(vah.z, vbh.z, 0x5410);
            Vsh[2 * hp + 5][kp] = __byte_perm(vah.z, vbh.z, 0x7632);
            Vsh[2 * hp + 6][kp] = __byte_perm(vah.w, vbh.w, 0x5410);
            Vsh[2 * hp + 7][kp] = __byte_perm(vah.w, vbh.w, 0x7632);
            Vsl[2 * hp + 0][kp] = __byte_perm(val_.x, vbl.x, 0x5410);
            Vsl[2 * hp + 1][kp] = __byte_perm(val_.x, vbl.x, 0x7632);
            Vsl[2 * hp + 2][kp] = __byte_perm(val_.y, vbl.y, 0x5410);
            Vsl[2 * hp + 3][kp] = __byte_perm(val_.y, vbl.y, 0x7632);
            Vsl[2 * hp + 4][kp] = __byte_perm(val_.z, vbl.z, 0x5410);
            Vsl[2 * hp + 5][kp] = __byte_perm(val_.z, vbl.z, 0x7632);
            Vsl[2 * hp + 6][kp] = __byte_perm(val_.w, vbl.w, 0x5410);
            Vsl[2 * hp + 7][kp] = __byte_perm(val_.w, vbl.w, 0x7632);
        }
        __syncthreads();
        if (jt + 1 < 33) {
            int n0 = (jt + 1) * 64;
            bool kv = n0 + lkey < NFT;
            const uint32_t* kb = &Khg[(size_t)(n0 + lkey) * D2 + z * 16 + lhalf];
            const uint32_t* lb = &Klg[(size_t)(n0 + lkey) * D2 + z * 16 + lhalf];
            rkh0 = kv ? *(const uint4*)kb : z4;
            rkh1 = kv ? *(const uint4*)(kb + 4) : z4;
            rkl0 = kv ? *(const uint4*)lb : z4;
            rkl1 = kv ? *(const uint4*)(lb + 4) : z4;
            int ra = n0 + 2 * kp, rb = ra + 1;
            vah = (ra < NFT) ? *(const uint4*)&Vhg[(size_t)ra * D2 + z * 16 + hp] : z4;
            val_ = (ra < NFT) ? *(const uint4*)&Vlg[(size_t)ra * D2 + z * 16 + hp] : z4;
            vbh = (rb < NFT) ? *(const uint4*)&Vhg[(size_t)rb * D2 + z * 16 + hp] : z4;
            vbl = (rb < NFT) ? *(const uint4*)&Vlg[(size_t)rb * D2 + z * 16 + hp] : z4;
        }

        // S = Q @ K^T
        float cs[8][4] = {};
#pragma unroll
        for (int kk = 0; kk < 2; kk++) {
            uint32_t koff = kk * 32;
#pragma unroll
            for (int gg = 0; gg < 4; gg++) {
                uint32_t f0, f1, f2, f3, e0, e1, e2, e3;
                ldsm_x4(f0, f1, f2, f3, k_h[gg] + koff);
                ldsm_x4(e0, e1, e2, e3, k_l[gg] + koff);
                mma_hf(cs[2 * gg], qh[kk][0], qh[kk][1], qh[kk][2], qh[kk][3], f0, f1);
                mma_hf(cs[2 * gg], qh[kk][0], qh[kk][1], qh[kk][2], qh[kk][3], e0, e1);
                mma_hf(cs[2 * gg], ql[kk][0], ql[kk][1], ql[kk][2], ql[kk][3], f0, f1);
                mma_hf(cs[2 * gg + 1], qh[kk][0], qh[kk][1], qh[kk][2], qh[kk][3], f2, f3);
                mma_hf(cs[2 * gg + 1], qh[kk][0], qh[kk][1], qh[kk][2], qh[kk][3], e2, e3);
                mma_hf(cs[2 * gg + 1], ql[kk][0], ql[kk][1], ql[kk][2], ql[kk][3], f2, f3);
            }
        }

        // scale + bias + guards
#pragma unroll
        for (int ni = 0; ni < 8; ni++) {
            int gg = ni >> 1;
            int col = j0 + gg * 16 + (ni & 1) * 8 + t * 2;
            int pidx = (col >> 1);
            union { uint32_t u; __nv_bfloat162 v; } w0, w1;
            w0.u = bp0[pidx]; w1.u = bp1[pidx];
            float2 f0 = __bfloat1622float2(w0.v);
            float2 f1 = __bfloat1622float2(w1.v);
            bool v0 = col < NFT, v1 = col + 1 < NFT;
            cs[ni][0] = v0 ? cs[ni][0] * inv + f0.x : -1e30f;
            cs[ni][1] = v1 ? cs[ni][1] * inv + f0.y : -1e30f;
            cs[ni][2] = v0 ? cs[ni][2] * inv + f1.x : -1e30f;
            cs[ni][3] = v1 ? cs[ni][3] * inv + f1.y : -1e30f;
        }

        // online softmax
#pragma unroll
        for (int hh = 0; hh < 2; hh++) {
            int c0 = hh * 2;
            float mx = -1e30f;
#pragma unroll
            for (int ni = 0; ni < 8; ni++)
                mx = fmaxf(mx, fmaxf(cs[ni][c0], cs[ni][c0 + 1]));
            mx = fmaxf(mx, __shfl_xor_sync(0xffffffffu, mx, 1));
            mx = fmaxf(mx, __shfl_xor_sync(0xffffffffu, mx, 2));
            float mn = fmaxf(m[hh], mx);
            float corr = __expf(m[hh] - mn);
            m[hh] = mn;
            l[hh] *= corr;
#pragma unroll
            for (int ni = 0; ni < 4; ni++) {
                co[ni][c0] *= corr;
                co[ni][c0 + 1] *= corr;
            }
            float sum = 0.f;
#pragma unroll
            for (int ni = 0; ni < 8; ni++) {
                float p0 = __expf(cs[ni][c0] - mn);
                float p1 = __expf(cs[ni][c0 + 1] - mn);
                cs[ni][c0] = p0; cs[ni][c0 + 1] = p1;
                sum += p0 + p1;
            }
            sum += __shfl_xor_sync(0xffffffffu, sum, 1);
            sum += __shfl_xor_sync(0xffffffffu, sum, 2);
            l[hh] += sum;
        }

        // O += P @ V : P packed to fp16 directly (no split), 2 MMAs per gg
#pragma unroll
        for (int kk = 0; kk < 4; kk++) {
            uint32_t a0 = pack_h2(cs[2 * kk][0], cs[2 * kk][1]);
            uint32_t a1 = pack_h2(cs[2 * kk][2], cs[2 * kk][3]);
            uint32_t a2 = pack_h2(cs[2 * kk + 1][0], cs[2 * kk + 1][1]);
            uint32_t a3 = pack_h2(cs[2 * kk + 1][2], cs[2 * kk + 1][3]);
            uint32_t koff = kk * 32;
#pragma unroll
            for (int gg = 0; gg < 2; gg++) {
                uint32_t f0, f1, f2, f3, e0, e1, e2, e3;
                ldsm_x4(f0, f1, f2, f3, v_h[gg] + koff);
                ldsm_x4(e0, e1, e2, e3, v_l[gg] + koff);
                mma_hf(co[2 * gg], a0, a1, a2, a3, f0, f1);
                mma_hf(co[2 * gg], a0, a1, a2, a3, e0, e1);
                mma_hf(co[2 * gg + 1], a0, a1, a2, a3, f2, f3);
                mma_hf(co[2 * gg + 1], a0, a1, a2, a3, e2, e3);
            }
        }
    }

    float inv0 = 1.f / l[0], inv1 = 1.f / l[1];
#pragma unroll
    for (int ni = 0; ni < 4; ni++) {
        int cc = (ni >> 1) * 16 + (ni & 1) * 8 + t * 2;
        int pi = z * 16 + (cc >> 1);
        if (r0 < NFT) {
            uint32_t hw, lw;
            split2(co[ni][0] * inv0, co[ni][1] * inv0, hw, lw);
            Oh[(size_t)r0 * D2 + pi] = hw;
            Ol[(size_t)r0 * D2 + pi] = lw;
        }
        if (r1 < NFT) {
            uint32_t hw, lw;
            split2(co[ni][2] * inv1, co[ni][3] * inv1, hw, lw);
            Oh[(size_t)r1 * D2 + pi] = hw;
            Ol[(size_t)r1 * D2 + pi] = lw;
        }
    }
}

// ---------------------------------------------------------------------------
// launch
// ---------------------------------------------------------------------------
extern "C" void kernel_launch(void* const* d_in, const int* in_sizes, int n_in,
                              void* d_out, int out_size) {
    const float* x            = (const float*)d_in[0];
    const float* edge_attr    = (const float*)d_in[1];
    const float* node_proj_w  = (const float*)d_in[2];
    const float* node_proj_b  = (const float*)d_in[3];
    const float* in_deg_emb   = (const float*)d_in[4];
    const float* out_deg_emb  = (const float*)d_in[5];
    const float* dist_bias    = (const float*)d_in[6];
    const float* edge_proj_w  = (const float*)d_in[7];
    const float* edge_proj_b  = (const float*)d_in[8];
    const float* cls_token    = (const float*)d_in[9];
    const float* q_w = (const float*)d_in[10];
    const float* q_b = (const float*)d_in[11];
    const float* k_w = (const float*)d_in[12];
    const float* k_b = (const float*)d_in[13];
    const float* v_w = (const float*)d_in[14];
    const float* v_b = (const float*)d_in[15];
    const float* o_w = (const float*)d_in[16];
    const float* o_b = (const float*)d_in[17];
    const float* ffn1_w = (const float*)d_in[18];
    const float* ffn1_b = (const float*)d_in[19];
    const float* ffn2_w = (const float*)d_in[20];
    const float* ffn2_b = (const float*)d_in[21];
    const float* ln1_s = (const float*)d_in[22];
    const float* ln1_b = (const float*)d_in[23];
    const float* ln2_s = (const float*)d_in[24];
    const float* ln2_b = (const float*)d_in[25];
    const float* fn_s = (const float*)d_in[26];
    const float* fn_b = (const float*)d_in[27];
    const int* edge_index  = (const int*)d_in[28];
    const int* dist_matrix = (const int*)d_in[29];
    float* out = (float*)d_out;

    float *h, *fin, *qkvb;
    uint32_t *hnh, *hnl, *qh, *ql, *kh, *kl, *vh, *vl, *oh, *ol, *fh, *fl;
    uint32_t *wh, *wl, *biasb;
    cudaGetSymbolAddress((void**)&h, g_h);
    cudaGetSymbolAddress((void**)&fin, g_fin);
    cudaGetSymbolAddress((void**)&hnh, g_hnh); cudaGetSymbolAddress((void**)&hnl, g_hnl);
    cudaGetSymbolAddress((void**)&qh, g_qh); cudaGetSymbolAddress((void**)&ql, g_ql);
    cudaGetSymbolAddress((void**)&kh, g_kh); cudaGetSymbolAddress((void**)&kl, g_kl);
    cudaGetSymbolAddress((void**)&vh, g_vh); cudaGetSymbolAddress((void**)&vl, g_vl);
    cudaGetSymbolAddress((void**)&oh, g_oh); cudaGetSymbolAddress((void**)&ol, g_ol);
    cudaGetSymbolAddress((void**)&fh, g_fh); cudaGetSymbolAddress((void**)&fl, g_fl);
    cudaGetSymbolAddress((void**)&wh, g_wh); cudaGetSymbolAddress((void**)&wl, g_wl);
    cudaGetSymbolAddress((void**)&biasb, g_biasb);
    cudaGetSymbolAddress((void**)&qkvb, g_qkvb);

    const int PQKV = LL * 768 * 128;
    const int DQ = LL * DD * DD / 2;
    const int DF = LL * FFND * DD / 2;
    split_qkv_kernel<<<(PQKV + 255) / 256, 256>>>(q_w, k_w, v_w, wh + WOFF_QKV, wl + WOFF_QKV);
    qkvb_prep_kernel<<<(LL * 768 + 255) / 256, 256>>>(q_b, k_b, v_b);
    split_prep_kernel<<<(DQ + 255) / 256, 256>>>(o_w, wh + WOFF_O, wl + WOFF_O, DQ);
    split_prep_kernel<<<(DF + 255) / 256, 256>>>(ffn1_w, wh + WOFF_F1, wl + WOFF_F1, DF);
    split_prep_kernel<<<(DF + 255) / 256, 256>>>(ffn2_w, wh + WOFF_F2, wl + WOFF_F2, DF);

    zero_deg_kernel<<<(NN + 255) / 256, 256>>>();
    count_deg_kernel<<<(EE + 255) / 256, 256>>>(edge_index);
    node_embed_kernel<<<NN, 256>>>(x, node_proj_w, node_proj_b, in_deg_emb, out_deg_emb);
    cls_kernel<<<1, 256>>>(cls_token);

    size_t nbp = (size_t)HH * NFT * BP;
    bias_fillb_kernel<<<(unsigned)((nbp + 255) / 256), 256>>>(dist_matrix, dist_bias);
    edge_bias_kernel<<<(EE + 255) / 256, 256>>>(edge_attr, edge_proj_w, edge_proj_b,
                                                edge_index);

    dim3 gemmQKV(12, 33);
    dim3 gemmD(4, 33);
    dim3 gemmF1(16, 33);
    dim3 attnG(33, 8);
    int lnG = (NFT + 7) / 8;

    for (int l = 0; l < LL; l++) {
        ln_warp_kernel<1><<<lnG, 256>>>(h, nullptr, hnh, hnl,
                                        ln1_s + l * DD, ln1_b + l * DD);
        gemm_sp_kernel<3><<<gemmQKV, 256>>>(hnh, hnl,
                                            wh + WOFF_QKV + (size_t)l * 98304,
                                            wl + WOFF_QKV + (size_t)l * 98304,
                                            qkvb + l * 768, nullptr, nullptr,
                                            qh, ql, kh, kl, vh, vl,
                                            NFT, 768, DD);
        attn_kernel<<<attnG, 128>>>(qh, ql, kh, kl, vh, vl, biasb, oh, ol);
        gemm_sp_kernel<1><<<gemmD, 256>>>(oh, ol,
                                          wh + WOFF_O + (size_t)l * 32768,
                                          wl + WOFF_O + (size_t)l * 32768,
                                          o_b + l * DD, h, h, nullptr, nullptr,
                                          nullptr, nullptr, nullptr, nullptr,
                                          NFT, DD, DD);
        ln_warp_kernel<1><<<lnG, 256>>>(h, nullptr, hnh, hnl,
                                        ln2_s + l * DD, ln2_b + l * DD);
        gemm_sp_kernel<2><<<gemmF1, 256>>>(hnh, hnl,
                                           wh + WOFF_F1 + (size_t)l * 131072,
                                           wl + WOFF_F1 + (size_t)l * 131072,
                                           ffn1_b + l * FFND, nullptr, nullptr, fh, fl,
                                           nullptr, nullptr, nullptr, nullptr,
                                           NFT, FFND, DD);
        gemm_sp_kernel<1><<<gemmD, 256>>>(fh, fl,
                                          wh + WOFF_F2 + (size_t)l * 131072,
                                          wl + WOFF_F2 + (size_t)l * 131072,
                                          ffn2_b + l * DD, h, h, nullptr, nullptr,
                                          nullptr, nullptr, nullptr, nullptr,
                                          NFT, DD, FFND);
    }

    ln_warp_kernel<0><<<lnG, 256>>>(h, fin, nullptr, nullptr, fn_s, fn_b);
    size_t total = (size_t)NFT * DD;
    if ((size_t)out_size >= total + DD) {
        cudaMemcpyAsync(out, fin, total * sizeof(float), cudaMemcpyDeviceToDevice);
        cudaMemcpyAsync(out + total, fin, DD * sizeof(float), cudaMemcpyDeviceToDevice);
    } else if ((size_t)out_size >= total) {
        cudaMemcpyAsync(out, fin, total * sizeof(float), cudaMemcpyDeviceToDevice);
    } else {
        cudaMemcpyAsync(out, fin, (size_t)out_size * sizeof(float),
                        cudaMemcpyDeviceToDevice);
    }
}